// round 2
// baseline (speedup 1.0000x reference)
#include <cuda_runtime.h>
#include <cuda_bf16.h>
#include <math.h>

#define NN   65536
#define DD   256
#define HH   8
#define DKK  32
#define DFFv 1024
#define E1v  1048576
#define E2v  524288
#define EPSv 1e-5f
#define SCALEv 0.17677669529663687f  // 1/sqrt(32)

// ------------------------- scratch (static device globals) -------------------------
__device__ float g_q[NN * DD];
__device__ float g_k[NN * DD];
__device__ float g_v[NN * DD];
__device__ float g_agg[NN * DD];
__device__ float g_h1[NN * DD];
__device__ float g_o[NN * DD];
__device__ float g_e[(size_t)E1v * HH];
__device__ int   g_m[NN * HH];
__device__ float g_den[NN * HH];
__device__ float g_ffn[(size_t)NN * DFFv];

// ------------------------- helpers -------------------------
__device__ __forceinline__ int fenc(float f) {
    int i = __float_as_int(f);
    return i >= 0 ? i : (i ^ 0x7fffffff);
}
__device__ __forceinline__ float fdec(int i) {
    return __int_as_float(i >= 0 ? i : (i ^ 0x7fffffff));
}

// ------------------------- SGEMM: C[Nn,Mm] = A[Nn,Kk] @ B[Kk,Mm] (+bias)(+relu) ----
#define BM 64
#define BN 64
#define BK 16
__global__ __launch_bounds__(256) void sgemm_kernel(
    const float* __restrict__ A, const float* __restrict__ B, float* __restrict__ C,
    int Nn, int Kk, int Mm, const float* __restrict__ bias, int relu)
{
    __shared__ float As[BK][BM + 4];
    __shared__ float Bs[BK][BN];

    int bm = blockIdx.y * BM;
    int bn = blockIdx.x * BN;
    int tid = threadIdx.x;
    int tr = tid >> 4;        // 0..15
    int tc = tid & 15;        // 0..15

    float acc[4][4];
#pragma unroll
    for (int i = 0; i < 4; i++)
#pragma unroll
        for (int j = 0; j < 4; j++) acc[i][j] = 0.f;

    for (int k0 = 0; k0 < Kk; k0 += BK) {
#pragma unroll
        for (int j = 0; j < 4; j++) {
            int id = tid + 256 * j;
            int r = id >> 4, c = id & 15;
            As[c][r] = A[(size_t)(bm + r) * Kk + k0 + c];
            int r2 = id >> 6, c2 = id & 63;
            Bs[r2][c2] = B[(size_t)(k0 + r2) * Mm + bn + c2];
        }
        __syncthreads();
#pragma unroll
        for (int kk = 0; kk < BK; kk++) {
            float4 av = *reinterpret_cast<const float4*>(&As[kk][tr * 4]);
            float4 bv = *reinterpret_cast<const float4*>(&Bs[kk][tc * 4]);
            float a[4] = {av.x, av.y, av.z, av.w};
            float b[4] = {bv.x, bv.y, bv.z, bv.w};
#pragma unroll
            for (int i = 0; i < 4; i++)
#pragma unroll
                for (int j = 0; j < 4; j++) acc[i][j] += a[i] * b[j];
        }
        __syncthreads();
    }

#pragma unroll
    for (int i = 0; i < 4; i++) {
        int row = bm + tr * 4 + i;
#pragma unroll
        for (int j = 0; j < 4; j++) {
            int col = bn + tc * 4 + j;
            float vv = acc[i][j];
            if (bias) vv += bias[col];
            if (relu) vv = fmaxf(vv, 0.f);
            C[(size_t)row * Mm + col] = vv;
        }
    }
}

// ------------------------- edge pass A: logits + segment max ----------------------
// warp per edge; e = ((k[src] + ak?) . q[dst]) * SCALE per head
__global__ void edge_logits(const float* __restrict__ q, const float* __restrict__ k,
                            const float* __restrict__ ak, const int* __restrict__ etype,
                            const int* __restrict__ src, const int* __restrict__ dst,
                            float* __restrict__ e_out, int* __restrict__ m_enc, int E)
{
    int w = (blockIdx.x * blockDim.x + threadIdx.x) >> 5;
    int lane = threadIdx.x & 31;
    if (w >= E) return;
    int s = src[w], d0 = dst[w];
    float akv = 0.f;
    if (ak) akv = ak[(size_t)etype[w] * DKK + lane];
    const float* krow = k + (size_t)s * DD;
    const float* qrow = q + (size_t)d0 * DD;
#pragma unroll
    for (int hh = 0; hh < HH; hh++) {
        float val = (krow[hh * DKK + lane] + akv) * qrow[hh * DKK + lane];
#pragma unroll
        for (int off = 16; off; off >>= 1) val += __shfl_down_sync(0xffffffffu, val, off);
        if (lane == 0) {
            float ee = val * SCALEv;
            e_out[(size_t)w * HH + hh] = ee;
            atomicMax(&m_enc[d0 * HH + hh], fenc(ee));
        }
    }
}

// ------------------------- edge pass B: exp + segment sum -------------------------
__global__ void edge_softmax(float* __restrict__ e, const int* __restrict__ m_enc,
                             const int* __restrict__ dst, float* __restrict__ den, int E)
{
    int idx = blockIdx.x * blockDim.x + threadIdx.x;
    if (idx >= E) return;
    int d0 = dst[idx];
#pragma unroll
    for (int hh = 0; hh < HH; hh++) {
        float mh = fdec(m_enc[d0 * HH + hh]);
        float ex = __expf(e[(size_t)idx * HH + hh] - mh);
        e[(size_t)idx * HH + hh] = ex;
        atomicAdd(&den[d0 * HH + hh], ex);
    }
}

// ------------------------- edge pass C: normalized scatter-aggregate --------------
__global__ void edge_aggregate(const float* __restrict__ ex, const float* __restrict__ den,
                               const float* __restrict__ v, const int* __restrict__ src,
                               const int* __restrict__ dst, float* __restrict__ agg, int E)
{
    int w = (blockIdx.x * blockDim.x + threadIdx.x) >> 5;
    int lane = threadIdx.x & 31;
    if (w >= E) return;
    int s = src[w], d0 = dst[w];
    float a = 0.f;
    if (lane < HH) a = ex[(size_t)w * HH + lane] / den[d0 * HH + lane];
    const float* vrow = v + (size_t)s * DD;
    float* arow = agg + (size_t)d0 * DD;
#pragma unroll
    for (int hh = 0; hh < HH; hh++) {
        float ah = __shfl_sync(0xffffffffu, a, hh);
        atomicAdd(&arow[hh * DKK + lane], ah * vrow[hh * DKK + lane]);
    }
}

// ------------------------- residual + layernorm (1 block per row) -----------------
__global__ __launch_bounds__(256) void residual_ln(
    const float* __restrict__ x, const float* __restrict__ o,
    const float* __restrict__ g, const float* __restrict__ b, float* __restrict__ out)
{
    int row = blockIdx.x;
    int i = threadIdx.x;
    float val = x[(size_t)row * DD + i] + o[(size_t)row * DD + i];

    __shared__ float sh[8];
    float s = val;
#pragma unroll
    for (int off = 16; off; off >>= 1) s += __shfl_xor_sync(0xffffffffu, s, off);
    if ((i & 31) == 0) sh[i >> 5] = s;
    __syncthreads();
    float tot = 0.f;
#pragma unroll
    for (int j = 0; j < 8; j++) tot += sh[j];
    float mu = tot * (1.f / DD);
    float dv = val - mu;
    __syncthreads();

    float s2 = dv * dv;
#pragma unroll
    for (int off = 16; off; off >>= 1) s2 += __shfl_xor_sync(0xffffffffu, s2, off);
    if ((i & 31) == 0) sh[i >> 5] = s2;
    __syncthreads();
    float tot2 = 0.f;
#pragma unroll
    for (int j = 0; j < 8; j++) tot2 += sh[j];
    float var = tot2 * (1.f / DD);

    out[(size_t)row * DD + i] = dv * rsqrtf(var + EPSv) * g[i] + b[i];
}

// ------------------------- host launch -------------------------
extern "C" void kernel_launch(void* const* d_in, const int* in_sizes, int n_in,
                              void* d_out, int out_size)
{
    // Classify inputs by element-count signature (robust to metadata ordering).
    const float *h = nullptr, *mem = nullptr, *ak = nullptr, *bf1 = nullptr;
    const float *W[8] = {nullptr};       // Wq0,Wk0,Wv0,Wo0,Wq1,Wk1,Wv1,Wo1
    const float *Wf[2] = {nullptr};      // Wf1, Wf2
    const float *v256[8] = {nullptr};    // ln0_g, ln0_b, ln1_g, ln1_b, ln2_g, ln2_b, bf2
    const int *src_intra = nullptr, *dst_intra = nullptr, *etype = nullptr;
    const int *src_inter = nullptr, *dst_inter = nullptr;
    int c16 = 0, c1m = 0, c512k = 0, c64k = 0, c262k = 0, c256 = 0;

    for (int i = 0; i < n_in; i++) {
        int sz = in_sizes[i];
        void* p = d_in[i];
        if (sz == 16777216)      { if (c16 == 0) h = (const float*)p; else mem = (const float*)p; c16++; }
        else if (sz == 1048576)  { if (c1m == 0) src_intra = (const int*)p;
                                   else if (c1m == 1) dst_intra = (const int*)p;
                                   else etype = (const int*)p; c1m++; }
        else if (sz == 524288)   { if (c512k == 0) src_inter = (const int*)p; else dst_inter = (const int*)p; c512k++; }
        else if (sz == 65536)    { if (c64k < 8) W[c64k] = (const float*)p; c64k++; }
        else if (sz == 32000)    { ak = (const float*)p; }
        else if (sz == 262144)   { if (c262k < 2) Wf[c262k] = (const float*)p; c262k++; }
        else if (sz == 1024)     { bf1 = (const float*)p; }
        else if (sz == 256)      { if (c256 < 8) v256[c256] = (const float*)p; c256++; }
    }
    const float *ln0_g = v256[0], *ln0_b = v256[1];
    const float *ln1_g = v256[2], *ln1_b = v256[3];
    const float *ln2_g = v256[4], *ln2_b = v256[5];
    const float *bf2   = v256[6];

    float *q, *k, *v, *agg, *h1, *o, *e, *den, *ffn; int *m;
    cudaGetSymbolAddress((void**)&q,   g_q);
    cudaGetSymbolAddress((void**)&k,   g_k);
    cudaGetSymbolAddress((void**)&v,   g_v);
    cudaGetSymbolAddress((void**)&agg, g_agg);
    cudaGetSymbolAddress((void**)&h1,  g_h1);
    cudaGetSymbolAddress((void**)&o,   g_o);
    cudaGetSymbolAddress((void**)&e,   g_e);
    cudaGetSymbolAddress((void**)&m,   g_m);
    cudaGetSymbolAddress((void**)&den, g_den);
    cudaGetSymbolAddress((void**)&ffn, g_ffn);

    float* out = (float*)d_out;

    dim3 gD(DD / BN, NN / BM);      // 256-wide output
    dim3 gF1(DFFv / BN, NN / BM);   // 1024-wide output

    // ---------------- stage 1: intra attention ----------------
    sgemm_kernel<<<gD, 256>>>(h, W[0], q, NN, DD, DD, nullptr, 0);
    sgemm_kernel<<<gD, 256>>>(h, W[1], k, NN, DD, DD, nullptr, 0);
    sgemm_kernel<<<gD, 256>>>(h, W[2], v, NN, DD, DD, nullptr, 0);
    cudaMemsetAsync(m,   0x80, (size_t)NN * HH * sizeof(int));
    cudaMemsetAsync(den, 0,    (size_t)NN * HH * sizeof(float));
    cudaMemsetAsync(agg, 0,    (size_t)NN * DD * sizeof(float));
    edge_logits   <<<E1v / 8,   256>>>(q, k, ak, etype, src_intra, dst_intra, e, m, E1v);
    edge_softmax  <<<E1v / 256, 256>>>(e, m, dst_intra, den, E1v);
    edge_aggregate<<<E1v / 8,   256>>>(e, den, v, src_intra, dst_intra, agg, E1v);
    sgemm_kernel<<<gD, 256>>>(agg, W[3], o, NN, DD, DD, nullptr, 0);
    residual_ln<<<NN, 256>>>(h, o, ln0_g, ln0_b, h1);

    // ---------------- stage 2: inter (memory) attention ----------------
    sgemm_kernel<<<gD, 256>>>(h1,  W[4], q, NN, DD, DD, nullptr, 0);
    sgemm_kernel<<<gD, 256>>>(mem, W[5], k, NN, DD, DD, nullptr, 0);
    sgemm_kernel<<<gD, 256>>>(mem, W[6], v, NN, DD, DD, nullptr, 0);
    cudaMemsetAsync(m,   0x80, (size_t)NN * HH * sizeof(int));
    cudaMemsetAsync(den, 0,    (size_t)NN * HH * sizeof(float));
    cudaMemsetAsync(agg, 0,    (size_t)NN * DD * sizeof(float));
    edge_logits   <<<E2v / 8,   256>>>(q, k, nullptr, nullptr, src_inter, dst_inter, e, m, E2v);
    edge_softmax  <<<E2v / 256, 256>>>(e, m, dst_inter, den, E2v);
    edge_aggregate<<<E2v / 8,   256>>>(e, den, v, src_inter, dst_inter, agg, E2v);
    sgemm_kernel<<<gD, 256>>>(agg, W[7], o, NN, DD, DD, nullptr, 0);
    residual_ln<<<NN, 256>>>(h1, o, ln1_g, ln1_b, h1);   // in-place safe: row read before write

    // ---------------- FFN + final norm ----------------
    sgemm_kernel<<<gF1, 256>>>(h1, Wf[0], ffn, NN, DD, DFFv, bf1, 1);
    sgemm_kernel<<<gD,  256>>>(ffn, Wf[1], o, NN, DFFv, DD, bf2, 0);
    residual_ln<<<NN, 256>>>(h1, o, ln2_g, ln2_b, out);
}

// round 3
// speedup vs baseline: 1.3468x; 1.3468x over previous
#include <cuda_runtime.h>
#include <cuda_bf16.h>
#include <math.h>

#define NN   65536
#define DD   256
#define HH   8
#define DKK  32
#define DFFv 1024
#define E1v  1048576
#define E2v  524288
#define EPSv 1e-5f
#define SCALEv 0.17677669529663687f  // 1/sqrt(32)

// ------------------------- scratch (static device globals) -------------------------
__device__ float g_q[NN * DD];
__device__ float g_k[NN * DD];
__device__ float g_v[NN * DD];
__device__ float g_agg[NN * DD];
__device__ float g_h1[NN * DD];
__device__ float g_o[NN * DD];
__device__ float g_e[(size_t)E1v * HH];
__device__ int   g_m[NN * HH];
__device__ float g_den[NN * HH];
__device__ float g_ffn[(size_t)NN * DFFv];

// ------------------------- helpers -------------------------
__device__ __forceinline__ int fenc(float f) {
    int i = __float_as_int(f);
    return i >= 0 ? i : (i ^ 0x7fffffff);
}
__device__ __forceinline__ float fdec(int i) {
    return __int_as_float(i >= 0 ? i : (i ^ 0x7fffffff));
}
__device__ __forceinline__ unsigned f2tf32(float f) {
    unsigned r;
    asm("cvt.rna.tf32.f32 %0, %1;" : "=r"(r) : "f"(f));
    return r;
}

// ------------------------- TF32 tensor-core GEMM ----------------------------------
// C[65536, Mm] = A[65536, Kk] @ B[Kk, Mm]  (+bias)(+relu), fp32 io, tf32 mma
#define GBM 128
#define GBN 128
#define GBK 32
#define AST 36    // As row stride (words): (4m+k)%32 distinct for m0..7,k0..3
#define BST 136   // Bs row stride (words): (8k+n)%32 distinct for k0..3,n0..7

__global__ __launch_bounds__(256) void tf32_gemm(
    const float* __restrict__ A, const float* __restrict__ B, float* __restrict__ C,
    int Kk, int Mm, const float* __restrict__ bias, int relu)
{
    __shared__ unsigned As[GBM * AST];
    __shared__ unsigned Bs[GBK * BST];

    const int tid  = threadIdx.x;
    const int bm   = blockIdx.y * GBM;
    const int bn   = blockIdx.x * GBN;
    const int wid  = tid >> 5;
    const int lane = tid & 31;
    const int wm   = (wid & 3) * 32;   // warp row offset within tile
    const int wn   = (wid >> 2) * 64;  // warp col offset within tile
    const int gid  = lane >> 2;        // group id 0..7
    const int tig  = lane & 3;         // thread-in-group 0..3

    float acc[2][8][4];
#pragma unroll
    for (int mt = 0; mt < 2; mt++)
#pragma unroll
        for (int nt = 0; nt < 8; nt++)
#pragma unroll
            for (int c = 0; c < 4; c++) acc[mt][nt][c] = 0.f;

    // global load mapping
    const int a_r = tid >> 3;           // 0..31, step 32 over 4 iters
    const int a_c = (tid & 7) * 4;      // 0..28
    const int b_r = tid >> 5;           // 0..7, step 8 over 4 iters
    const int b_c = (tid & 31) * 4;     // 0..124

    const int nIter = Kk / GBK;
    for (int it = 0; it < nIter; it++) {
        const int k0 = it * GBK;
        float4 av[4], bv[4];
#pragma unroll
        for (int i = 0; i < 4; i++)
            av[i] = *reinterpret_cast<const float4*>(
                &A[(size_t)(bm + a_r + 32 * i) * Kk + k0 + a_c]);
#pragma unroll
        for (int i = 0; i < 4; i++)
            bv[i] = *reinterpret_cast<const float4*>(
                &B[(size_t)(k0 + b_r + 8 * i) * Mm + bn + b_c]);

        if (it) __syncthreads();   // previous compute done before overwrite
#pragma unroll
        for (int i = 0; i < 4; i++) {
            unsigned* p = &As[(a_r + 32 * i) * AST + a_c];
            p[0] = f2tf32(av[i].x); p[1] = f2tf32(av[i].y);
            p[2] = f2tf32(av[i].z); p[3] = f2tf32(av[i].w);
        }
#pragma unroll
        for (int i = 0; i < 4; i++) {
            unsigned* p = &Bs[(b_r + 8 * i) * BST + b_c];
            p[0] = f2tf32(bv[i].x); p[1] = f2tf32(bv[i].y);
            p[2] = f2tf32(bv[i].z); p[3] = f2tf32(bv[i].w);
        }
        __syncthreads();

#pragma unroll
        for (int ks = 0; ks < 4; ks++) {
            const int kb = ks * 8;
            unsigned af[2][4];
#pragma unroll
            for (int mt = 0; mt < 2; mt++) {
                const int mr = wm + mt * 16 + gid;
                af[mt][0] = As[mr * AST + kb + tig];
                af[mt][1] = As[(mr + 8) * AST + kb + tig];
                af[mt][2] = As[mr * AST + kb + tig + 4];
                af[mt][3] = As[(mr + 8) * AST + kb + tig + 4];
            }
            unsigned bf[8][2];
#pragma unroll
            for (int nt = 0; nt < 8; nt++) {
                const int nc = wn + nt * 8 + gid;
                bf[nt][0] = Bs[(kb + tig) * BST + nc];
                bf[nt][1] = Bs[(kb + tig + 4) * BST + nc];
            }
#pragma unroll
            for (int mt = 0; mt < 2; mt++)
#pragma unroll
                for (int nt = 0; nt < 8; nt++) {
                    asm volatile(
                        "mma.sync.aligned.m16n8k8.row.col.f32.tf32.tf32.f32 "
                        "{%0,%1,%2,%3}, {%4,%5,%6,%7}, {%8,%9}, {%0,%1,%2,%3};"
                        : "+f"(acc[mt][nt][0]), "+f"(acc[mt][nt][1]),
                          "+f"(acc[mt][nt][2]), "+f"(acc[mt][nt][3])
                        : "r"(af[mt][0]), "r"(af[mt][1]), "r"(af[mt][2]), "r"(af[mt][3]),
                          "r"(bf[nt][0]), "r"(bf[nt][1]));
                }
        }
    }

    // epilogue
#pragma unroll
    for (int mt = 0; mt < 2; mt++) {
        const int row0 = bm + wm + mt * 16 + gid;
#pragma unroll
        for (int nt = 0; nt < 8; nt++) {
            const int col = bn + wn + nt * 8 + 2 * tig;
            float b0 = 0.f, b1 = 0.f;
            if (bias) { b0 = bias[col]; b1 = bias[col + 1]; }
            float2 v0 = make_float2(acc[mt][nt][0] + b0, acc[mt][nt][1] + b1);
            float2 v1 = make_float2(acc[mt][nt][2] + b0, acc[mt][nt][3] + b1);
            if (relu) {
                v0.x = fmaxf(v0.x, 0.f); v0.y = fmaxf(v0.y, 0.f);
                v1.x = fmaxf(v1.x, 0.f); v1.y = fmaxf(v1.y, 0.f);
            }
            *reinterpret_cast<float2*>(&C[(size_t)row0 * Mm + col]) = v0;
            *reinterpret_cast<float2*>(&C[(size_t)(row0 + 8) * Mm + col]) = v1;
        }
    }
}

// ------------------------- edge pass A: logits + segment max ----------------------
// warp per edge: lane owns 8 contiguous elems (= one head's quarter)
__global__ void edge_logits(const float* __restrict__ q, const float* __restrict__ k,
                            const float* __restrict__ ak, const int* __restrict__ etype,
                            const int* __restrict__ src, const int* __restrict__ dst,
                            float* __restrict__ e_out, int* __restrict__ m_enc, int E)
{
    int w = (blockIdx.x * blockDim.x + threadIdx.x) >> 5;
    int lane = threadIdx.x & 31;
    if (w >= E) return;
    int s = src[w], d0 = dst[w];
    const float4* kr = reinterpret_cast<const float4*>(k + (size_t)s * DD);
    const float4* qr = reinterpret_cast<const float4*>(q + (size_t)d0 * DD);
    float4 k0 = kr[lane * 2],     k1 = kr[lane * 2 + 1];
    float4 q0 = qr[lane * 2],     q1 = qr[lane * 2 + 1];
    if (ak) {
        const float4* ar = reinterpret_cast<const float4*>(ak + (size_t)etype[w] * DKK);
        float4 a0 = ar[(lane & 3) * 2], a1 = ar[(lane & 3) * 2 + 1];
        k0.x += a0.x; k0.y += a0.y; k0.z += a0.z; k0.w += a0.w;
        k1.x += a1.x; k1.y += a1.y; k1.z += a1.z; k1.w += a1.w;
    }
    float p = k0.x * q0.x + k0.y * q0.y + k0.z * q0.z + k0.w * q0.w
            + k1.x * q1.x + k1.y * q1.y + k1.z * q1.z + k1.w * q1.w;
    p += __shfl_xor_sync(0xffffffffu, p, 1);
    p += __shfl_xor_sync(0xffffffffu, p, 2);   // head sum in all 4 lanes of quad
    float hv = __shfl_sync(0xffffffffu, p, (lane & 7) * 4);
    if (lane < HH) {
        float ee = hv * SCALEv;
        e_out[(size_t)w * HH + lane] = ee;
        atomicMax(&m_enc[d0 * HH + lane], fenc(ee));
    }
}

// ------------------------- edge pass B: exp + segment sum -------------------------
__global__ void edge_softmax(float* __restrict__ e, const int* __restrict__ m_enc,
                             const int* __restrict__ dst, float* __restrict__ den, int E)
{
    int idx = blockIdx.x * blockDim.x + threadIdx.x;
    if (idx >= E) return;
    int d0 = dst[idx];
#pragma unroll
    for (int hh = 0; hh < HH; hh++) {
        float mh = fdec(m_enc[d0 * HH + hh]);
        float ex = __expf(e[(size_t)idx * HH + hh] - mh);
        e[(size_t)idx * HH + hh] = ex;
        atomicAdd(&den[d0 * HH + hh], ex);
    }
}

// ------------------------- edge pass C: normalized scatter-aggregate --------------
__global__ void edge_aggregate(const float* __restrict__ ex, const float* __restrict__ den,
                               const float* __restrict__ v, const int* __restrict__ src,
                               const int* __restrict__ dst, float* __restrict__ agg, int E)
{
    int w = (blockIdx.x * blockDim.x + threadIdx.x) >> 5;
    int lane = threadIdx.x & 31;
    if (w >= E) return;
    int s = src[w], d0 = dst[w];
    float a = 0.f;
    if (lane < HH) a = ex[(size_t)w * HH + lane] / den[d0 * HH + lane];
    const float4* vr = reinterpret_cast<const float4*>(v + (size_t)s * DD);
    float4 v0 = vr[lane * 2], v1 = vr[lane * 2 + 1];
    // lane's 8 elems [lane*8, lane*8+8) all belong to head lane>>2
    float ah = __shfl_sync(0xffffffffu, a, lane >> 2);
    float* arow = agg + (size_t)d0 * DD + lane * 8;
    atomicAdd(&arow[0], ah * v0.x);
    atomicAdd(&arow[1], ah * v0.y);
    atomicAdd(&arow[2], ah * v0.z);
    atomicAdd(&arow[3], ah * v0.w);
    atomicAdd(&arow[4], ah * v1.x);
    atomicAdd(&arow[5], ah * v1.y);
    atomicAdd(&arow[6], ah * v1.z);
    atomicAdd(&arow[7], ah * v1.w);
}

// ------------------------- residual + layernorm (1 block per row) -----------------
__global__ __launch_bounds__(256) void residual_ln(
    const float* __restrict__ x, const float* __restrict__ o,
    const float* __restrict__ g, const float* __restrict__ b, float* __restrict__ out)
{
    int row = blockIdx.x;
    int i = threadIdx.x;
    float val = x[(size_t)row * DD + i] + o[(size_t)row * DD + i];

    __shared__ float sh[8];
    float s = val;
#pragma unroll
    for (int off = 16; off; off >>= 1) s += __shfl_xor_sync(0xffffffffu, s, off);
    if ((i & 31) == 0) sh[i >> 5] = s;
    __syncthreads();
    float tot = 0.f;
#pragma unroll
    for (int j = 0; j < 8; j++) tot += sh[j];
    float mu = tot * (1.f / DD);
    float dv = val - mu;
    __syncthreads();

    float s2 = dv * dv;
#pragma unroll
    for (int off = 16; off; off >>= 1) s2 += __shfl_xor_sync(0xffffffffu, s2, off);
    if ((i & 31) == 0) sh[i >> 5] = s2;
    __syncthreads();
    float tot2 = 0.f;
#pragma unroll
    for (int j = 0; j < 8; j++) tot2 += sh[j];
    float var = tot2 * (1.f / DD);

    out[(size_t)row * DD + i] = dv * rsqrtf(var + EPSv) * g[i] + b[i];
}

// ------------------------- host launch -------------------------
extern "C" void kernel_launch(void* const* d_in, const int* in_sizes, int n_in,
                              void* d_out, int out_size)
{
    const float *h = nullptr, *mem = nullptr, *ak = nullptr, *bf1 = nullptr;
    const float *W[8] = {nullptr};
    const float *Wf[2] = {nullptr};
    const float *v256[8] = {nullptr};
    const int *src_intra = nullptr, *dst_intra = nullptr, *etype = nullptr;
    const int *src_inter = nullptr, *dst_inter = nullptr;
    int c16 = 0, c1m = 0, c512k = 0, c64k = 0, c262k = 0, c256 = 0;

    for (int i = 0; i < n_in; i++) {
        int sz = in_sizes[i];
        void* p = d_in[i];
        if (sz == 16777216)      { if (c16 == 0) h = (const float*)p; else mem = (const float*)p; c16++; }
        else if (sz == 1048576)  { if (c1m == 0) src_intra = (const int*)p;
                                   else if (c1m == 1) dst_intra = (const int*)p;
                                   else etype = (const int*)p; c1m++; }
        else if (sz == 524288)   { if (c512k == 0) src_inter = (const int*)p; else dst_inter = (const int*)p; c512k++; }
        else if (sz == 65536)    { if (c64k < 8) W[c64k] = (const float*)p; c64k++; }
        else if (sz == 32000)    { ak = (const float*)p; }
        else if (sz == 262144)   { if (c262k < 2) Wf[c262k] = (const float*)p; c262k++; }
        else if (sz == 1024)     { bf1 = (const float*)p; }
        else if (sz == 256)      { if (c256 < 8) v256[c256] = (const float*)p; c256++; }
    }
    const float *ln0_g = v256[0], *ln0_b = v256[1];
    const float *ln1_g = v256[2], *ln1_b = v256[3];
    const float *ln2_g = v256[4], *ln2_b = v256[5];
    const float *bf2   = v256[6];

    float *q, *k, *v, *agg, *h1, *o, *e, *den, *ffn; int *m;
    cudaGetSymbolAddress((void**)&q,   g_q);
    cudaGetSymbolAddress((void**)&k,   g_k);
    cudaGetSymbolAddress((void**)&v,   g_v);
    cudaGetSymbolAddress((void**)&agg, g_agg);
    cudaGetSymbolAddress((void**)&h1,  g_h1);
    cudaGetSymbolAddress((void**)&o,   g_o);
    cudaGetSymbolAddress((void**)&e,   g_e);
    cudaGetSymbolAddress((void**)&m,   g_m);
    cudaGetSymbolAddress((void**)&den, g_den);
    cudaGetSymbolAddress((void**)&ffn, g_ffn);

    float* out = (float*)d_out;

    dim3 gD(DD / GBN, NN / GBM);      // (2, 512)
    dim3 gF1(DFFv / GBN, NN / GBM);   // (8, 512)

    // ---------------- stage 1: intra attention ----------------
    tf32_gemm<<<gD, 256>>>(h, W[0], q, DD, DD, nullptr, 0);
    tf32_gemm<<<gD, 256>>>(h, W[1], k, DD, DD, nullptr, 0);
    tf32_gemm<<<gD, 256>>>(h, W[2], v, DD, DD, nullptr, 0);
    cudaMemsetAsync(m,   0x80, (size_t)NN * HH * sizeof(int));
    cudaMemsetAsync(den, 0,    (size_t)NN * HH * sizeof(float));
    cudaMemsetAsync(agg, 0,    (size_t)NN * DD * sizeof(float));
    edge_logits   <<<E1v / 8,   256>>>(q, k, ak, etype, src_intra, dst_intra, e, m, E1v);
    edge_softmax  <<<E1v / 256, 256>>>(e, m, dst_intra, den, E1v);
    edge_aggregate<<<E1v / 8,   256>>>(e, den, v, src_intra, dst_intra, agg, E1v);
    tf32_gemm<<<gD, 256>>>(agg, W[3], o, DD, DD, nullptr, 0);
    residual_ln<<<NN, 256>>>(h, o, ln0_g, ln0_b, h1);

    // ---------------- stage 2: inter (memory) attention ----------------
    tf32_gemm<<<gD, 256>>>(h1,  W[4], q, DD, DD, nullptr, 0);
    tf32_gemm<<<gD, 256>>>(mem, W[5], k, DD, DD, nullptr, 0);
    tf32_gemm<<<gD, 256>>>(mem, W[6], v, DD, DD, nullptr, 0);
    cudaMemsetAsync(m,   0x80, (size_t)NN * HH * sizeof(int));
    cudaMemsetAsync(den, 0,    (size_t)NN * HH * sizeof(float));
    cudaMemsetAsync(agg, 0,    (size_t)NN * DD * sizeof(float));
    edge_logits   <<<E2v / 8,   256>>>(q, k, nullptr, nullptr, src_inter, dst_inter, e, m, E2v);
    edge_softmax  <<<E2v / 256, 256>>>(e, m, dst_inter, den, E2v);
    edge_aggregate<<<E2v / 8,   256>>>(e, den, v, src_inter, dst_inter, agg, E2v);
    tf32_gemm<<<gD, 256>>>(agg, W[7], o, DD, DD, nullptr, 0);
    residual_ln<<<NN, 256>>>(h1, o, ln1_g, ln1_b, h1);   // in-place safe: row read before write

    // ---------------- FFN + final norm ----------------
    tf32_gemm<<<gF1, 256>>>(h1, Wf[0], ffn, DD, DFFv, bf1, 1);
    tf32_gemm<<<gD,  256>>>(ffn, Wf[1], o, DFFv, DD, bf2, 0);
    residual_ln<<<NN, 256>>>(h1, o, ln2_g, ln2_b, out);
}

// round 4
// speedup vs baseline: 2.4332x; 1.8066x over previous
#include <cuda_runtime.h>
#include <cuda_bf16.h>
#include <math.h>

#define NN   65536
#define DD   256
#define HH   8
#define DKK  32
#define DFFv 1024
#define E1v  1048576
#define E2v  524288
#define EPSv 1e-5f
#define SCALEv 0.17677669529663687f  // 1/sqrt(32)

// ------------------------- scratch (static device globals) -------------------------
__device__ float g_q[NN * DD];
__device__ float g_k[NN * DD];
__device__ float g_v[NN * DD];
__device__ float g_agg[NN * DD];
__device__ float g_h1[NN * DD];
__device__ float g_o[NN * DD];
__device__ float g_e[(size_t)E1v * HH];
__device__ float g_den[NN * HH];
__device__ float g_ffn[(size_t)NN * DFFv];

// ------------------------- helpers -------------------------
__device__ __forceinline__ unsigned f2tf32(float f) {
    unsigned r;
    asm("cvt.rna.tf32.f32 %0, %1;" : "=r"(r) : "f"(f));
    return r;
}
__device__ __forceinline__ void red_add_v4(float* p, float a, float b, float c, float d) {
    asm volatile("red.global.add.v4.f32 [%0], {%1,%2,%3,%4};"
                 :: "l"(p), "f"(a), "f"(b), "f"(c), "f"(d) : "memory");
}

// ------------------------- TF32 tensor-core GEMM (double-buffered) ----------------
// C[65536, Mm] = A[65536, Kk] @ B[Kk, Mm]  (+bias)(+relu), fp32 io, tf32 mma
#define GBM 128
#define GBN 128
#define GBK 32
#define AST 36    // As row stride (words)
#define BST 136   // Bs row stride (words)
#define A_WORDS (GBM * AST)
#define B_WORDS (GBK * BST)
#define SMEM_GEMM (2 * (A_WORDS + B_WORDS) * 4)

__global__ __launch_bounds__(256) void tf32_gemm(
    const float* __restrict__ A, const float* __restrict__ B, float* __restrict__ C,
    int Kk, int Mm, const float* __restrict__ bias, int relu)
{
    extern __shared__ unsigned smw[];
    unsigned* AsAll = smw;                 // [2][A_WORDS]
    unsigned* BsAll = smw + 2 * A_WORDS;   // [2][B_WORDS]

    const int tid  = threadIdx.x;
    const int bm   = blockIdx.y * GBM;
    const int bn   = blockIdx.x * GBN;
    const int wid  = tid >> 5;
    const int lane = tid & 31;
    const int wm   = (wid & 3) * 32;
    const int wn   = (wid >> 2) * 64;
    const int gid  = lane >> 2;
    const int tig  = lane & 3;

    float acc[2][8][4];
#pragma unroll
    for (int mt = 0; mt < 2; mt++)
#pragma unroll
        for (int nt = 0; nt < 8; nt++)
#pragma unroll
            for (int c = 0; c < 4; c++) acc[mt][nt][c] = 0.f;

    const int a_r = tid >> 3;
    const int a_c = (tid & 7) * 4;
    const int b_r = tid >> 5;
    const int b_c = (tid & 31) * 4;

    const int nIter = Kk / GBK;
    float4 av[4], bv[4];

    // prefetch tile 0 into registers
#pragma unroll
    for (int i = 0; i < 4; i++)
        av[i] = *reinterpret_cast<const float4*>(&A[(size_t)(bm + a_r + 32 * i) * Kk + a_c]);
#pragma unroll
    for (int i = 0; i < 4; i++)
        bv[i] = *reinterpret_cast<const float4*>(&B[(size_t)(b_r + 8 * i) * Mm + bn + b_c]);

    for (int it = 0; it < nIter; it++) {
        unsigned* As = AsAll + (it & 1) * A_WORDS;
        unsigned* Bs = BsAll + (it & 1) * B_WORDS;

#pragma unroll
        for (int i = 0; i < 4; i++) {
            unsigned* p = &As[(a_r + 32 * i) * AST + a_c];
            p[0] = f2tf32(av[i].x); p[1] = f2tf32(av[i].y);
            p[2] = f2tf32(av[i].z); p[3] = f2tf32(av[i].w);
        }
#pragma unroll
        for (int i = 0; i < 4; i++) {
            unsigned* p = &Bs[(b_r + 8 * i) * BST + b_c];
            p[0] = f2tf32(bv[i].x); p[1] = f2tf32(bv[i].y);
            p[2] = f2tf32(bv[i].z); p[3] = f2tf32(bv[i].w);
        }
        __syncthreads();

        if (it + 1 < nIter) {
            const int k1 = (it + 1) * GBK;
#pragma unroll
            for (int i = 0; i < 4; i++)
                av[i] = *reinterpret_cast<const float4*>(
                    &A[(size_t)(bm + a_r + 32 * i) * Kk + k1 + a_c]);
#pragma unroll
            for (int i = 0; i < 4; i++)
                bv[i] = *reinterpret_cast<const float4*>(
                    &B[(size_t)(k1 + b_r + 8 * i) * Mm + bn + b_c]);
        }

#pragma unroll
        for (int ks = 0; ks < 4; ks++) {
            const int kb = ks * 8;
            unsigned af[2][4];
#pragma unroll
            for (int mt = 0; mt < 2; mt++) {
                const int mr = wm + mt * 16 + gid;
                af[mt][0] = As[mr * AST + kb + tig];
                af[mt][1] = As[(mr + 8) * AST + kb + tig];
                af[mt][2] = As[mr * AST + kb + tig + 4];
                af[mt][3] = As[(mr + 8) * AST + kb + tig + 4];
            }
            unsigned bf[8][2];
#pragma unroll
            for (int nt = 0; nt < 8; nt++) {
                const int nc = wn + nt * 8 + gid;
                bf[nt][0] = Bs[(kb + tig) * BST + nc];
                bf[nt][1] = Bs[(kb + tig + 4) * BST + nc];
            }
#pragma unroll
            for (int mt = 0; mt < 2; mt++)
#pragma unroll
                for (int nt = 0; nt < 8; nt++) {
                    asm volatile(
                        "mma.sync.aligned.m16n8k8.row.col.f32.tf32.tf32.f32 "
                        "{%0,%1,%2,%3}, {%4,%5,%6,%7}, {%8,%9}, {%0,%1,%2,%3};"
                        : "+f"(acc[mt][nt][0]), "+f"(acc[mt][nt][1]),
                          "+f"(acc[mt][nt][2]), "+f"(acc[mt][nt][3])
                        : "r"(af[mt][0]), "r"(af[mt][1]), "r"(af[mt][2]), "r"(af[mt][3]),
                          "r"(bf[nt][0]), "r"(bf[nt][1]));
                }
        }
    }

#pragma unroll
    for (int mt = 0; mt < 2; mt++) {
        const int row0 = bm + wm + mt * 16 + gid;
#pragma unroll
        for (int nt = 0; nt < 8; nt++) {
            const int col = bn + wn + nt * 8 + 2 * tig;
            float b0 = 0.f, b1 = 0.f;
            if (bias) { b0 = bias[col]; b1 = bias[col + 1]; }
            float2 v0 = make_float2(acc[mt][nt][0] + b0, acc[mt][nt][1] + b1);
            float2 v1 = make_float2(acc[mt][nt][2] + b0, acc[mt][nt][3] + b1);
            if (relu) {
                v0.x = fmaxf(v0.x, 0.f); v0.y = fmaxf(v0.y, 0.f);
                v1.x = fmaxf(v1.x, 0.f); v1.y = fmaxf(v1.y, 0.f);
            }
            *reinterpret_cast<float2*>(&C[(size_t)row0 * Mm + col]) = v0;
            *reinterpret_cast<float2*>(&C[(size_t)(row0 + 8) * Mm + col]) = v1;
        }
    }
}

// ------------------------- edge pass A: logits + exp + segment sum ----------------
// warp per edge; no max-shift (logits are O(±6), exp cannot overflow in fp32)
__global__ void edge_logits_exp(const float* __restrict__ q, const float* __restrict__ k,
                                const float* __restrict__ ak, const int* __restrict__ etype,
                                const int* __restrict__ src, const int* __restrict__ dst,
                                float* __restrict__ ex_out, float* __restrict__ den, int E)
{
    int w = (blockIdx.x * blockDim.x + threadIdx.x) >> 5;
    int lane = threadIdx.x & 31;
    if (w >= E) return;
    int s = src[w], d0 = dst[w];
    const float4* kr = reinterpret_cast<const float4*>(k + (size_t)s * DD);
    const float4* qr = reinterpret_cast<const float4*>(q + (size_t)d0 * DD);
    float4 k0 = kr[lane * 2],     k1 = kr[lane * 2 + 1];
    float4 q0 = qr[lane * 2],     q1 = qr[lane * 2 + 1];
    if (ak) {
        const float4* ar = reinterpret_cast<const float4*>(ak + (size_t)etype[w] * DKK);
        float4 a0 = ar[(lane & 3) * 2], a1 = ar[(lane & 3) * 2 + 1];
        k0.x += a0.x; k0.y += a0.y; k0.z += a0.z; k0.w += a0.w;
        k1.x += a1.x; k1.y += a1.y; k1.z += a1.z; k1.w += a1.w;
    }
    float p = k0.x * q0.x + k0.y * q0.y + k0.z * q0.z + k0.w * q0.w
            + k1.x * q1.x + k1.y * q1.y + k1.z * q1.z + k1.w * q1.w;
    p += __shfl_xor_sync(0xffffffffu, p, 1);
    p += __shfl_xor_sync(0xffffffffu, p, 2);   // head sum in all 4 lanes of quad
    float hv = __shfl_sync(0xffffffffu, p, (lane & 7) * 4);
    if (lane < HH) {
        float ex = __expf(hv * SCALEv);
        ex_out[(size_t)w * HH + lane] = ex;
        atomicAdd(&den[d0 * HH + lane], ex);
    }
}

// ------------------------- reciprocal of denominators -----------------------------
__global__ void recip_kernel(float* __restrict__ den, int n)
{
    int i = blockIdx.x * blockDim.x + threadIdx.x;
    if (i < n) den[i] = __frcp_rn(den[i]);
}

// ------------------------- edge pass B: normalized scatter-aggregate --------------
__global__ void edge_aggregate(const float* __restrict__ ex, const float* __restrict__ rden,
                               const float* __restrict__ v, const int* __restrict__ src,
                               const int* __restrict__ dst, float* __restrict__ agg, int E)
{
    int w = (blockIdx.x * blockDim.x + threadIdx.x) >> 5;
    int lane = threadIdx.x & 31;
    if (w >= E) return;
    int s = src[w], d0 = dst[w];
    float a = 0.f;
    if (lane < HH) a = ex[(size_t)w * HH + lane] * rden[d0 * HH + lane];
    const float4* vr = reinterpret_cast<const float4*>(v + (size_t)s * DD);
    float4 v0 = vr[lane * 2], v1 = vr[lane * 2 + 1];
    float ah = __shfl_sync(0xffffffffu, a, lane >> 2);
    float* arow = agg + (size_t)d0 * DD + lane * 8;
    red_add_v4(arow,     ah * v0.x, ah * v0.y, ah * v0.z, ah * v0.w);
    red_add_v4(arow + 4, ah * v1.x, ah * v1.y, ah * v1.z, ah * v1.w);
}

// ------------------------- residual + layernorm (1 block per row) -----------------
__global__ __launch_bounds__(256) void residual_ln(
    const float* __restrict__ x, const float* __restrict__ o,
    const float* __restrict__ g, const float* __restrict__ b, float* __restrict__ out)
{
    int row = blockIdx.x;
    int i = threadIdx.x;
    float val = x[(size_t)row * DD + i] + o[(size_t)row * DD + i];

    __shared__ float sh[8];
    float s = val;
#pragma unroll
    for (int off = 16; off; off >>= 1) s += __shfl_xor_sync(0xffffffffu, s, off);
    if ((i & 31) == 0) sh[i >> 5] = s;
    __syncthreads();
    float tot = 0.f;
#pragma unroll
    for (int j = 0; j < 8; j++) tot += sh[j];
    float mu = tot * (1.f / DD);
    float dv = val - mu;
    __syncthreads();

    float s2 = dv * dv;
#pragma unroll
    for (int off = 16; off; off >>= 1) s2 += __shfl_xor_sync(0xffffffffu, s2, off);
    if ((i & 31) == 0) sh[i >> 5] = s2;
    __syncthreads();
    float tot2 = 0.f;
#pragma unroll
    for (int j = 0; j < 8; j++) tot2 += sh[j];
    float var = tot2 * (1.f / DD);

    out[(size_t)row * DD + i] = dv * rsqrtf(var + EPSv) * g[i] + b[i];
}

// ------------------------- host launch -------------------------
extern "C" void kernel_launch(void* const* d_in, const int* in_sizes, int n_in,
                              void* d_out, int out_size)
{
    const float *h = nullptr, *mem = nullptr, *ak = nullptr, *bf1 = nullptr;
    const float *W[8] = {nullptr};
    const float *Wf[2] = {nullptr};
    const float *v256[8] = {nullptr};
    const int *src_intra = nullptr, *dst_intra = nullptr, *etype = nullptr;
    const int *src_inter = nullptr, *dst_inter = nullptr;
    int c16 = 0, c1m = 0, c512k = 0, c64k = 0, c262k = 0, c256 = 0;

    for (int i = 0; i < n_in; i++) {
        int sz = in_sizes[i];
        void* p = d_in[i];
        if (sz == 16777216)      { if (c16 == 0) h = (const float*)p; else mem = (const float*)p; c16++; }
        else if (sz == 1048576)  { if (c1m == 0) src_intra = (const int*)p;
                                   else if (c1m == 1) dst_intra = (const int*)p;
                                   else etype = (const int*)p; c1m++; }
        else if (sz == 524288)   { if (c512k == 0) src_inter = (const int*)p; else dst_inter = (const int*)p; c512k++; }
        else if (sz == 65536)    { if (c64k < 8) W[c64k] = (const float*)p; c64k++; }
        else if (sz == 32000)    { ak = (const float*)p; }
        else if (sz == 262144)   { if (c262k < 2) Wf[c262k] = (const float*)p; c262k++; }
        else if (sz == 1024)     { bf1 = (const float*)p; }
        else if (sz == 256)      { if (c256 < 8) v256[c256] = (const float*)p; c256++; }
    }
    const float *ln0_g = v256[0], *ln0_b = v256[1];
    const float *ln1_g = v256[2], *ln1_b = v256[3];
    const float *ln2_g = v256[4], *ln2_b = v256[5];
    const float *bf2   = v256[6];

    float *q, *k, *v, *agg, *h1, *o, *e, *den, *ffn;
    cudaGetSymbolAddress((void**)&q,   g_q);
    cudaGetSymbolAddress((void**)&k,   g_k);
    cudaGetSymbolAddress((void**)&v,   g_v);
    cudaGetSymbolAddress((void**)&agg, g_agg);
    cudaGetSymbolAddress((void**)&h1,  g_h1);
    cudaGetSymbolAddress((void**)&o,   g_o);
    cudaGetSymbolAddress((void**)&e,   g_e);
    cudaGetSymbolAddress((void**)&den, g_den);
    cudaGetSymbolAddress((void**)&ffn, g_ffn);

    float* out = (float*)d_out;

    cudaFuncSetAttribute(tf32_gemm, cudaFuncAttributeMaxDynamicSharedMemorySize, SMEM_GEMM);

    dim3 gD(DD / GBN, NN / GBM);      // (2, 512)
    dim3 gF1(DFFv / GBN, NN / GBM);   // (8, 512)

    // ---------------- stage 1: intra attention ----------------
    tf32_gemm<<<gD, 256, SMEM_GEMM>>>(h, W[0], q, DD, DD, nullptr, 0);
    tf32_gemm<<<gD, 256, SMEM_GEMM>>>(h, W[1], k, DD, DD, nullptr, 0);
    tf32_gemm<<<gD, 256, SMEM_GEMM>>>(h, W[2], v, DD, DD, nullptr, 0);
    cudaMemsetAsync(den, 0, (size_t)NN * HH * sizeof(float));
    cudaMemsetAsync(agg, 0, (size_t)NN * DD * sizeof(float));
    edge_logits_exp<<<E1v / 8,   256>>>(q, k, ak, etype, src_intra, dst_intra, e, den, E1v);
    recip_kernel   <<<NN * HH / 256, 256>>>(den, NN * HH);
    edge_aggregate <<<E1v / 8,   256>>>(e, den, v, src_intra, dst_intra, agg, E1v);
    tf32_gemm<<<gD, 256, SMEM_GEMM>>>(agg, W[3], o, DD, DD, nullptr, 0);
    residual_ln<<<NN, 256>>>(h, o, ln0_g, ln0_b, h1);

    // ---------------- stage 2: inter (memory) attention ----------------
    tf32_gemm<<<gD, 256, SMEM_GEMM>>>(h1,  W[4], q, DD, DD, nullptr, 0);
    tf32_gemm<<<gD, 256, SMEM_GEMM>>>(mem, W[5], k, DD, DD, nullptr, 0);
    tf32_gemm<<<gD, 256, SMEM_GEMM>>>(mem, W[6], v, DD, DD, nullptr, 0);
    cudaMemsetAsync(den, 0, (size_t)NN * HH * sizeof(float));
    cudaMemsetAsync(agg, 0, (size_t)NN * DD * sizeof(float));
    edge_logits_exp<<<E2v / 8,   256>>>(q, k, nullptr, nullptr, src_inter, dst_inter, e, den, E2v);
    recip_kernel   <<<NN * HH / 256, 256>>>(den, NN * HH);
    edge_aggregate <<<E2v / 8,   256>>>(e, den, v, src_inter, dst_inter, agg, E2v);
    tf32_gemm<<<gD, 256, SMEM_GEMM>>>(agg, W[7], o, DD, DD, nullptr, 0);
    residual_ln<<<NN, 256>>>(h1, o, ln1_g, ln1_b, h1);   // in-place safe: row read before write

    // ---------------- FFN + final norm ----------------
    tf32_gemm<<<gF1, 256, SMEM_GEMM>>>(h1, Wf[0], ffn, DD, DFFv, bf1, 1);
    tf32_gemm<<<gD,  256, SMEM_GEMM>>>(ffn, Wf[1], o, DFFv, DD, bf2, 0);
    residual_ln<<<NN, 256>>>(h1, o, ln2_g, ln2_b, out);
}

// round 5
// speedup vs baseline: 2.4952x; 1.0255x over previous
#include <cuda_runtime.h>
#include <cuda_bf16.h>
#include <math.h>

#define NN   65536
#define DD   256
#define HH   8
#define DKK  32
#define DFFv 1024
#define E1v  1048576
#define E2v  524288
#define EPSv 1e-5f
#define SCALEv 0.17677669529663687f  // 1/sqrt(32)

// ------------------------- scratch (static device globals) -------------------------
__device__ float g_q[NN * DD];
__device__ float g_k[NN * DD];
__device__ float g_v[NN * DD];
__device__ float g_agg[NN * DD];
__device__ float g_h1[NN * DD];
__device__ float g_e[(size_t)E1v * HH];
__device__ float g_den[NN * HH];
__device__ float g_ffn[(size_t)NN * DFFv];

// ------------------------- helpers -------------------------
__device__ __forceinline__ unsigned f2tf32(float f) {
    unsigned r;
    asm("cvt.rna.tf32.f32 %0, %1;" : "=r"(r) : "f"(f));
    return r;
}
__device__ __forceinline__ void red_add_v4(float* p, float a, float b, float c, float d) {
    asm volatile("red.global.add.v4.f32 [%0], {%1,%2,%3,%4};"
                 :: "l"(p), "f"(a), "f"(b), "f"(c), "f"(d) : "memory");
}
__device__ __forceinline__ void cp16(float* smem, const float* g) {
    unsigned saddr = (unsigned)__cvta_generic_to_shared(smem);
    asm volatile("cp.async.cg.shared.global [%0], [%1], 16;" :: "r"(saddr), "l"(g));
}
#define CP_COMMIT() asm volatile("cp.async.commit_group;")
#define CP_WAIT1()  asm volatile("cp.async.wait_group 1;")
#define CP_WAIT0()  asm volatile("cp.async.wait_group 0;")

// ------------------------- TF32 tensor-core GEMM, 3-stage cp.async ----------------
// block tile 128x256, warp tile 64x64, K-step 32. fp32 io, tf32 mma (cvt at LDS).
#define GBM 128
#define GBN 256
#define GBK 32
#define AST 36                  // A smem row stride (words)
#define BST 264                 // B smem row stride (words)
#define A_WORDS (GBM * AST)     // 4608
#define B_WORDS (GBK * BST)     // 8448
#define STAGE_WORDS (A_WORDS + B_WORDS)
#define N_STAGE 3
#define SMEM_GEMM (N_STAGE * STAGE_WORDS * 4)   // 156,672 B

__device__ __forceinline__ void gemm_body(
    float* sm,
    const float* __restrict__ A, const float* __restrict__ B, float* __restrict__ C,
    int Kk, int Mm, const float* __restrict__ bias, int relu,
    const float* __restrict__ resid, const float* __restrict__ lng,
    const float* __restrict__ lnb)
{
    const int tid  = threadIdx.x;
    const int bm   = blockIdx.y * GBM;
    const int bn   = blockIdx.x * GBN;
    const int wid  = tid >> 5;
    const int lane = tid & 31;
    const int wm   = (wid & 1) * 64;
    const int wn   = (wid >> 1) * 64;
    const int gid  = lane >> 2;
    const int tig  = lane & 3;

    float acc[4][8][4];
#pragma unroll
    for (int mt = 0; mt < 4; mt++)
#pragma unroll
        for (int nt = 0; nt < 8; nt++)
#pragma unroll
            for (int c = 0; c < 4; c++) acc[mt][nt][c] = 0.f;

    const int nIter = Kk / GBK;

    // async-copy issue for stage it
    auto issue = [&](int it) {
        float* As = sm + (it % N_STAGE) * STAGE_WORDS;
        float* Bs = As + A_WORDS;
        const int k0 = it * GBK;
#pragma unroll
        for (int i = 0; i < 4; i++) {               // A: 128x32 = 1024 x16B chunks? (128*32*4/16=1024)
            int c = tid + 256 * i;
            int r = c >> 3, cc = (c & 7) * 4;
            cp16(&As[r * AST + cc], &A[(size_t)(bm + r) * Kk + k0 + cc]);
        }
#pragma unroll
        for (int i = 0; i < 8; i++) {               // B: 32x256 = 2048 chunks
            int c = tid + 256 * i;
            int r = c >> 6, cc = (c & 63) * 4;
            cp16(&Bs[r * BST + cc], &B[(size_t)(k0 + r) * Mm + bn + cc]);
        }
        CP_COMMIT();
    };

    issue(0);
    if (nIter > 1) issue(1);

    for (int it = 0; it < nIter; it++) {
        if (it + 1 < nIter) { CP_WAIT1(); } else { CP_WAIT0(); }
        __syncthreads();
        if (it + 2 < nIter) issue(it + 2);

        const float* As = sm + (it % N_STAGE) * STAGE_WORDS;
        const float* Bs = As + A_WORDS;

#pragma unroll
        for (int ks = 0; ks < 4; ks++) {
            const int kb = ks * 8;
            unsigned af[4][4];
#pragma unroll
            for (int mt = 0; mt < 4; mt++) {
                const int mr = wm + mt * 16 + gid;
                af[mt][0] = f2tf32(As[mr * AST + kb + tig]);
                af[mt][1] = f2tf32(As[(mr + 8) * AST + kb + tig]);
                af[mt][2] = f2tf32(As[mr * AST + kb + tig + 4]);
                af[mt][3] = f2tf32(As[(mr + 8) * AST + kb + tig + 4]);
            }
            unsigned bf[8][2];
#pragma unroll
            for (int nt = 0; nt < 8; nt++) {
                const int nc = wn + nt * 8 + gid;
                bf[nt][0] = f2tf32(Bs[(kb + tig) * BST + nc]);
                bf[nt][1] = f2tf32(Bs[(kb + tig + 4) * BST + nc]);
            }
#pragma unroll
            for (int mt = 0; mt < 4; mt++)
#pragma unroll
                for (int nt = 0; nt < 8; nt++) {
                    asm volatile(
                        "mma.sync.aligned.m16n8k8.row.col.f32.tf32.tf32.f32 "
                        "{%0,%1,%2,%3}, {%4,%5,%6,%7}, {%8,%9}, {%0,%1,%2,%3};"
                        : "+f"(acc[mt][nt][0]), "+f"(acc[mt][nt][1]),
                          "+f"(acc[mt][nt][2]), "+f"(acc[mt][nt][3])
                        : "r"(af[mt][0]), "r"(af[mt][1]), "r"(af[mt][2]), "r"(af[mt][3]),
                          "r"(bf[nt][0]), "r"(bf[nt][1]));
                }
        }
    }

    if (!lng) {
        // plain epilogue: (+bias)(+relu) store
#pragma unroll
        for (int mt = 0; mt < 4; mt++) {
            const int row0 = bm + wm + mt * 16 + gid;
#pragma unroll
            for (int nt = 0; nt < 8; nt++) {
                const int col = bn + wn + nt * 8 + 2 * tig;
                float b0 = 0.f, b1 = 0.f;
                if (bias) { b0 = bias[col]; b1 = bias[col + 1]; }
                float2 v0 = make_float2(acc[mt][nt][0] + b0, acc[mt][nt][1] + b1);
                float2 v1 = make_float2(acc[mt][nt][2] + b0, acc[mt][nt][3] + b1);
                if (relu) {
                    v0.x = fmaxf(v0.x, 0.f); v0.y = fmaxf(v0.y, 0.f);
                    v1.x = fmaxf(v1.x, 0.f); v1.y = fmaxf(v1.y, 0.f);
                }
                *reinterpret_cast<float2*>(&C[(size_t)row0 * Mm + col]) = v0;
                *reinterpret_cast<float2*>(&C[(size_t)(row0 + 8) * Mm + col]) = v1;
            }
        }
        return;
    }

    // ---------- fused residual + LayerNorm epilogue (requires Mm==256, gridDim.x==1) ----------
    // fold bias + residual into acc
#pragma unroll
    for (int mt = 0; mt < 4; mt++) {
        const int r0 = bm + wm + mt * 16 + gid;
        const int r1 = r0 + 8;
#pragma unroll
        for (int nt = 0; nt < 8; nt++) {
            const int col = wn + nt * 8 + 2 * tig;
            float b0 = 0.f, b1 = 0.f;
            if (bias) { b0 = bias[col]; b1 = bias[col + 1]; }
            float2 xa = *reinterpret_cast<const float2*>(&resid[(size_t)r0 * 256 + col]);
            float2 xb = *reinterpret_cast<const float2*>(&resid[(size_t)r1 * 256 + col]);
            acc[mt][nt][0] += b0 + xa.x; acc[mt][nt][1] += b1 + xa.y;
            acc[mt][nt][2] += b0 + xb.x; acc[mt][nt][3] += b1 + xb.y;
        }
    }

    __syncthreads();                     // all stage reads done; reuse smem for row stats
    float* sums  = sm;                   // [128]
    float* sumsq = sm + 128;             // [128]
    if (tid < 128) { sums[tid] = 0.f; sumsq[tid] = 0.f; }
    __syncthreads();

#pragma unroll
    for (int mt = 0; mt < 4; mt++) {
        float sA = 0.f, qA = 0.f, sB = 0.f, qB = 0.f;
#pragma unroll
        for (int nt = 0; nt < 8; nt++) {
            sA += acc[mt][nt][0] + acc[mt][nt][1];
            qA += acc[mt][nt][0] * acc[mt][nt][0] + acc[mt][nt][1] * acc[mt][nt][1];
            sB += acc[mt][nt][2] + acc[mt][nt][3];
            qB += acc[mt][nt][2] * acc[mt][nt][2] + acc[mt][nt][3] * acc[mt][nt][3];
        }
        // reduce across the 4 tig lanes (same row)
        sA += __shfl_xor_sync(0xffffffffu, sA, 1); sA += __shfl_xor_sync(0xffffffffu, sA, 2);
        qA += __shfl_xor_sync(0xffffffffu, qA, 1); qA += __shfl_xor_sync(0xffffffffu, qA, 2);
        sB += __shfl_xor_sync(0xffffffffu, sB, 1); sB += __shfl_xor_sync(0xffffffffu, sB, 2);
        qB += __shfl_xor_sync(0xffffffffu, qB, 1); qB += __shfl_xor_sync(0xffffffffu, qB, 2);
        if (tig == 0) {
            const int lr = wm + mt * 16 + gid;
            atomicAdd(&sums[lr], sA);  atomicAdd(&sumsq[lr], qA);
            atomicAdd(&sums[lr + 8], sB); atomicAdd(&sumsq[lr + 8], qB);
        }
    }
    __syncthreads();

    const float inv = 1.f / 256.f;
#pragma unroll
    for (int mt = 0; mt < 4; mt++) {
        const int lr0 = wm + mt * 16 + gid;
        const int lr1 = lr0 + 8;
        const float mu0 = sums[lr0] * inv;
        const float mu1 = sums[lr1] * inv;
        const float rs0 = rsqrtf(sumsq[lr0] * inv - mu0 * mu0 + EPSv);
        const float rs1 = rsqrtf(sumsq[lr1] * inv - mu1 * mu1 + EPSv);
        const int r0 = bm + lr0, r1 = bm + lr1;
#pragma unroll
        for (int nt = 0; nt < 8; nt++) {
            const int col = wn + nt * 8 + 2 * tig;
            float2 gv = *reinterpret_cast<const float2*>(&lng[col]);
            float2 bv = *reinterpret_cast<const float2*>(&lnb[col]);
            float2 o0 = make_float2((acc[mt][nt][0] - mu0) * rs0 * gv.x + bv.x,
                                    (acc[mt][nt][1] - mu0) * rs0 * gv.y + bv.y);
            float2 o1 = make_float2((acc[mt][nt][2] - mu1) * rs1 * gv.x + bv.x,
                                    (acc[mt][nt][3] - mu1) * rs1 * gv.y + bv.y);
            *reinterpret_cast<float2*>(&C[(size_t)r0 * 256 + col]) = o0;
            *reinterpret_cast<float2*>(&C[(size_t)r1 * 256 + col]) = o1;
        }
    }
}

__global__ __launch_bounds__(256) void tf32_gemm(
    const float* __restrict__ A, const float* __restrict__ B, float* __restrict__ C,
    int Kk, int Mm, const float* __restrict__ bias, int relu,
    const float* __restrict__ resid, const float* __restrict__ lng,
    const float* __restrict__ lnb)
{
    extern __shared__ float sm[];
    gemm_body(sm, A, B, C, Kk, Mm, bias, relu, resid, lng, lnb);
}

__global__ __launch_bounds__(256) void tf32_gemm_qkv(
    const float* __restrict__ A0, const float* __restrict__ A1, const float* __restrict__ A2,
    const float* __restrict__ B0, const float* __restrict__ B1, const float* __restrict__ B2,
    float* __restrict__ C0, float* __restrict__ C1, float* __restrict__ C2)
{
    extern __shared__ float sm[];
    const float* A = (blockIdx.z == 0) ? A0 : (blockIdx.z == 1 ? A1 : A2);
    const float* B = (blockIdx.z == 0) ? B0 : (blockIdx.z == 1 ? B1 : B2);
    float*       C = (blockIdx.z == 0) ? C0 : (blockIdx.z == 1 ? C1 : C2);
    gemm_body(sm, A, B, C, DD, DD, nullptr, 0, nullptr, nullptr, nullptr);
}

// ------------------------- edge pass A: logits + exp + segment sum ----------------
__global__ void edge_logits_exp(const float* __restrict__ q, const float* __restrict__ k,
                                const float* __restrict__ ak, const int* __restrict__ etype,
                                const int* __restrict__ src, const int* __restrict__ dst,
                                float* __restrict__ ex_out, float* __restrict__ den, int E)
{
    int w = (blockIdx.x * blockDim.x + threadIdx.x) >> 5;
    int lane = threadIdx.x & 31;
    if (w >= E) return;
    int s = src[w], d0 = dst[w];
    const float4* kr = reinterpret_cast<const float4*>(k + (size_t)s * DD);
    const float4* qr = reinterpret_cast<const float4*>(q + (size_t)d0 * DD);
    float4 k0 = kr[lane * 2],     k1 = kr[lane * 2 + 1];
    float4 q0 = qr[lane * 2],     q1 = qr[lane * 2 + 1];
    if (ak) {
        const float4* ar = reinterpret_cast<const float4*>(ak + (size_t)etype[w] * DKK);
        float4 a0 = ar[(lane & 3) * 2], a1 = ar[(lane & 3) * 2 + 1];
        k0.x += a0.x; k0.y += a0.y; k0.z += a0.z; k0.w += a0.w;
        k1.x += a1.x; k1.y += a1.y; k1.z += a1.z; k1.w += a1.w;
    }
    float p = k0.x * q0.x + k0.y * q0.y + k0.z * q0.z + k0.w * q0.w
            + k1.x * q1.x + k1.y * q1.y + k1.z * q1.z + k1.w * q1.w;
    p += __shfl_xor_sync(0xffffffffu, p, 1);
    p += __shfl_xor_sync(0xffffffffu, p, 2);
    float hv = __shfl_sync(0xffffffffu, p, (lane & 7) * 4);
    if (lane < HH) {
        float ex = __expf(hv * SCALEv);
        ex_out[(size_t)w * HH + lane] = ex;
        atomicAdd(&den[d0 * HH + lane], ex);
    }
}

// ------------------------- reciprocal of denominators -----------------------------
__global__ void recip_kernel(float* __restrict__ den, int n)
{
    int i = blockIdx.x * blockDim.x + threadIdx.x;
    if (i < n) den[i] = __frcp_rn(den[i]);
}

// ------------------------- edge pass B: normalized scatter-aggregate --------------
__global__ void edge_aggregate(const float* __restrict__ ex, const float* __restrict__ rden,
                               const float* __restrict__ v, const int* __restrict__ src,
                               const int* __restrict__ dst, float* __restrict__ agg, int E)
{
    int w = (blockIdx.x * blockDim.x + threadIdx.x) >> 5;
    int lane = threadIdx.x & 31;
    if (w >= E) return;
    int s = src[w], d0 = dst[w];
    float a = 0.f;
    if (lane < HH) a = ex[(size_t)w * HH + lane] * rden[d0 * HH + lane];
    const float4* vr = reinterpret_cast<const float4*>(v + (size_t)s * DD);
    float4 v0 = vr[lane * 2], v1 = vr[lane * 2 + 1];
    float ah = __shfl_sync(0xffffffffu, a, lane >> 2);
    float* arow = agg + (size_t)d0 * DD + lane * 8;
    red_add_v4(arow,     ah * v0.x, ah * v0.y, ah * v0.z, ah * v0.w);
    red_add_v4(arow + 4, ah * v1.x, ah * v1.y, ah * v1.z, ah * v1.w);
}

// ------------------------- host launch -------------------------
extern "C" void kernel_launch(void* const* d_in, const int* in_sizes, int n_in,
                              void* d_out, int out_size)
{
    const float *h = nullptr, *mem = nullptr, *ak = nullptr, *bf1 = nullptr;
    const float *W[8] = {nullptr};
    const float *Wf[2] = {nullptr};
    const float *v256[8] = {nullptr};
    const int *src_intra = nullptr, *dst_intra = nullptr, *etype = nullptr;
    const int *src_inter = nullptr, *dst_inter = nullptr;
    int c16 = 0, c1m = 0, c512k = 0, c64k = 0, c262k = 0, c256 = 0;

    for (int i = 0; i < n_in; i++) {
        int sz = in_sizes[i];
        void* p = d_in[i];
        if (sz == 16777216)      { if (c16 == 0) h = (const float*)p; else mem = (const float*)p; c16++; }
        else if (sz == 1048576)  { if (c1m == 0) src_intra = (const int*)p;
                                   else if (c1m == 1) dst_intra = (const int*)p;
                                   else etype = (const int*)p; c1m++; }
        else if (sz == 524288)   { if (c512k == 0) src_inter = (const int*)p; else dst_inter = (const int*)p; c512k++; }
        else if (sz == 65536)    { if (c64k < 8) W[c64k] = (const float*)p; c64k++; }
        else if (sz == 32000)    { ak = (const float*)p; }
        else if (sz == 262144)   { if (c262k < 2) Wf[c262k] = (const float*)p; c262k++; }
        else if (sz == 1024)     { bf1 = (const float*)p; }
        else if (sz == 256)      { if (c256 < 8) v256[c256] = (const float*)p; c256++; }
    }
    const float *ln0_g = v256[0], *ln0_b = v256[1];
    const float *ln1_g = v256[2], *ln1_b = v256[3];
    const float *ln2_g = v256[4], *ln2_b = v256[5];
    const float *bf2   = v256[6];

    float *q, *k, *v, *agg, *h1, *e, *den, *ffn;
    cudaGetSymbolAddress((void**)&q,   g_q);
    cudaGetSymbolAddress((void**)&k,   g_k);
    cudaGetSymbolAddress((void**)&v,   g_v);
    cudaGetSymbolAddress((void**)&agg, g_agg);
    cudaGetSymbolAddress((void**)&h1,  g_h1);
    cudaGetSymbolAddress((void**)&e,   g_e);
    cudaGetSymbolAddress((void**)&den, g_den);
    cudaGetSymbolAddress((void**)&ffn, g_ffn);

    float* out = (float*)d_out;

    cudaFuncSetAttribute(tf32_gemm,     cudaFuncAttributeMaxDynamicSharedMemorySize, SMEM_GEMM);
    cudaFuncSetAttribute(tf32_gemm_qkv, cudaFuncAttributeMaxDynamicSharedMemorySize, SMEM_GEMM);

    dim3 gQKV(1, NN / GBM, 3);        // (1, 512, 3)
    dim3 gD(1, NN / GBM);             // N=256 GEMMs
    dim3 gF1(DFFv / GBN, NN / GBM);   // (4, 512)

    // ---------------- stage 1: intra attention ----------------
    tf32_gemm_qkv<<<gQKV, 256, SMEM_GEMM>>>(h, h, h, W[0], W[1], W[2], q, k, v);
    cudaMemsetAsync(den, 0, (size_t)NN * HH * sizeof(float));
    cudaMemsetAsync(agg, 0, (size_t)NN * DD * sizeof(float));
    edge_logits_exp<<<E1v / 8,   256>>>(q, k, ak, etype, src_intra, dst_intra, e, den, E1v);
    recip_kernel   <<<NN * HH / 256, 256>>>(den, NN * HH);
    edge_aggregate <<<E1v / 8,   256>>>(e, den, v, src_intra, dst_intra, agg, E1v);
    // Wo0 + residual(h) + LN0 -> h1
    tf32_gemm<<<gD, 256, SMEM_GEMM>>>(agg, W[3], h1, DD, DD, nullptr, 0, h, ln0_g, ln0_b);

    // ---------------- stage 2: inter (memory) attention ----------------
    tf32_gemm_qkv<<<gQKV, 256, SMEM_GEMM>>>(h1, mem, mem, W[4], W[5], W[6], q, k, v);
    cudaMemsetAsync(den, 0, (size_t)NN * HH * sizeof(float));
    cudaMemsetAsync(agg, 0, (size_t)NN * DD * sizeof(float));
    edge_logits_exp<<<E2v / 8,   256>>>(q, k, nullptr, nullptr, src_inter, dst_inter, e, den, E2v);
    recip_kernel   <<<NN * HH / 256, 256>>>(den, NN * HH);
    edge_aggregate <<<E2v / 8,   256>>>(e, den, v, src_inter, dst_inter, agg, E2v);
    // Wo1 + residual(h1) + LN1 -> h1 (in place; each block owns its rows)
    tf32_gemm<<<gD, 256, SMEM_GEMM>>>(agg, W[7], h1, DD, DD, nullptr, 0, h1, ln1_g, ln1_b);

    // ---------------- FFN + final norm ----------------
    tf32_gemm<<<gF1, 256, SMEM_GEMM>>>(h1, Wf[0], ffn, DD, DFFv, bf1, 1,
                                       nullptr, nullptr, nullptr);
    // FFN2 + bias + residual(h1) + LN2 -> out
    tf32_gemm<<<gD, 256, SMEM_GEMM>>>(ffn, Wf[1], out, DFFv, DD, bf2, 0, h1, ln2_g, ln2_b);
}

// round 6
// speedup vs baseline: 2.5174x; 1.0089x over previous
#include <cuda_runtime.h>
#include <cuda_bf16.h>
#include <math.h>

#define NN   65536
#define DD   256
#define HH   8
#define DKK  32
#define DFFv 1024
#define E1v  1048576
#define E2v  524288
#define EPSv 1e-5f
#define SCALEv 0.17677669529663687f  // 1/sqrt(32)
#define GBK 32

// ------------------------- scratch (static device globals) -------------------------
__device__ float g_q[NN * DD];
__device__ float g_k[NN * DD];
__device__ float g_v[NN * DD];
__device__ float g_agg[NN * DD];
__device__ float g_h1[NN * DD];
__device__ float g_den[NN * HH];
__device__ float g_ffn[(size_t)NN * DFFv];

// ------------------------- helpers -------------------------
__device__ __forceinline__ unsigned f2tf32(float f) {
    unsigned r;
    asm("cvt.rna.tf32.f32 %0, %1;" : "=r"(r) : "f"(f));
    return r;
}
__device__ __forceinline__ void red_add_v4(float* p, float a, float b, float c, float d) {
    asm volatile("red.global.add.v4.f32 [%0], {%1,%2,%3,%4};"
                 :: "l"(p), "f"(a), "f"(b), "f"(c), "f"(d) : "memory");
}
__device__ __forceinline__ void cp16(float* smem, const float* g) {
    unsigned saddr = (unsigned)__cvta_generic_to_shared(smem);
    asm volatile("cp.async.cg.shared.global [%0], [%1], 16;" :: "r"(saddr), "l"(g));
}
#define CP_COMMIT() asm volatile("cp.async.commit_group;")
#define CP_WAIT1()  asm volatile("cp.async.wait_group 1;")
#define CP_WAIT0()  asm volatile("cp.async.wait_group 0;")

// ------------------------- templated TF32 GEMM core -------------------------------
// warp tile 32x64; 8 warps => (GBM_/32)*(GBN_/64) must be 8.
template<int GBM_, int GBN_, int NST, bool LNFUSE>
__device__ __forceinline__ void gemm_core(
    const float* __restrict__ A, const float* __restrict__ B, float* __restrict__ C,
    int Kk, int Mm, const float* __restrict__ bias, int relu,
    const float* __restrict__ resid, const float* __restrict__ lng,
    const float* __restrict__ lnb)
{
    constexpr int AST_ = 36;
    constexpr int BST_ = GBN_ + 8;
    constexpr int AW   = GBM_ * AST_;
    constexpr int BW   = GBK * BST_;
    constexpr int SW   = AW + BW;
    constexpr int MW   = GBM_ / 32;

    extern __shared__ float sm[];

    const int tid  = threadIdx.x;
    const int bm   = blockIdx.y * GBM_;
    const int bn   = blockIdx.x * GBN_;
    const int wid  = tid >> 5;
    const int lane = tid & 31;
    const int wm   = (wid % MW) * 32;
    const int wn   = (wid / MW) * 64;
    const int gid  = lane >> 2;
    const int tig  = lane & 3;

    float acc[2][8][4];
#pragma unroll
    for (int mt = 0; mt < 2; mt++)
#pragma unroll
        for (int nt = 0; nt < 8; nt++)
#pragma unroll
            for (int c = 0; c < 4; c++) acc[mt][nt][c] = 0.f;

    const int nIter = Kk / GBK;

    auto issue = [&](int it) {
        float* As = sm + (it % NST) * SW;
        float* Bs = As + AW;
        const int k0 = it * GBK;
#pragma unroll
        for (int i = 0; i < GBM_ / 32; i++) {
            int c = tid + 256 * i;
            int r = c >> 3, cc = (c & 7) * 4;
            cp16(&As[r * AST_ + cc], &A[(size_t)(bm + r) * Kk + k0 + cc]);
        }
#pragma unroll
        for (int i = 0; i < GBN_ / 32; i++) {
            int c = tid + 256 * i;
            int r = c / (GBN_ / 4), cc = (c % (GBN_ / 4)) * 4;
            cp16(&Bs[r * BST_ + cc], &B[(size_t)(k0 + r) * Mm + bn + cc]);
        }
        CP_COMMIT();
    };

    issue(0);
    if (nIter > 1) issue(1);

    for (int it = 0; it < nIter; it++) {
        if (it + 1 < nIter) { CP_WAIT1(); } else { CP_WAIT0(); }
        __syncthreads();
        if (NST >= 3 && it + 2 < nIter) issue(it + 2);

        const float* As = sm + (it % NST) * SW;
        const float* Bs = As + AW;

#pragma unroll
        for (int ks = 0; ks < 4; ks++) {
            const int kb = ks * 8;
            unsigned af[2][4];
#pragma unroll
            for (int mt = 0; mt < 2; mt++) {
                const int mr = wm + mt * 16 + gid;
                af[mt][0] = f2tf32(As[mr * AST_ + kb + tig]);
                af[mt][1] = f2tf32(As[(mr + 8) * AST_ + kb + tig]);
                af[mt][2] = f2tf32(As[mr * AST_ + kb + tig + 4]);
                af[mt][3] = f2tf32(As[(mr + 8) * AST_ + kb + tig + 4]);
            }
            unsigned bf[8][2];
#pragma unroll
            for (int nt = 0; nt < 8; nt++) {
                const int nc = wn + nt * 8 + gid;
                bf[nt][0] = f2tf32(Bs[(kb + tig) * BST_ + nc]);
                bf[nt][1] = f2tf32(Bs[(kb + tig + 4) * BST_ + nc]);
            }
#pragma unroll
            for (int mt = 0; mt < 2; mt++)
#pragma unroll
                for (int nt = 0; nt < 8; nt++) {
                    asm volatile(
                        "mma.sync.aligned.m16n8k8.row.col.f32.tf32.tf32.f32 "
                        "{%0,%1,%2,%3}, {%4,%5,%6,%7}, {%8,%9}, {%0,%1,%2,%3};"
                        : "+f"(acc[mt][nt][0]), "+f"(acc[mt][nt][1]),
                          "+f"(acc[mt][nt][2]), "+f"(acc[mt][nt][3])
                        : "r"(af[mt][0]), "r"(af[mt][1]), "r"(af[mt][2]), "r"(af[mt][3]),
                          "r"(bf[nt][0]), "r"(bf[nt][1]));
                }
        }

        if (NST == 2 && it + 2 < nIter) {
            __syncthreads();
            issue(it + 2);
        }
    }

    if (!LNFUSE) {
#pragma unroll
        for (int mt = 0; mt < 2; mt++) {
            const int row0 = bm + wm + mt * 16 + gid;
#pragma unroll
            for (int nt = 0; nt < 8; nt++) {
                const int col = bn + wn + nt * 8 + 2 * tig;
                float b0 = 0.f, b1 = 0.f;
                if (bias) { b0 = bias[col]; b1 = bias[col + 1]; }
                float2 v0 = make_float2(acc[mt][nt][0] + b0, acc[mt][nt][1] + b1);
                float2 v1 = make_float2(acc[mt][nt][2] + b0, acc[mt][nt][3] + b1);
                if (relu) {
                    v0.x = fmaxf(v0.x, 0.f); v0.y = fmaxf(v0.y, 0.f);
                    v1.x = fmaxf(v1.x, 0.f); v1.y = fmaxf(v1.y, 0.f);
                }
                *reinterpret_cast<float2*>(&C[(size_t)row0 * Mm + col]) = v0;
                *reinterpret_cast<float2*>(&C[(size_t)(row0 + 8) * Mm + col]) = v1;
            }
        }
        return;
    }

    // ---------- fused residual + LayerNorm epilogue (Mm==256, gridDim.x==1) ----------
#pragma unroll
    for (int mt = 0; mt < 2; mt++) {
        const int r0 = bm + wm + mt * 16 + gid;
        const int r1 = r0 + 8;
#pragma unroll
        for (int nt = 0; nt < 8; nt++) {
            const int col = wn + nt * 8 + 2 * tig;
            float b0 = 0.f, b1 = 0.f;
            if (bias) { b0 = bias[col]; b1 = bias[col + 1]; }
            float2 xa = *reinterpret_cast<const float2*>(&resid[(size_t)r0 * 256 + col]);
            float2 xb = *reinterpret_cast<const float2*>(&resid[(size_t)r1 * 256 + col]);
            acc[mt][nt][0] += b0 + xa.x; acc[mt][nt][1] += b1 + xa.y;
            acc[mt][nt][2] += b0 + xb.x; acc[mt][nt][3] += b1 + xb.y;
        }
    }

    __syncthreads();
    float* sums  = sm;
    float* sumsq = sm + GBM_;
    if (tid < GBM_) { sums[tid] = 0.f; sumsq[tid] = 0.f; }
    __syncthreads();

#pragma unroll
    for (int mt = 0; mt < 2; mt++) {
        float sA = 0.f, qA = 0.f, sB = 0.f, qB = 0.f;
#pragma unroll
        for (int nt = 0; nt < 8; nt++) {
            sA += acc[mt][nt][0] + acc[mt][nt][1];
            qA += acc[mt][nt][0] * acc[mt][nt][0] + acc[mt][nt][1] * acc[mt][nt][1];
            sB += acc[mt][nt][2] + acc[mt][nt][3];
            qB += acc[mt][nt][2] * acc[mt][nt][2] + acc[mt][nt][3] * acc[mt][nt][3];
        }
        sA += __shfl_xor_sync(0xffffffffu, sA, 1); sA += __shfl_xor_sync(0xffffffffu, sA, 2);
        qA += __shfl_xor_sync(0xffffffffu, qA, 1); qA += __shfl_xor_sync(0xffffffffu, qA, 2);
        sB += __shfl_xor_sync(0xffffffffu, sB, 1); sB += __shfl_xor_sync(0xffffffffu, sB, 2);
        qB += __shfl_xor_sync(0xffffffffu, qB, 1); qB += __shfl_xor_sync(0xffffffffu, qB, 2);
        if (tig == 0) {
            const int lr = wm + mt * 16 + gid;
            atomicAdd(&sums[lr], sA);     atomicAdd(&sumsq[lr], qA);
            atomicAdd(&sums[lr + 8], sB); atomicAdd(&sumsq[lr + 8], qB);
        }
    }
    __syncthreads();

    const float inv = 1.f / 256.f;
#pragma unroll
    for (int mt = 0; mt < 2; mt++) {
        const int lr0 = wm + mt * 16 + gid;
        const int lr1 = lr0 + 8;
        const float mu0 = sums[lr0] * inv;
        const float mu1 = sums[lr1] * inv;
        const float rs0 = rsqrtf(sumsq[lr0] * inv - mu0 * mu0 + EPSv);
        const float rs1 = rsqrtf(sumsq[lr1] * inv - mu1 * mu1 + EPSv);
        const int r0 = bm + lr0, r1 = bm + lr1;
#pragma unroll
        for (int nt = 0; nt < 8; nt++) {
            const int col = wn + nt * 8 + 2 * tig;
            float2 gv = *reinterpret_cast<const float2*>(&lng[col]);
            float2 bv = *reinterpret_cast<const float2*>(&lnb[col]);
            float2 o0 = make_float2((acc[mt][nt][0] - mu0) * rs0 * gv.x + bv.x,
                                    (acc[mt][nt][1] - mu0) * rs0 * gv.y + bv.y);
            float2 o1 = make_float2((acc[mt][nt][2] - mu1) * rs1 * gv.x + bv.x,
                                    (acc[mt][nt][3] - mu1) * rs1 * gv.y + bv.y);
            *reinterpret_cast<float2*>(&C[(size_t)r0 * 256 + col]) = o0;
            *reinterpret_cast<float2*>(&C[(size_t)r1 * 256 + col]) = o1;
        }
    }
}

#define SMEM_A (3 * (128 * 36 + GBK * 136) * 4)   // 107,520 B
#define SMEM_B (2 * (64 * 36 + GBK * 264) * 4)    // 86,016 B

__global__ __launch_bounds__(256, 2) void gemmA(
    const float* __restrict__ A, const float* __restrict__ B, float* __restrict__ C,
    int Kk, int Mm, const float* __restrict__ bias, int relu)
{
    gemm_core<128, 128, 3, false>(A, B, C, Kk, Mm, bias, relu, nullptr, nullptr, nullptr);
}

__global__ __launch_bounds__(256, 2) void gemmA_qkv(
    const float* __restrict__ A0, const float* __restrict__ A1, const float* __restrict__ A2,
    const float* __restrict__ B0, const float* __restrict__ B1, const float* __restrict__ B2,
    float* __restrict__ C0, float* __restrict__ C1, float* __restrict__ C2)
{
    const float* A = (blockIdx.z == 0) ? A0 : (blockIdx.z == 1 ? A1 : A2);
    const float* B = (blockIdx.z == 0) ? B0 : (blockIdx.z == 1 ? B1 : B2);
    float*       C = (blockIdx.z == 0) ? C0 : (blockIdx.z == 1 ? C1 : C2);
    gemm_core<128, 128, 3, false>(A, B, C, DD, DD, nullptr, 0, nullptr, nullptr, nullptr);
}

__global__ __launch_bounds__(256, 2) void gemmB_ln(
    const float* __restrict__ A, const float* __restrict__ B, float* __restrict__ C,
    int Kk, const float* __restrict__ bias,
    const float* __restrict__ resid, const float* __restrict__ lng,
    const float* __restrict__ lnb)
{
    gemm_core<64, 256, 2, true>(A, B, C, Kk, 256, bias, 0, resid, lng, lnb);
}

// ------------------------- fused edge pass: logits+exp+den+aggregate --------------
// warp per edge; aggregates UNNORMALIZED exp(e)*v into agg, exp(e) into den.
__global__ void edge_attn(const float* __restrict__ q, const float* __restrict__ k,
                          const float* __restrict__ v,
                          const float* __restrict__ ak, const int* __restrict__ etype,
                          const int* __restrict__ src, const int* __restrict__ dst,
                          float* __restrict__ den, float* __restrict__ agg, int E)
{
    int w = (blockIdx.x * blockDim.x + threadIdx.x) >> 5;
    int lane = threadIdx.x & 31;
    if (w >= E) return;
    int s = src[w], d0 = dst[w];
    const float4* kr = reinterpret_cast<const float4*>(k + (size_t)s * DD);
    const float4* qr = reinterpret_cast<const float4*>(q + (size_t)d0 * DD);
    const float4* vr = reinterpret_cast<const float4*>(v + (size_t)s * DD);
    float4 k0 = kr[lane * 2], k1 = kr[lane * 2 + 1];
    float4 q0 = qr[lane * 2], q1 = qr[lane * 2 + 1];
    float4 v0 = vr[lane * 2], v1 = vr[lane * 2 + 1];
    if (ak) {
        const float4* ar = reinterpret_cast<const float4*>(ak + (size_t)etype[w] * DKK);
        float4 a0 = ar[(lane & 3) * 2], a1 = ar[(lane & 3) * 2 + 1];
        k0.x += a0.x; k0.y += a0.y; k0.z += a0.z; k0.w += a0.w;
        k1.x += a1.x; k1.y += a1.y; k1.z += a1.z; k1.w += a1.w;
    }
    float p = k0.x * q0.x + k0.y * q0.y + k0.z * q0.z + k0.w * q0.w
            + k1.x * q1.x + k1.y * q1.y + k1.z * q1.z + k1.w * q1.w;
    p += __shfl_xor_sync(0xffffffffu, p, 1);
    p += __shfl_xor_sync(0xffffffffu, p, 2);    // each lane now holds its own head's dot
    float wgt = __expf(p * SCALEv);             // weight for head lane>>2
    // den: lanes 0..7 add their head's exp
    float ph = __shfl_sync(0xffffffffu, p, (lane & 7) * 4);
    if (lane < HH) atomicAdd(&den[d0 * HH + lane], __expf(ph * SCALEv));
    float* arow = agg + (size_t)d0 * DD + lane * 8;
    red_add_v4(arow,     wgt * v0.x, wgt * v0.y, wgt * v0.z, wgt * v0.w);
    red_add_v4(arow + 4, wgt * v1.x, wgt * v1.y, wgt * v1.z, wgt * v1.w);
}

// ------------------------- normalize agg by den (in place) ------------------------
__global__ void normalize_agg(float* __restrict__ agg, const float* __restrict__ den)
{
    int i = blockIdx.x * blockDim.x + threadIdx.x;   // one float4 per thread
    int n  = i >> 6;                                  // 64 float4 per row
    int c4 = i & 63;                                  // head = c4>>3
    float dv = den[n * HH + (c4 >> 3)];
    float r = dv > 0.f ? __frcp_rn(dv) : 0.f;         // empty segment -> 0 (matches ref)
    float4 a = reinterpret_cast<float4*>(agg)[i];
    a.x *= r; a.y *= r; a.z *= r; a.w *= r;
    reinterpret_cast<float4*>(agg)[i] = a;
}

// ------------------------- host launch -------------------------
extern "C" void kernel_launch(void* const* d_in, const int* in_sizes, int n_in,
                              void* d_out, int out_size)
{
    const float *h = nullptr, *mem = nullptr, *ak = nullptr, *bf1 = nullptr;
    const float *W[8] = {nullptr};
    const float *Wf[2] = {nullptr};
    const float *v256[8] = {nullptr};
    const int *src_intra = nullptr, *dst_intra = nullptr, *etype = nullptr;
    const int *src_inter = nullptr, *dst_inter = nullptr;
    int c16 = 0, c1m = 0, c512k = 0, c64k = 0, c262k = 0, c256 = 0;

    for (int i = 0; i < n_in; i++) {
        int sz = in_sizes[i];
        void* p = d_in[i];
        if (sz == 16777216)      { if (c16 == 0) h = (const float*)p; else mem = (const float*)p; c16++; }
        else if (sz == 1048576)  { if (c1m == 0) src_intra = (const int*)p;
                                   else if (c1m == 1) dst_intra = (const int*)p;
                                   else etype = (const int*)p; c1m++; }
        else if (sz == 524288)   { if (c512k == 0) src_inter = (const int*)p; else dst_inter = (const int*)p; c512k++; }
        else if (sz == 65536)    { if (c64k < 8) W[c64k] = (const float*)p; c64k++; }
        else if (sz == 32000)    { ak = (const float*)p; }
        else if (sz == 262144)   { if (c262k < 2) Wf[c262k] = (const float*)p; c262k++; }
        else if (sz == 1024)     { bf1 = (const float*)p; }
        else if (sz == 256)      { if (c256 < 8) v256[c256] = (const float*)p; c256++; }
    }
    const float *ln0_g = v256[0], *ln0_b = v256[1];
    const float *ln1_g = v256[2], *ln1_b = v256[3];
    const float *ln2_g = v256[4], *ln2_b = v256[5];
    const float *bf2   = v256[6];

    float *q, *k, *v, *agg, *h1, *den, *ffn;
    cudaGetSymbolAddress((void**)&q,   g_q);
    cudaGetSymbolAddress((void**)&k,   g_k);
    cudaGetSymbolAddress((void**)&v,   g_v);
    cudaGetSymbolAddress((void**)&agg, g_agg);
    cudaGetSymbolAddress((void**)&h1,  g_h1);
    cudaGetSymbolAddress((void**)&den, g_den);
    cudaGetSymbolAddress((void**)&ffn, g_ffn);

    float* out = (float*)d_out;

    cudaFuncSetAttribute(gemmA,     cudaFuncAttributeMaxDynamicSharedMemorySize, SMEM_A);
    cudaFuncSetAttribute(gemmA_qkv, cudaFuncAttributeMaxDynamicSharedMemorySize, SMEM_A);
    cudaFuncSetAttribute(gemmB_ln,  cudaFuncAttributeMaxDynamicSharedMemorySize, SMEM_B);

    dim3 gQKV(DD / 128, NN / 128, 3);   // (2, 512, 3)
    dim3 gLN(1, NN / 64);               // (1, 1024)
    dim3 gF1(DFFv / 128, NN / 128);     // (8, 512)
    const int NORM_BLKS = NN * DD / 4 / 256;

    // ---------------- stage 1: intra attention ----------------
    gemmA_qkv<<<gQKV, 256, SMEM_A>>>(h, h, h, W[0], W[1], W[2], q, k, v);
    cudaMemsetAsync(den, 0, (size_t)NN * HH * sizeof(float));
    cudaMemsetAsync(agg, 0, (size_t)NN * DD * sizeof(float));
    edge_attn<<<E1v / 8, 256>>>(q, k, v, ak, etype, src_intra, dst_intra, den, agg, E1v);
    normalize_agg<<<NORM_BLKS, 256>>>(agg, den);
    gemmB_ln<<<gLN, 256, SMEM_B>>>(agg, W[3], h1, DD, nullptr, h, ln0_g, ln0_b);

    // ---------------- stage 2: inter (memory) attention ----------------
    gemmA_qkv<<<gQKV, 256, SMEM_A>>>(h1, mem, mem, W[4], W[5], W[6], q, k, v);
    cudaMemsetAsync(den, 0, (size_t)NN * HH * sizeof(float));
    cudaMemsetAsync(agg, 0, (size_t)NN * DD * sizeof(float));
    edge_attn<<<E2v / 8, 256>>>(q, k, v, nullptr, nullptr, src_inter, dst_inter, den, agg, E2v);
    normalize_agg<<<NORM_BLKS, 256>>>(agg, den);
    gemmB_ln<<<gLN, 256, SMEM_B>>>(agg, W[7], h1, DD, nullptr, h1, ln1_g, ln1_b);

    // ---------------- FFN + final norm ----------------
    gemmA<<<gF1, 256, SMEM_A>>>(h1, Wf[0], ffn, DD, DFFv, bf1, 1);
    gemmB_ln<<<gLN, 256, SMEM_B>>>(ffn, Wf[1], out, DFFv, bf2, h1, ln2_g, ln2_b);
}

// round 7
// speedup vs baseline: 2.9552x; 1.1739x over previous
#include <cuda_runtime.h>
#include <cuda_bf16.h>
#include <math.h>

#define NN   65536
#define DD   256
#define HH   8
#define DKK  32
#define DFFv 1024
#define E1v  1048576
#define E2v  524288
#define EPSv 1e-5f
#define SCALEv 0.17677669529663687f  // 1/sqrt(32)
#define GBK 32
#define QKVS 768                     // packed qkv row stride

// ------------------------- scratch (static device globals) -------------------------
__device__ float g_qkv[(size_t)NN * QKVS];
__device__ float g_agg[NN * DD];
__device__ float g_h1[NN * DD];
__device__ float g_ffn[(size_t)NN * DFFv];
__device__ float g_wqkv0[DD * QKVS];
__device__ float g_wqkv1[DD * QKVS];
__device__ float g_wo0r[DD * DD];
__device__ float g_wo1r[DD * DD];
__device__ float g_wf1r[DD * DFFv];
__device__ float g_wf2r[DFFv * DD];
__device__ int   g_cnt[NN];
__device__ int   g_wr[NN];
__device__ int   g_rowptr[NN + 1];
__device__ int   g_srcs[E1v];
__device__ int   g_ets[E1v];

// ------------------------- helpers -------------------------
__device__ __forceinline__ unsigned f2tf32(float f) {
    unsigned r;
    asm("cvt.rna.tf32.f32 %0, %1;" : "=r"(r) : "f"(f));
    return r;
}
__device__ __forceinline__ float tf32r(float f) { return __uint_as_float(f2tf32(f)); }
__device__ __forceinline__ void cp16(float* smem, const float* g) {
    unsigned saddr = (unsigned)__cvta_generic_to_shared(smem);
    asm volatile("cp.async.cg.shared.global [%0], [%1], 16;" :: "r"(saddr), "l"(g));
}
#define CP_COMMIT() asm volatile("cp.async.commit_group;")
#define CP_WAIT1()  asm volatile("cp.async.wait_group 1;")
#define CP_WAIT0()  asm volatile("cp.async.wait_group 0;")

// ------------------------- weight prep (rounded to tf32 once per launch) ----------
__global__ void pack_qkv_w(const float* __restrict__ Wq, const float* __restrict__ Wk,
                           const float* __restrict__ Wv, float* __restrict__ out)
{
    int i = blockIdx.x * 256 + threadIdx.x;        // DD*QKVS total
    int r = i / QKVS, c = i % QKVS;
    const float* W = (c < 256) ? Wq : (c < 512 ? Wk : Wv);
    out[i] = tf32r(W[r * DD + (c & 255)]);
}
__global__ void round_w(const float* __restrict__ W, float* __restrict__ out, int n)
{
    int i = blockIdx.x * 256 + threadIdx.x;
    if (i < n) out[i] = tf32r(W[i]);
}

// ------------------------- templated TF32 GEMM core -------------------------------
// warp tile 32x64; 8 warps => (GBM_/32)*(GBN_/64) == 8. B pre-rounded to tf32.
template<int GBM_, int GBN_, int NST, bool LNFUSE>
__device__ __forceinline__ void gemm_core(
    const float* __restrict__ A, const float* __restrict__ B, float* __restrict__ C,
    int Kk, int Mm, int bn, const float* __restrict__ bias, int relu,
    const float* __restrict__ resid, const float* __restrict__ lng,
    const float* __restrict__ lnb)
{
    constexpr int AST_ = 36;
    constexpr int BST_ = GBN_ + 8;
    constexpr int AW   = GBM_ * AST_;
    constexpr int BW   = GBK * BST_;
    constexpr int SW   = AW + BW;
    constexpr int MW   = GBM_ / 32;

    extern __shared__ float sm[];

    const int tid  = threadIdx.x;
    const int bm   = blockIdx.y * GBM_;
    const int wid  = tid >> 5;
    const int lane = tid & 31;
    const int wm   = (wid % MW) * 32;
    const int wn   = (wid / MW) * 64;
    const int gid  = lane >> 2;
    const int tig  = lane & 3;

    float acc[2][8][4];
#pragma unroll
    for (int mt = 0; mt < 2; mt++)
#pragma unroll
        for (int nt = 0; nt < 8; nt++)
#pragma unroll
            for (int c = 0; c < 4; c++) acc[mt][nt][c] = 0.f;

    const int nIter = Kk / GBK;

    auto issue = [&](int it) {
        float* As = sm + (it % NST) * SW;
        float* Bs = As + AW;
        const int k0 = it * GBK;
#pragma unroll
        for (int i = 0; i < GBM_ / 32; i++) {
            int c = tid + 256 * i;
            int r = c >> 3, cc = (c & 7) * 4;
            cp16(&As[r * AST_ + cc], &A[(size_t)(bm + r) * Kk + k0 + cc]);
        }
#pragma unroll
        for (int i = 0; i < GBN_ / 32; i++) {
            int c = tid + 256 * i;
            int r = c / (GBN_ / 4), cc = (c % (GBN_ / 4)) * 4;
            cp16(&Bs[r * BST_ + cc], &B[(size_t)(k0 + r) * Mm + bn + cc]);
        }
        CP_COMMIT();
    };

    issue(0);
    if (nIter > 1) issue(1);

    for (int it = 0; it < nIter; it++) {
        if (it + 1 < nIter) { CP_WAIT1(); } else { CP_WAIT0(); }
        __syncthreads();
        if (NST >= 3 && it + 2 < nIter) issue(it + 2);

        const float* As = sm + (it % NST) * SW;
        const float* Bs = As + AW;

#pragma unroll
        for (int ks = 0; ks < 4; ks++) {
            const int kb = ks * 8;
            unsigned af[2][4];
#pragma unroll
            for (int mt = 0; mt < 2; mt++) {
                const int mr = wm + mt * 16 + gid;
                af[mt][0] = f2tf32(As[mr * AST_ + kb + tig]);
                af[mt][1] = f2tf32(As[(mr + 8) * AST_ + kb + tig]);
                af[mt][2] = f2tf32(As[mr * AST_ + kb + tig + 4]);
                af[mt][3] = f2tf32(As[(mr + 8) * AST_ + kb + tig + 4]);
            }
            unsigned bf[8][2];
#pragma unroll
            for (int nt = 0; nt < 8; nt++) {
                const int nc = wn + nt * 8 + gid;
                bf[nt][0] = __float_as_uint(Bs[(kb + tig) * BST_ + nc]);     // pre-rounded
                bf[nt][1] = __float_as_uint(Bs[(kb + tig + 4) * BST_ + nc]);
            }
#pragma unroll
            for (int mt = 0; mt < 2; mt++)
#pragma unroll
                for (int nt = 0; nt < 8; nt++) {
                    asm volatile(
                        "mma.sync.aligned.m16n8k8.row.col.f32.tf32.tf32.f32 "
                        "{%0,%1,%2,%3}, {%4,%5,%6,%7}, {%8,%9}, {%0,%1,%2,%3};"
                        : "+f"(acc[mt][nt][0]), "+f"(acc[mt][nt][1]),
                          "+f"(acc[mt][nt][2]), "+f"(acc[mt][nt][3])
                        : "r"(af[mt][0]), "r"(af[mt][1]), "r"(af[mt][2]), "r"(af[mt][3]),
                          "r"(bf[nt][0]), "r"(bf[nt][1]));
                }
        }

        if (NST == 2 && it + 2 < nIter) {
            __syncthreads();
            issue(it + 2);
        }
    }

    if (!LNFUSE) {
#pragma unroll
        for (int mt = 0; mt < 2; mt++) {
            const int row0 = bm + wm + mt * 16 + gid;
#pragma unroll
            for (int nt = 0; nt < 8; nt++) {
                const int col = bn + wn + nt * 8 + 2 * tig;
                float b0 = 0.f, b1 = 0.f;
                if (bias) { b0 = bias[col]; b1 = bias[col + 1]; }
                float2 v0 = make_float2(acc[mt][nt][0] + b0, acc[mt][nt][1] + b1);
                float2 v1 = make_float2(acc[mt][nt][2] + b0, acc[mt][nt][3] + b1);
                if (relu) {
                    v0.x = fmaxf(v0.x, 0.f); v0.y = fmaxf(v0.y, 0.f);
                    v1.x = fmaxf(v1.x, 0.f); v1.y = fmaxf(v1.y, 0.f);
                }
                *reinterpret_cast<float2*>(&C[(size_t)row0 * Mm + col]) = v0;
                *reinterpret_cast<float2*>(&C[(size_t)(row0 + 8) * Mm + col]) = v1;
            }
        }
        return;
    }

    // ---------- fused residual + LayerNorm epilogue (Mm==256, gridDim.x==1) ----------
#pragma unroll
    for (int mt = 0; mt < 2; mt++) {
        const int r0 = bm + wm + mt * 16 + gid;
        const int r1 = r0 + 8;
#pragma unroll
        for (int nt = 0; nt < 8; nt++) {
            const int col = wn + nt * 8 + 2 * tig;
            float b0 = 0.f, b1 = 0.f;
            if (bias) { b0 = bias[col]; b1 = bias[col + 1]; }
            float2 xa = *reinterpret_cast<const float2*>(&resid[(size_t)r0 * 256 + col]);
            float2 xb = *reinterpret_cast<const float2*>(&resid[(size_t)r1 * 256 + col]);
            acc[mt][nt][0] += b0 + xa.x; acc[mt][nt][1] += b1 + xa.y;
            acc[mt][nt][2] += b0 + xb.x; acc[mt][nt][3] += b1 + xb.y;
        }
    }

    __syncthreads();
    float* sums  = sm;
    float* sumsq = sm + GBM_;
    if (tid < GBM_) { sums[tid] = 0.f; sumsq[tid] = 0.f; }
    __syncthreads();

#pragma unroll
    for (int mt = 0; mt < 2; mt++) {
        float sA = 0.f, qA = 0.f, sB = 0.f, qB = 0.f;
#pragma unroll
        for (int nt = 0; nt < 8; nt++) {
            sA += acc[mt][nt][0] + acc[mt][nt][1];
            qA += acc[mt][nt][0] * acc[mt][nt][0] + acc[mt][nt][1] * acc[mt][nt][1];
            sB += acc[mt][nt][2] + acc[mt][nt][3];
            qB += acc[mt][nt][2] * acc[mt][nt][2] + acc[mt][nt][3] * acc[mt][nt][3];
        }
        sA += __shfl_xor_sync(0xffffffffu, sA, 1); sA += __shfl_xor_sync(0xffffffffu, sA, 2);
        qA += __shfl_xor_sync(0xffffffffu, qA, 1); qA += __shfl_xor_sync(0xffffffffu, qA, 2);
        sB += __shfl_xor_sync(0xffffffffu, sB, 1); sB += __shfl_xor_sync(0xffffffffu, sB, 2);
        qB += __shfl_xor_sync(0xffffffffu, qB, 1); qB += __shfl_xor_sync(0xffffffffu, qB, 2);
        if (tig == 0) {
            const int lr = wm + mt * 16 + gid;
            atomicAdd(&sums[lr], sA);     atomicAdd(&sumsq[lr], qA);
            atomicAdd(&sums[lr + 8], sB); atomicAdd(&sumsq[lr + 8], qB);
        }
    }
    __syncthreads();

    const float inv = 1.f / 256.f;
#pragma unroll
    for (int mt = 0; mt < 2; mt++) {
        const int lr0 = wm + mt * 16 + gid;
        const int lr1 = lr0 + 8;
        const float mu0 = sums[lr0] * inv;
        const float mu1 = sums[lr1] * inv;
        const float rs0 = rsqrtf(sumsq[lr0] * inv - mu0 * mu0 + EPSv);
        const float rs1 = rsqrtf(sumsq[lr1] * inv - mu1 * mu1 + EPSv);
        const int r0 = bm + lr0, r1 = bm + lr1;
#pragma unroll
        for (int nt = 0; nt < 8; nt++) {
            const int col = wn + nt * 8 + 2 * tig;
            float2 gv = *reinterpret_cast<const float2*>(&lng[col]);
            float2 bv = *reinterpret_cast<const float2*>(&lnb[col]);
            float2 o0 = make_float2((acc[mt][nt][0] - mu0) * rs0 * gv.x + bv.x,
                                    (acc[mt][nt][1] - mu0) * rs0 * gv.y + bv.y);
            float2 o1 = make_float2((acc[mt][nt][2] - mu1) * rs1 * gv.x + bv.x,
                                    (acc[mt][nt][3] - mu1) * rs1 * gv.y + bv.y);
            *reinterpret_cast<float2*>(&C[(size_t)r0 * 256 + col]) = o0;
            *reinterpret_cast<float2*>(&C[(size_t)r1 * 256 + col]) = o1;
        }
    }
}

#define SMEM_A (3 * (128 * 36 + GBK * 136) * 4)   // 107,520 B
#define SMEM_B (2 * (64 * 36 + GBK * 264) * 4)    // 86,016 B

__global__ __launch_bounds__(256, 2) void gemmA(
    const float* __restrict__ A, const float* __restrict__ B, float* __restrict__ C,
    int Kk, int Mm, const float* __restrict__ bias, int relu)
{
    gemm_core<128, 128, 3, false>(A, B, C, Kk, Mm, blockIdx.x * 128, bias, relu,
                                  nullptr, nullptr, nullptr);
}

// QKV fused: N = 768, C/B stride 768. A selected per column block (q-cols from A0, k/v from A1).
__global__ __launch_bounds__(256, 2) void gemm_qkv(
    const float* __restrict__ A0, const float* __restrict__ A1,
    const float* __restrict__ B, float* __restrict__ C)
{
    const int bn = blockIdx.x * 128;
    const float* A = (bn < 256) ? A0 : A1;
    gemm_core<128, 128, 3, false>(A, B, C, DD, QKVS, bn, nullptr, 0,
                                  nullptr, nullptr, nullptr);
}

__global__ __launch_bounds__(256, 2) void gemmB_ln(
    const float* __restrict__ A, const float* __restrict__ B, float* __restrict__ C,
    int Kk, const float* __restrict__ bias,
    const float* __restrict__ resid, const float* __restrict__ lng,
    const float* __restrict__ lnb)
{
    gemm_core<64, 256, 2, true>(A, B, C, Kk, 256, 0, bias, 0, resid, lng, lnb);
}

// ------------------------- CSR build ----------------------------------------------
__global__ void hist_kernel(const int* __restrict__ dst, int* __restrict__ cnt, int E)
{
    int e = blockIdx.x * blockDim.x + threadIdx.x;
    if (e < E) atomicAdd(&cnt[dst[e]], 1);
}

__global__ __launch_bounds__(1024) void scan64k(
    const int* __restrict__ cnt, int* __restrict__ rowptr, int* __restrict__ wr)
{
    __shared__ int ss[1024];
    const int tid = threadIdx.x;
    const int base = tid * 64;
    int s = 0;
#pragma unroll
    for (int i = 0; i < 64; i++) s += cnt[base + i];
    ss[tid] = s;
    __syncthreads();
#pragma unroll
    for (int off = 1; off < 1024; off <<= 1) {
        int t = (tid >= off) ? ss[tid - off] : 0;
        __syncthreads();
        ss[tid] += t;
        __syncthreads();
    }
    int run = ss[tid] - s;   // exclusive prefix of this thread's chunk
    for (int i = 0; i < 64; i++) {
        rowptr[base + i] = run;
        wr[base + i] = run;
        run += cnt[base + i];
    }
    if (tid == 1023) rowptr[NN] = run;
}

__global__ void scatter_csr(const int* __restrict__ src, const int* __restrict__ dst,
                            const int* __restrict__ et, int* __restrict__ wr,
                            int* __restrict__ srcs, int* __restrict__ ets, int E)
{
    int e = blockIdx.x * blockDim.x + threadIdx.x;
    if (e >= E) return;
    int pos = atomicAdd(&wr[dst[e]], 1);
    srcs[pos] = src[e];
    if (et) ets[pos] = et[e];
}

// ------------------------- per-destination attention (no atomics) -----------------
// one warp per dst node; softmax + aggregation in registers over incoming edges.
template<bool HASAK>
__global__ void dst_attn(const float* __restrict__ qkv, const float* __restrict__ ak,
                         const int* __restrict__ srcs, const int* __restrict__ ets,
                         const int* __restrict__ rowptr, float* __restrict__ agg)
{
    const int node = (blockIdx.x * blockDim.x + threadIdx.x) >> 5;
    const int lane = threadIdx.x & 31;
    const float4* qr = reinterpret_cast<const float4*>(qkv + (size_t)node * QKVS);
    float4 q0 = qr[lane * 2], q1 = qr[lane * 2 + 1];
    const int beg = rowptr[node], end = rowptr[node + 1];

    float4 acc0 = make_float4(0.f, 0.f, 0.f, 0.f);
    float4 acc1 = make_float4(0.f, 0.f, 0.f, 0.f);
    float den = 0.f;

#pragma unroll 2
    for (int j = beg; j < end; j++) {
        const int s = srcs[j];
        const float4* kr = reinterpret_cast<const float4*>(qkv + (size_t)s * QKVS + 256);
        float4 k0 = kr[lane * 2], k1 = kr[lane * 2 + 1];
        if (HASAK) {
            const float4* ar = reinterpret_cast<const float4*>(ak + (size_t)ets[j] * DKK);
            float4 a0 = ar[(lane & 3) * 2], a1 = ar[(lane & 3) * 2 + 1];
            k0.x += a0.x; k0.y += a0.y; k0.z += a0.z; k0.w += a0.w;
            k1.x += a1.x; k1.y += a1.y; k1.z += a1.z; k1.w += a1.w;
        }
        float p = k0.x * q0.x + k0.y * q0.y + k0.z * q0.z + k0.w * q0.w
                + k1.x * q1.x + k1.y * q1.y + k1.z * q1.z + k1.w * q1.w;
        p += __shfl_xor_sync(0xffffffffu, p, 1);
        p += __shfl_xor_sync(0xffffffffu, p, 2);     // per-head dot in every quad lane
        const float w = __expf(p * SCALEv);
        const float4* vr = reinterpret_cast<const float4*>(qkv + (size_t)s * QKVS + 512);
        float4 v0 = vr[lane * 2], v1 = vr[lane * 2 + 1];
        acc0.x += w * v0.x; acc0.y += w * v0.y; acc0.z += w * v0.z; acc0.w += w * v0.w;
        acc1.x += w * v1.x; acc1.y += w * v1.y; acc1.z += w * v1.z; acc1.w += w * v1.w;
        den += w;
    }
    const float r = den > 0.f ? __frcp_rn(den) : 0.f;
    float4* out = reinterpret_cast<float4*>(agg + (size_t)node * DD + lane * 8);
    out[0] = make_float4(acc0.x * r, acc0.y * r, acc0.z * r, acc0.w * r);
    out[1] = make_float4(acc1.x * r, acc1.y * r, acc1.z * r, acc1.w * r);
}

// ------------------------- host launch -------------------------
extern "C" void kernel_launch(void* const* d_in, const int* in_sizes, int n_in,
                              void* d_out, int out_size)
{
    const float *h = nullptr, *mem = nullptr, *ak = nullptr, *bf1 = nullptr;
    const float *W[8] = {nullptr};
    const float *Wf[2] = {nullptr};
    const float *v256[8] = {nullptr};
    const int *src_intra = nullptr, *dst_intra = nullptr, *etype = nullptr;
    const int *src_inter = nullptr, *dst_inter = nullptr;
    int c16 = 0, c1m = 0, c512k = 0, c64k = 0, c262k = 0, c256 = 0;

    for (int i = 0; i < n_in; i++) {
        int sz = in_sizes[i];
        void* p = d_in[i];
        if (sz == 16777216)      { if (c16 == 0) h = (const float*)p; else mem = (const float*)p; c16++; }
        else if (sz == 1048576)  { if (c1m == 0) src_intra = (const int*)p;
                                   else if (c1m == 1) dst_intra = (const int*)p;
                                   else etype = (const int*)p; c1m++; }
        else if (sz == 524288)   { if (c512k == 0) src_inter = (const int*)p; else dst_inter = (const int*)p; c512k++; }
        else if (sz == 65536)    { if (c64k < 8) W[c64k] = (const float*)p; c64k++; }
        else if (sz == 32000)    { ak = (const float*)p; }
        else if (sz == 262144)   { if (c262k < 2) Wf[c262k] = (const float*)p; c262k++; }
        else if (sz == 1024)     { bf1 = (const float*)p; }
        else if (sz == 256)      { if (c256 < 8) v256[c256] = (const float*)p; c256++; }
    }
    const float *ln0_g = v256[0], *ln0_b = v256[1];
    const float *ln1_g = v256[2], *ln1_b = v256[3];
    const float *ln2_g = v256[4], *ln2_b = v256[5];
    const float *bf2   = v256[6];

    float *qkv, *agg, *h1, *ffn, *wqkv0, *wqkv1, *wo0r, *wo1r, *wf1r, *wf2r;
    int *cnt, *wr, *rowptr, *srcs, *ets;
    cudaGetSymbolAddress((void**)&qkv,   g_qkv);
    cudaGetSymbolAddress((void**)&agg,   g_agg);
    cudaGetSymbolAddress((void**)&h1,    g_h1);
    cudaGetSymbolAddress((void**)&ffn,   g_ffn);
    cudaGetSymbolAddress((void**)&wqkv0, g_wqkv0);
    cudaGetSymbolAddress((void**)&wqkv1, g_wqkv1);
    cudaGetSymbolAddress((void**)&wo0r,  g_wo0r);
    cudaGetSymbolAddress((void**)&wo1r,  g_wo1r);
    cudaGetSymbolAddress((void**)&wf1r,  g_wf1r);
    cudaGetSymbolAddress((void**)&wf2r,  g_wf2r);
    cudaGetSymbolAddress((void**)&cnt,   g_cnt);
    cudaGetSymbolAddress((void**)&wr,    g_wr);
    cudaGetSymbolAddress((void**)&rowptr,g_rowptr);
    cudaGetSymbolAddress((void**)&srcs,  g_srcs);
    cudaGetSymbolAddress((void**)&ets,   g_ets);

    float* out = (float*)d_out;

    cudaFuncSetAttribute(gemmA,    cudaFuncAttributeMaxDynamicSharedMemorySize, SMEM_A);
    cudaFuncSetAttribute(gemm_qkv, cudaFuncAttributeMaxDynamicSharedMemorySize, SMEM_A);
    cudaFuncSetAttribute(gemmB_ln, cudaFuncAttributeMaxDynamicSharedMemorySize, SMEM_B);

    // ---------------- weight prep (tf32 rounding + QKV pack) ----------------
    pack_qkv_w<<<DD * QKVS / 256, 256>>>(W[0], W[1], W[2], wqkv0);
    pack_qkv_w<<<DD * QKVS / 256, 256>>>(W[4], W[5], W[6], wqkv1);
    round_w<<<DD * DD / 256, 256>>>(W[3], wo0r, DD * DD);
    round_w<<<DD * DD / 256, 256>>>(W[7], wo1r, DD * DD);
    round_w<<<DD * DFFv / 256, 256>>>(Wf[0], wf1r, DD * DFFv);
    round_w<<<DFFv * DD / 256, 256>>>(Wf[1], wf2r, DFFv * DD);

    dim3 gQKV(QKVS / 128, NN / 128);   // (6, 512)
    dim3 gLN(1, NN / 64);              // (1, 1024)
    dim3 gF1(DFFv / 128, NN / 128);    // (8, 512)
    const int ATT_BLKS = NN / 8;       // warp per node, 8 warps/block

    // ---------------- stage 1: intra attention ----------------
    gemm_qkv<<<gQKV, 256, SMEM_A>>>(h, h, wqkv0, qkv);
    cudaMemsetAsync(cnt, 0, NN * sizeof(int));
    hist_kernel<<<E1v / 256, 256>>>(dst_intra, cnt, E1v);
    scan64k<<<1, 1024>>>(cnt, rowptr, wr);
    scatter_csr<<<E1v / 256, 256>>>(src_intra, dst_intra, etype, wr, srcs, ets, E1v);
    dst_attn<true><<<ATT_BLKS, 256>>>(qkv, ak, srcs, ets, rowptr, agg);
    gemmB_ln<<<gLN, 256, SMEM_B>>>(agg, wo0r, h1, DD, nullptr, h, ln0_g, ln0_b);

    // ---------------- stage 2: inter (memory) attention ----------------
    gemm_qkv<<<gQKV, 256, SMEM_A>>>(h1, mem, wqkv1, qkv);
    cudaMemsetAsync(cnt, 0, NN * sizeof(int));
    hist_kernel<<<E2v / 256, 256>>>(dst_inter, cnt, E2v);
    scan64k<<<1, 1024>>>(cnt, rowptr, wr);
    scatter_csr<<<E2v / 256, 256>>>(src_inter, dst_inter, nullptr, wr, srcs, nullptr, E2v);
    dst_attn<false><<<ATT_BLKS, 256>>>(qkv, nullptr, srcs, nullptr, rowptr, agg);
    gemmB_ln<<<gLN, 256, SMEM_B>>>(agg, wo1r, h1, DD, nullptr, h1, ln1_g, ln1_b);

    // ---------------- FFN + final norm ----------------
    gemmA<<<gF1, 256, SMEM_A>>>(h1, wf1r, ffn, DD, DFFv, bf1, 1);
    gemmB_ln<<<gLN, 256, SMEM_B>>>(ffn, wf2r, out, DFFv, bf2, h1, ln2_g, ln2_b);
}

// round 8
// speedup vs baseline: 2.9832x; 1.0095x over previous
#include <cuda_runtime.h>
#include <cuda_bf16.h>
#include <math.h>

#define NN   65536
#define DD   256
#define HH   8
#define DKK  32
#define DFFv 1024
#define E1v  1048576
#define E2v  524288
#define EPSv 1e-5f
#define SCALEv 0.17677669529663687f  // 1/sqrt(32)
#define GBK 32
#define QKVS 768                     // packed qkv row stride

// ------------------------- scratch (static device globals) -------------------------
__device__ float g_qkv[(size_t)NN * QKVS];
__device__ float g_agg[NN * DD];
__device__ float g_h1[NN * DD];
__device__ float g_h1r[NN * DD];
__device__ float g_hr[NN * DD];
__device__ float g_memr[NN * DD];
__device__ float g_ffn[(size_t)NN * DFFv];
__device__ float g_wqkv0[DD * QKVS];
__device__ float g_wqkv1[DD * QKVS];
__device__ float g_wo0r[DD * DD];
__device__ float g_wo1r[DD * DD];
__device__ float g_wf1r[DD * DFFv];
__device__ float g_wf2r[DFFv * DD];
__device__ int   g_cnt[NN];
__device__ int   g_wr[NN];
__device__ int   g_rowptr[NN + 1];
__device__ int   g_srcs[E1v];
__device__ int   g_ets[E1v];

// ------------------------- helpers -------------------------
__device__ __forceinline__ unsigned f2tf32(float f) {
    unsigned r;
    asm("cvt.rna.tf32.f32 %0, %1;" : "=r"(r) : "f"(f));
    return r;
}
__device__ __forceinline__ float tf32r(float f) { return __uint_as_float(f2tf32(f)); }
__device__ __forceinline__ void cp16(void* smem, const void* g) {
    unsigned saddr = (unsigned)__cvta_generic_to_shared(smem);
    asm volatile("cp.async.cg.shared.global [%0], [%1], 16;" :: "r"(saddr), "l"(g));
}
#define CP_COMMIT() asm volatile("cp.async.commit_group;")
#define CP_WAIT1()  asm volatile("cp.async.wait_group 1;")
#define CP_WAIT0()  asm volatile("cp.async.wait_group 0;")

// ------------------------- weight / activation prep ------------------------------
// fragment-major B pack: 8x8 blocks; within a block, thread pair (b0,b1) contiguous.
// slot(k,n) = blk*64 + ((n&7)*4 + (k&3))*2 + ((k&7)>>2),  blk = (k>>3)*(Mm>>3) + (n>>3)
__global__ void pack_b_frag(const float* __restrict__ W, float* __restrict__ out,
                            int K, int Mm)
{
    int i = blockIdx.x * 256 + threadIdx.x;
    if (i >= K * Mm) return;
    int k = i / Mm, n = i % Mm;
    int blk = (k >> 3) * (Mm >> 3) + (n >> 3);
    int slot = blk * 64 + ((n & 7) * 4 + (k & 3)) * 2 + ((k & 7) >> 2);
    out[slot] = tf32r(W[i]);
}
__global__ void pack_qkv_b_frag(const float* __restrict__ Wq, const float* __restrict__ Wk,
                                const float* __restrict__ Wv, float* __restrict__ out)
{
    int i = blockIdx.x * 256 + threadIdx.x;          // DD*QKVS
    int k = i / QKVS, n = i % QKVS;
    const float* W = (n < 256) ? Wq : (n < 512 ? Wk : Wv);
    int blk = (k >> 3) * (QKVS >> 3) + (n >> 3);
    int slot = blk * 64 + ((n & 7) * 4 + (k & 3)) * 2 + ((k & 7) >> 2);
    out[slot] = tf32r(W[k * DD + (n & 255)]);
}
__global__ void round_act(const float* __restrict__ in, float* __restrict__ out)
{
    int i = blockIdx.x * 256 + threadIdx.x;
    float4 v = reinterpret_cast<const float4*>(in)[i];
    v.x = tf32r(v.x); v.y = tf32r(v.y); v.z = tf32r(v.z); v.w = tf32r(v.w);
    reinterpret_cast<float4*>(out)[i] = v;
}

// ------------------------- templated TF32 GEMM core -------------------------------
// warp tile 32x64; 8 warps. A pre-rounded tf32 (row-major), B in fragment-major pack.
template<int GBM_, int GBN_, int NST, bool LNFUSE, bool ROUND>
__device__ __forceinline__ void gemm_core(
    const float* __restrict__ A, const float* __restrict__ B, float* __restrict__ C,
    int Kk, int Mm, int bn, const float* __restrict__ bias, int relu,
    const float* __restrict__ resid, const float* __restrict__ lng,
    const float* __restrict__ lnb, float* __restrict__ C2)
{
    constexpr int AST_ = 36;
    constexpr int AW   = GBM_ * AST_;
    constexpr int BW   = 32 * GBN_;          // 4 k-blocks x (GBN_/8) n-blocks x 64
    constexpr int SW   = AW + BW;
    constexpr int MW   = GBM_ / 32;

    extern __shared__ float sm[];

    const int tid  = threadIdx.x;
    const int bm   = blockIdx.y * GBM_;
    const int wid  = tid >> 5;
    const int lane = tid & 31;
    const int wm   = (wid % MW) * 32;
    const int wn   = (wid / MW) * 64;
    const int gid  = lane >> 2;
    const int tig  = lane & 3;

    float acc[2][8][4];
#pragma unroll
    for (int mt = 0; mt < 2; mt++)
#pragma unroll
        for (int nt = 0; nt < 8; nt++)
#pragma unroll
            for (int c = 0; c < 4; c++) acc[mt][nt][c] = 0.f;

    const int nIter = Kk / GBK;
    const int mm8 = Mm >> 3;

    auto issue = [&](int it) {
        float* As = sm + (it % NST) * SW;
        float* Bs = As + AW;
        const int k0 = it * GBK;
#pragma unroll
        for (int i = 0; i < GBM_ / 32; i++) {
            int c = tid + 256 * i;
            int r = c >> 3, cc = (c & 7) * 4;
            cp16(&As[r * AST_ + cc], &A[(size_t)(bm + r) * Kk + k0 + cc]);
        }
        // B: 4 k-blocks, each a linear run of GBN_*8 floats (= 2*GBN_ float4)
#pragma unroll
        for (int i = 0; i < GBN_ / 32; i++) {
            int c = tid + 256 * i;                   // float4 chunk index
            int ksb = c / (2 * GBN_);
            int rem = c - ksb * (2 * GBN_);
            const float4* gsrc = reinterpret_cast<const float4*>(B)
                + ((size_t)((k0 >> 3) + ksb) * mm8 + (bn >> 3)) * 16 + rem;
            cp16(&reinterpret_cast<float4*>(Bs)[ksb * 2 * GBN_ + rem], gsrc);
        }
        CP_COMMIT();
    };

    issue(0);
    if (nIter > 1) issue(1);

    for (int it = 0; it < nIter; it++) {
        if (it + 1 < nIter) { CP_WAIT1(); } else { CP_WAIT0(); }
        __syncthreads();
        if (NST >= 3 && it + 2 < nIter) issue(it + 2);

        const float* As = sm + (it % NST) * SW;
        const float2* Bs2 = reinterpret_cast<const float2*>(As + AW);

#pragma unroll
        for (int ks = 0; ks < 4; ks++) {
            const int kb = ks * 8;
            unsigned af[2][4];
#pragma unroll
            for (int mt = 0; mt < 2; mt++) {
                const int mr = wm + mt * 16 + gid;
                af[mt][0] = __float_as_uint(As[mr * AST_ + kb + tig]);
                af[mt][1] = __float_as_uint(As[(mr + 8) * AST_ + kb + tig]);
                af[mt][2] = __float_as_uint(As[mr * AST_ + kb + tig + 4]);
                af[mt][3] = __float_as_uint(As[(mr + 8) * AST_ + kb + tig + 4]);
            }
            unsigned bf[8][2];
#pragma unroll
            for (int nt = 0; nt < 8; nt++) {
                float2 pr = Bs2[ks * GBN_ * 4 + (wn / 8 + nt) * 32 + lane];
                bf[nt][0] = __float_as_uint(pr.x);
                bf[nt][1] = __float_as_uint(pr.y);
            }
#pragma unroll
            for (int mt = 0; mt < 2; mt++)
#pragma unroll
                for (int nt = 0; nt < 8; nt++) {
                    asm volatile(
                        "mma.sync.aligned.m16n8k8.row.col.f32.tf32.tf32.f32 "
                        "{%0,%1,%2,%3}, {%4,%5,%6,%7}, {%8,%9}, {%0,%1,%2,%3};"
                        : "+f"(acc[mt][nt][0]), "+f"(acc[mt][nt][1]),
                          "+f"(acc[mt][nt][2]), "+f"(acc[mt][nt][3])
                        : "r"(af[mt][0]), "r"(af[mt][1]), "r"(af[mt][2]), "r"(af[mt][3]),
                          "r"(bf[nt][0]), "r"(bf[nt][1]));
                }
        }

        if (NST == 2 && it + 2 < nIter) {
            __syncthreads();
            issue(it + 2);
        }
    }

    if (!LNFUSE) {
#pragma unroll
        for (int mt = 0; mt < 2; mt++) {
            const int row0 = bm + wm + mt * 16 + gid;
#pragma unroll
            for (int nt = 0; nt < 8; nt++) {
                const int col = bn + wn + nt * 8 + 2 * tig;
                float b0 = 0.f, b1 = 0.f;
                if (bias) { b0 = bias[col]; b1 = bias[col + 1]; }
                float2 v0 = make_float2(acc[mt][nt][0] + b0, acc[mt][nt][1] + b1);
                float2 v1 = make_float2(acc[mt][nt][2] + b0, acc[mt][nt][3] + b1);
                if (relu) {
                    v0.x = fmaxf(v0.x, 0.f); v0.y = fmaxf(v0.y, 0.f);
                    v1.x = fmaxf(v1.x, 0.f); v1.y = fmaxf(v1.y, 0.f);
                }
                if (ROUND) {
                    v0.x = tf32r(v0.x); v0.y = tf32r(v0.y);
                    v1.x = tf32r(v1.x); v1.y = tf32r(v1.y);
                }
                *reinterpret_cast<float2*>(&C[(size_t)row0 * Mm + col]) = v0;
                *reinterpret_cast<float2*>(&C[(size_t)(row0 + 8) * Mm + col]) = v1;
            }
        }
        return;
    }

    // ---------- fused residual + LayerNorm epilogue (Mm==256, gridDim.x==1) ----------
#pragma unroll
    for (int mt = 0; mt < 2; mt++) {
        const int r0 = bm + wm + mt * 16 + gid;
        const int r1 = r0 + 8;
#pragma unroll
        for (int nt = 0; nt < 8; nt++) {
            const int col = wn + nt * 8 + 2 * tig;
            float b0 = 0.f, b1 = 0.f;
            if (bias) { b0 = bias[col]; b1 = bias[col + 1]; }
            float2 xa = *reinterpret_cast<const float2*>(&resid[(size_t)r0 * 256 + col]);
            float2 xb = *reinterpret_cast<const float2*>(&resid[(size_t)r1 * 256 + col]);
            acc[mt][nt][0] += b0 + xa.x; acc[mt][nt][1] += b1 + xa.y;
            acc[mt][nt][2] += b0 + xb.x; acc[mt][nt][3] += b1 + xb.y;
        }
    }

    __syncthreads();
    float* sums  = sm;
    float* sumsq = sm + GBM_;
    if (tid < GBM_) { sums[tid] = 0.f; sumsq[tid] = 0.f; }
    __syncthreads();

#pragma unroll
    for (int mt = 0; mt < 2; mt++) {
        float sA = 0.f, qA = 0.f, sB = 0.f, qB = 0.f;
#pragma unroll
        for (int nt = 0; nt < 8; nt++) {
            sA += acc[mt][nt][0] + acc[mt][nt][1];
            qA += acc[mt][nt][0] * acc[mt][nt][0] + acc[mt][nt][1] * acc[mt][nt][1];
            sB += acc[mt][nt][2] + acc[mt][nt][3];
            qB += acc[mt][nt][2] * acc[mt][nt][2] + acc[mt][nt][3] * acc[mt][nt][3];
        }
        sA += __shfl_xor_sync(0xffffffffu, sA, 1); sA += __shfl_xor_sync(0xffffffffu, sA, 2);
        qA += __shfl_xor_sync(0xffffffffu, qA, 1); qA += __shfl_xor_sync(0xffffffffu, qA, 2);
        sB += __shfl_xor_sync(0xffffffffu, sB, 1); sB += __shfl_xor_sync(0xffffffffu, sB, 2);
        qB += __shfl_xor_sync(0xffffffffu, qB, 1); qB += __shfl_xor_sync(0xffffffffu, qB, 2);
        if (tig == 0) {
            const int lr = wm + mt * 16 + gid;
            atomicAdd(&sums[lr], sA);     atomicAdd(&sumsq[lr], qA);
            atomicAdd(&sums[lr + 8], sB); atomicAdd(&sumsq[lr + 8], qB);
        }
    }
    __syncthreads();

    const float inv = 1.f / 256.f;
#pragma unroll
    for (int mt = 0; mt < 2; mt++) {
        const int lr0 = wm + mt * 16 + gid;
        const int lr1 = lr0 + 8;
        const float mu0 = sums[lr0] * inv;
        const float mu1 = sums[lr1] * inv;
        const float rs0 = rsqrtf(sumsq[lr0] * inv - mu0 * mu0 + EPSv);
        const float rs1 = rsqrtf(sumsq[lr1] * inv - mu1 * mu1 + EPSv);
        const int r0 = bm + lr0, r1 = bm + lr1;
#pragma unroll
        for (int nt = 0; nt < 8; nt++) {
            const int col = wn + nt * 8 + 2 * tig;
            float2 gv = *reinterpret_cast<const float2*>(&lng[col]);
            float2 bv = *reinterpret_cast<const float2*>(&lnb[col]);
            float2 o0 = make_float2((acc[mt][nt][0] - mu0) * rs0 * gv.x + bv.x,
                                    (acc[mt][nt][1] - mu0) * rs0 * gv.y + bv.y);
            float2 o1 = make_float2((acc[mt][nt][2] - mu1) * rs1 * gv.x + bv.x,
                                    (acc[mt][nt][3] - mu1) * rs1 * gv.y + bv.y);
            *reinterpret_cast<float2*>(&C[(size_t)r0 * 256 + col]) = o0;
            *reinterpret_cast<float2*>(&C[(size_t)r1 * 256 + col]) = o1;
            if (C2) {
                float2 p0 = make_float2(tf32r(o0.x), tf32r(o0.y));
                float2 p1 = make_float2(tf32r(o1.x), tf32r(o1.y));
                *reinterpret_cast<float2*>(&C2[(size_t)r0 * 256 + col]) = p0;
                *reinterpret_cast<float2*>(&C2[(size_t)r1 * 256 + col]) = p1;
            }
        }
    }
}

#define SMEM_A (3 * (128 * 36 + 32 * 128) * 4)   // 104,448 B
#define SMEM_B (2 * (64 * 36 + 32 * 256) * 4)    // 83,968 B

__global__ __launch_bounds__(256, 2) void gemmA(
    const float* __restrict__ A, const float* __restrict__ B, float* __restrict__ C,
    int Kk, int Mm, const float* __restrict__ bias, int relu)
{
    gemm_core<128, 128, 3, false, true>(A, B, C, Kk, Mm, blockIdx.x * 128, bias, relu,
                                        nullptr, nullptr, nullptr, nullptr);
}

__global__ __launch_bounds__(256, 2) void gemm_qkv(
    const float* __restrict__ A0, const float* __restrict__ A1,
    const float* __restrict__ B, float* __restrict__ C)
{
    const int bn = blockIdx.x * 128;
    const float* A = (bn < 256) ? A0 : A1;
    gemm_core<128, 128, 3, false, false>(A, B, C, DD, QKVS, bn, nullptr, 0,
                                         nullptr, nullptr, nullptr, nullptr);
}

__global__ __launch_bounds__(256, 2) void gemmB_ln(
    const float* __restrict__ A, const float* __restrict__ B, float* __restrict__ C,
    int Kk, const float* __restrict__ bias,
    const float* __restrict__ resid, const float* __restrict__ lng,
    const float* __restrict__ lnb, float* __restrict__ C2)
{
    gemm_core<64, 256, 2, true, false>(A, B, C, Kk, 256, 0, bias, 0, resid, lng, lnb, C2);
}

// ------------------------- CSR build ----------------------------------------------
__global__ void hist_kernel(const int* __restrict__ dst, int* __restrict__ cnt, int E)
{
    int e = blockIdx.x * blockDim.x + threadIdx.x;
    if (e < E) atomicAdd(&cnt[dst[e]], 1);
}

__global__ __launch_bounds__(1024) void scan64k(
    const int* __restrict__ cnt, int* __restrict__ rowptr, int* __restrict__ wr)
{
    __shared__ int ss[1024];
    const int tid = threadIdx.x;
    const int base = tid * 64;
    int s = 0;
#pragma unroll
    for (int i = 0; i < 64; i++) s += cnt[base + i];
    ss[tid] = s;
    __syncthreads();
#pragma unroll
    for (int off = 1; off < 1024; off <<= 1) {
        int t = (tid >= off) ? ss[tid - off] : 0;
        __syncthreads();
        ss[tid] += t;
        __syncthreads();
    }
    int run = ss[tid] - s;
    for (int i = 0; i < 64; i++) {
        rowptr[base + i] = run;
        wr[base + i] = run;
        run += cnt[base + i];
    }
    if (tid == 1023) rowptr[NN] = run;
}

__global__ void scatter_csr(const int* __restrict__ src, const int* __restrict__ dst,
                            const int* __restrict__ et, int* __restrict__ wr,
                            int* __restrict__ srcs, int* __restrict__ ets, int E)
{
    int e = blockIdx.x * blockDim.x + threadIdx.x;
    if (e >= E) return;
    int pos = atomicAdd(&wr[dst[e]], 1);
    srcs[pos] = src[e];
    if (et) ets[pos] = et[e];
}

// ------------------------- per-destination attention (no atomics) -----------------
template<bool HASAK>
__global__ void dst_attn(const float* __restrict__ qkv, const float* __restrict__ ak,
                         const int* __restrict__ srcs, const int* __restrict__ ets,
                         const int* __restrict__ rowptr, float* __restrict__ agg)
{
    const int node = (blockIdx.x * blockDim.x + threadIdx.x) >> 5;
    const int lane = threadIdx.x & 31;
    const float4* qr = reinterpret_cast<const float4*>(qkv + (size_t)node * QKVS);
    float4 q0 = qr[lane * 2], q1 = qr[lane * 2 + 1];
    const int beg = rowptr[node], end = rowptr[node + 1];

    float4 acc0 = make_float4(0.f, 0.f, 0.f, 0.f);
    float4 acc1 = make_float4(0.f, 0.f, 0.f, 0.f);
    float den = 0.f;

#pragma unroll 4
    for (int j = beg; j < end; j++) {
        const int s = srcs[j];
        const float4* kr = reinterpret_cast<const float4*>(qkv + (size_t)s * QKVS + 256);
        float4 k0 = kr[lane * 2], k1 = kr[lane * 2 + 1];
        if (HASAK) {
            const float4* ar = reinterpret_cast<const float4*>(ak + (size_t)ets[j] * DKK);
            float4 a0 = ar[(lane & 3) * 2], a1 = ar[(lane & 3) * 2 + 1];
            k0.x += a0.x; k0.y += a0.y; k0.z += a0.z; k0.w += a0.w;
            k1.x += a1.x; k1.y += a1.y; k1.z += a1.z; k1.w += a1.w;
        }
        float p = k0.x * q0.x + k0.y * q0.y + k0.z * q0.z + k0.w * q0.w
                + k1.x * q1.x + k1.y * q1.y + k1.z * q1.z + k1.w * q1.w;
        p += __shfl_xor_sync(0xffffffffu, p, 1);
        p += __shfl_xor_sync(0xffffffffu, p, 2);
        const float w = __expf(p * SCALEv);
        const float4* vr = reinterpret_cast<const float4*>(qkv + (size_t)s * QKVS + 512);
        float4 v0 = vr[lane * 2], v1 = vr[lane * 2 + 1];
        acc0.x += w * v0.x; acc0.y += w * v0.y; acc0.z += w * v0.z; acc0.w += w * v0.w;
        acc1.x += w * v1.x; acc1.y += w * v1.y; acc1.z += w * v1.z; acc1.w += w * v1.w;
        den += w;
    }
    const float r = den > 0.f ? __frcp_rn(den) : 0.f;
    float4* out = reinterpret_cast<float4*>(agg + (size_t)node * DD + lane * 8);
    // pre-rounded to tf32: consumed only by the Wo GEMM (math-identical)
    out[0] = make_float4(tf32r(acc0.x * r), tf32r(acc0.y * r), tf32r(acc0.z * r), tf32r(acc0.w * r));
    out[1] = make_float4(tf32r(acc1.x * r), tf32r(acc1.y * r), tf32r(acc1.z * r), tf32r(acc1.w * r));
}

// ------------------------- host launch -------------------------
extern "C" void kernel_launch(void* const* d_in, const int* in_sizes, int n_in,
                              void* d_out, int out_size)
{
    const float *h = nullptr, *mem = nullptr, *ak = nullptr, *bf1 = nullptr;
    const float *W[8] = {nullptr};
    const float *Wf[2] = {nullptr};
    const float *v256[8] = {nullptr};
    const int *src_intra = nullptr, *dst_intra = nullptr, *etype = nullptr;
    const int *src_inter = nullptr, *dst_inter = nullptr;
    int c16 = 0, c1m = 0, c512k = 0, c64k = 0, c262k = 0, c256 = 0;

    for (int i = 0; i < n_in; i++) {
        int sz = in_sizes[i];
        void* p = d_in[i];
        if (sz == 16777216)      { if (c16 == 0) h = (const float*)p; else mem = (const float*)p; c16++; }
        else if (sz == 1048576)  { if (c1m == 0) src_intra = (const int*)p;
                                   else if (c1m == 1) dst_intra = (const int*)p;
                                   else etype = (const int*)p; c1m++; }
        else if (sz == 524288)   { if (c512k == 0) src_inter = (const int*)p; else dst_inter = (const int*)p; c512k++; }
        else if (sz == 65536)    { if (c64k < 8) W[c64k] = (const float*)p; c64k++; }
        else if (sz == 32000)    { ak = (const float*)p; }
        else if (sz == 262144)   { if (c262k < 2) Wf[c262k] = (const float*)p; c262k++; }
        else if (sz == 1024)     { bf1 = (const float*)p; }
        else if (sz == 256)      { if (c256 < 8) v256[c256] = (const float*)p; c256++; }
    }
    const float *ln0_g = v256[0], *ln0_b = v256[1];
    const float *ln1_g = v256[2], *ln1_b = v256[3];
    const float *ln2_g = v256[4], *ln2_b = v256[5];
    const float *bf2   = v256[6];

    float *qkv, *agg, *h1, *h1r, *hr, *memr, *ffn;
    float *wqkv0, *wqkv1, *wo0r, *wo1r, *wf1r, *wf2r;
    int *cnt, *wr, *rowptr, *srcs, *ets;
    cudaGetSymbolAddress((void**)&qkv,   g_qkv);
    cudaGetSymbolAddress((void**)&agg,   g_agg);
    cudaGetSymbolAddress((void**)&h1,    g_h1);
    cudaGetSymbolAddress((void**)&h1r,   g_h1r);
    cudaGetSymbolAddress((void**)&hr,    g_hr);
    cudaGetSymbolAddress((void**)&memr,  g_memr);
    cudaGetSymbolAddress((void**)&ffn,   g_ffn);
    cudaGetSymbolAddress((void**)&wqkv0, g_wqkv0);
    cudaGetSymbolAddress((void**)&wqkv1, g_wqkv1);
    cudaGetSymbolAddress((void**)&wo0r,  g_wo0r);
    cudaGetSymbolAddress((void**)&wo1r,  g_wo1r);
    cudaGetSymbolAddress((void**)&wf1r,  g_wf1r);
    cudaGetSymbolAddress((void**)&wf2r,  g_wf2r);
    cudaGetSymbolAddress((void**)&cnt,   g_cnt);
    cudaGetSymbolAddress((void**)&wr,    g_wr);
    cudaGetSymbolAddress((void**)&rowptr,g_rowptr);
    cudaGetSymbolAddress((void**)&srcs,  g_srcs);
    cudaGetSymbolAddress((void**)&ets,   g_ets);

    float* out = (float*)d_out;

    cudaFuncSetAttribute(gemmA,    cudaFuncAttributeMaxDynamicSharedMemorySize, SMEM_A);
    cudaFuncSetAttribute(gemm_qkv, cudaFuncAttributeMaxDynamicSharedMemorySize, SMEM_A);
    cudaFuncSetAttribute(gemmB_ln, cudaFuncAttributeMaxDynamicSharedMemorySize, SMEM_B);

    // ---------------- prep: B fragment packs + rounded activations ----------------
    pack_qkv_b_frag<<<DD * QKVS / 256, 256>>>(W[0], W[1], W[2], wqkv0);
    pack_qkv_b_frag<<<DD * QKVS / 256, 256>>>(W[4], W[5], W[6], wqkv1);
    pack_b_frag<<<DD * DD / 256, 256>>>(W[3], wo0r, DD, DD);
    pack_b_frag<<<DD * DD / 256, 256>>>(W[7], wo1r, DD, DD);
    pack_b_frag<<<DD * DFFv / 256, 256>>>(Wf[0], wf1r, DD, DFFv);
    pack_b_frag<<<DFFv * DD / 256, 256>>>(Wf[1], wf2r, DFFv, DD);
    round_act<<<NN * DD / 4 / 256, 256>>>(h, hr);
    round_act<<<NN * DD / 4 / 256, 256>>>(mem, memr);

    dim3 gQKV(QKVS / 128, NN / 128);   // (6, 512)
    dim3 gLN(1, NN / 64);              // (1, 1024)
    dim3 gF1(DFFv / 128, NN / 128);    // (8, 512)
    const int ATT_BLKS = NN / 8;

    // ---------------- stage 1: intra attention ----------------
    gemm_qkv<<<gQKV, 256, SMEM_A>>>(hr, hr, wqkv0, qkv);
    cudaMemsetAsync(cnt, 0, NN * sizeof(int));
    hist_kernel<<<E1v / 256, 256>>>(dst_intra, cnt, E1v);
    scan64k<<<1, 1024>>>(cnt, rowptr, wr);
    scatter_csr<<<E1v / 256, 256>>>(src_intra, dst_intra, etype, wr, srcs, ets, E1v);
    dst_attn<true><<<ATT_BLKS, 256>>>(qkv, ak, srcs, ets, rowptr, agg);
    gemmB_ln<<<gLN, 256, SMEM_B>>>(agg, wo0r, h1, DD, nullptr, h, ln0_g, ln0_b, h1r);

    // ---------------- stage 2: inter (memory) attention ----------------
    gemm_qkv<<<gQKV, 256, SMEM_A>>>(h1r, memr, wqkv1, qkv);
    cudaMemsetAsync(cnt, 0, NN * sizeof(int));
    hist_kernel<<<E2v / 256, 256>>>(dst_inter, cnt, E2v);
    scan64k<<<1, 1024>>>(cnt, rowptr, wr);
    scatter_csr<<<E2v / 256, 256>>>(src_inter, dst_inter, nullptr, wr, srcs, nullptr, E2v);
    dst_attn<false><<<ATT_BLKS, 256>>>(qkv, nullptr, srcs, nullptr, rowptr, agg);
    gemmB_ln<<<gLN, 256, SMEM_B>>>(agg, wo1r, h1, DD, nullptr, h1, ln1_g, ln1_b, h1r);

    // ---------------- FFN + final norm ----------------
    gemmA<<<gF1, 256, SMEM_A>>>(h1r, wf1r, ffn, DD, DFFv, bf1, 1);
    gemmB_ln<<<gLN, 256, SMEM_B>>>(ffn, wf2r, out, DFFv, bf2, h1, ln2_g, ln2_b, nullptr);
}

// round 11
// speedup vs baseline: 3.3554x; 1.1248x over previous
#include <cuda_runtime.h>
#include <cuda_bf16.h>
#include <cstdint>
#include <math.h>

#define NN   65536
#define DD   256
#define HH   8
#define DKK  32
#define DFFv 1024
#define E1v  1048576
#define E2v  524288
#define EPSv 1e-5f
#define SCALEv 0.17677669529663687f  // 1/sqrt(32)
#define GBK 32
#define QKVS 768                     // packed qkv row stride

// ------------------------- scratch (static device globals) -------------------------
__device__ float g_qkv[(size_t)NN * QKVS];
__device__ float g_qkv2[(size_t)NN * QKVS];
__device__ float g_agg[NN * DD];
__device__ float g_h1[NN * DD];
__device__ float g_h1r[NN * DD];
__device__ float g_hr[NN * DD];
__device__ float g_memr[NN * DD];
__device__ float g_ffn[(size_t)NN * DFFv];
__device__ float g_wqkv0[DD * QKVS];
__device__ float g_wqkv1[DD * QKVS];
__device__ float g_wo0r[DD * DD];
__device__ float g_wo1r[DD * DD];
__device__ float g_wf1r[DD * DFFv];
__device__ float g_wf2r[DFFv * DD];
__device__ int   g_cnt[NN];
__device__ int   g_wr[NN];
__device__ int   g_rowptr[NN + 1];
__device__ int   g_srcs[E1v];
__device__ int   g_ets[E1v];
__device__ int   g_cnt2[NN];
__device__ int   g_wr2[NN];
__device__ int   g_rowptr2[NN + 1];
__device__ int   g_srcs2[E2v];

// ------------------------- helpers -------------------------
__device__ __forceinline__ unsigned f2tf32(float f) {
    unsigned r;
    asm("cvt.rna.tf32.f32 %0, %1;" : "=r"(r) : "f"(f));
    return r;
}
__device__ __forceinline__ float tf32r(float f) { return __uint_as_float(f2tf32(f)); }
__device__ __forceinline__ void cp16(void* smem, const void* g) {
    unsigned saddr = (unsigned)__cvta_generic_to_shared(smem);
    asm volatile("cp.async.cg.shared.global [%0], [%1], 16;" :: "r"(saddr), "l"(g));
}
#define CP_COMMIT() asm volatile("cp.async.commit_group;")
#define CP_WAIT1()  asm volatile("cp.async.wait_group 1;")
#define CP_WAIT0()  asm volatile("cp.async.wait_group 0;")

// ------------------------- weight / activation prep ------------------------------
// fragment-major B pack: 8x8 blocks; within a block, thread pair (b0,b1) contiguous.
// slot(k,n) = blk*64 + ((n&7)*4 + (k&3))*2 + ((k&7)>>2),  blk = (k>>3)*(Mm>>3) + (n>>3)
__global__ void pack_b_frag(const float* __restrict__ W, float* __restrict__ out,
                            int K, int Mm)
{
    int i = blockIdx.x * 256 + threadIdx.x;
    if (i >= K * Mm) return;
    int k = i / Mm, n = i % Mm;
    int blk = (k >> 3) * (Mm >> 3) + (n >> 3);
    int slot = blk * 64 + ((n & 7) * 4 + (k & 3)) * 2 + ((k & 7) >> 2);
    out[slot] = tf32r(W[i]);
}
__global__ void pack_qkv_b_frag(const float* __restrict__ Wq, const float* __restrict__ Wk,
                                const float* __restrict__ Wv, float* __restrict__ out)
{
    int i = blockIdx.x * 256 + threadIdx.x;          // DD*QKVS
    int k = i / QKVS, n = i % QKVS;
    const float* W = (n < 256) ? Wq : (n < 512 ? Wk : Wv);
    int blk = (k >> 3) * (QKVS >> 3) + (n >> 3);
    int slot = blk * 64 + ((n & 7) * 4 + (k & 3)) * 2 + ((k & 7) >> 2);
    out[slot] = tf32r(W[k * DD + (n & 255)]);
}
__global__ void round_act(const float* __restrict__ in, float* __restrict__ out)
{
    int i = blockIdx.x * 256 + threadIdx.x;
    float4 v = reinterpret_cast<const float4*>(in)[i];
    v.x = tf32r(v.x); v.y = tf32r(v.y); v.z = tf32r(v.z); v.w = tf32r(v.w);
    reinterpret_cast<float4*>(out)[i] = v;
}

// ------------------------- templated TF32 GEMM core -------------------------------
// warp tile 32x64; 8 warps. A pre-rounded tf32 (row-major), B in fragment-major pack.
template<int GBM_, int GBN_, int NST, bool LNFUSE, bool ROUND>
__device__ __forceinline__ void gemm_core(
    const float* __restrict__ A, const float* __restrict__ B, float* __restrict__ C,
    int Kk, int Mm, int bn, const float* __restrict__ bias, int relu,
    const float* __restrict__ resid, const float* __restrict__ lng,
    const float* __restrict__ lnb, float* __restrict__ C2)
{
    constexpr int AST_ = 36;
    constexpr int AW   = GBM_ * AST_;
    constexpr int BW   = 32 * GBN_;          // 4 k-blocks x (GBN_/8) n-blocks x 64
    constexpr int SW   = AW + BW;
    constexpr int MW   = GBM_ / 32;

    extern __shared__ float sm[];

    const int tid  = threadIdx.x;
    const int bm   = blockIdx.y * GBM_;
    const int wid  = tid >> 5;
    const int lane = tid & 31;
    const int wm   = (wid % MW) * 32;
    const int wn   = (wid / MW) * 64;
    const int gid  = lane >> 2;
    const int tig  = lane & 3;

    float acc[2][8][4];
#pragma unroll
    for (int mt = 0; mt < 2; mt++)
#pragma unroll
        for (int nt = 0; nt < 8; nt++)
#pragma unroll
            for (int c = 0; c < 4; c++) acc[mt][nt][c] = 0.f;

    const int nIter = Kk / GBK;
    const int mm8 = Mm >> 3;

    auto issue = [&](int it) {
        float* As = sm + (it % NST) * SW;
        float* Bs = As + AW;
        const int k0 = it * GBK;
#pragma unroll
        for (int i = 0; i < GBM_ / 32; i++) {
            int c = tid + 256 * i;
            int r = c >> 3, cc = (c & 7) * 4;
            cp16(&As[r * AST_ + cc], &A[(size_t)(bm + r) * Kk + k0 + cc]);
        }
        // B: 4 k-blocks, each a linear run of GBN_*8 floats (= 2*GBN_ float4)
#pragma unroll
        for (int i = 0; i < GBN_ / 32; i++) {
            int c = tid + 256 * i;                   // float4 chunk index
            int ksb = c / (2 * GBN_);
            int rem = c - ksb * (2 * GBN_);
            const float4* gsrc = reinterpret_cast<const float4*>(B)
                + ((size_t)((k0 >> 3) + ksb) * mm8 + (bn >> 3)) * 16 + rem;
            cp16(&reinterpret_cast<float4*>(Bs)[ksb * 2 * GBN_ + rem], gsrc);
        }
        CP_COMMIT();
    };

    issue(0);
    if (nIter > 1) issue(1);

    for (int it = 0; it < nIter; it++) {
        if (it + 1 < nIter) { CP_WAIT1(); } else { CP_WAIT0(); }
        __syncthreads();
        if (NST >= 3 && it + 2 < nIter) issue(it + 2);

        const float* As = sm + (it % NST) * SW;
        const float2* Bs2 = reinterpret_cast<const float2*>(As + AW);

#pragma unroll
        for (int ks = 0; ks < 4; ks++) {
            const int kb = ks * 8;
            unsigned af[2][4];
#pragma unroll
            for (int mt = 0; mt < 2; mt++) {
                const int mr = wm + mt * 16 + gid;
                af[mt][0] = __float_as_uint(As[mr * AST_ + kb + tig]);
                af[mt][1] = __float_as_uint(As[(mr + 8) * AST_ + kb + tig]);
                af[mt][2] = __float_as_uint(As[mr * AST_ + kb + tig + 4]);
                af[mt][3] = __float_as_uint(As[(mr + 8) * AST_ + kb + tig + 4]);
            }
            unsigned bf[8][2];
#pragma unroll
            for (int nt = 0; nt < 8; nt++) {
                float2 pr = Bs2[ks * GBN_ * 4 + (wn / 8 + nt) * 32 + lane];
                bf[nt][0] = __float_as_uint(pr.x);
                bf[nt][1] = __float_as_uint(pr.y);
            }
#pragma unroll
            for (int mt = 0; mt < 2; mt++)
#pragma unroll
                for (int nt = 0; nt < 8; nt++) {
                    asm volatile(
                        "mma.sync.aligned.m16n8k8.row.col.f32.tf32.tf32.f32 "
                        "{%0,%1,%2,%3}, {%4,%5,%6,%7}, {%8,%9}, {%0,%1,%2,%3};"
                        : "+f"(acc[mt][nt][0]), "+f"(acc[mt][nt][1]),
                          "+f"(acc[mt][nt][2]), "+f"(acc[mt][nt][3])
                        : "r"(af[mt][0]), "r"(af[mt][1]), "r"(af[mt][2]), "r"(af[mt][3]),
                          "r"(bf[nt][0]), "r"(bf[nt][1]));
                }
        }

        if (NST == 2 && it + 2 < nIter) {
            __syncthreads();
            issue(it + 2);
        }
    }

    if (!LNFUSE) {
#pragma unroll
        for (int mt = 0; mt < 2; mt++) {
            const int row0 = bm + wm + mt * 16 + gid;
#pragma unroll
            for (int nt = 0; nt < 8; nt++) {
                const int col = bn + wn + nt * 8 + 2 * tig;
                float b0 = 0.f, b1 = 0.f;
                if (bias) { b0 = bias[col]; b1 = bias[col + 1]; }
                float2 v0 = make_float2(acc[mt][nt][0] + b0, acc[mt][nt][1] + b1);
                float2 v1 = make_float2(acc[mt][nt][2] + b0, acc[mt][nt][3] + b1);
                if (relu) {
                    v0.x = fmaxf(v0.x, 0.f); v0.y = fmaxf(v0.y, 0.f);
                    v1.x = fmaxf(v1.x, 0.f); v1.y = fmaxf(v1.y, 0.f);
                }
                if (ROUND) {
                    v0.x = tf32r(v0.x); v0.y = tf32r(v0.y);
                    v1.x = tf32r(v1.x); v1.y = tf32r(v1.y);
                }
                *reinterpret_cast<float2*>(&C[(size_t)row0 * Mm + col]) = v0;
                *reinterpret_cast<float2*>(&C[(size_t)(row0 + 8) * Mm + col]) = v1;
            }
        }
        return;
    }

    // ---------- fused residual + LayerNorm epilogue (Mm==256, gridDim.x==1) ----------
#pragma unroll
    for (int mt = 0; mt < 2; mt++) {
        const int r0 = bm + wm + mt * 16 + gid;
        const int r1 = r0 + 8;
#pragma unroll
        for (int nt = 0; nt < 8; nt++) {
            const int col = wn + nt * 8 + 2 * tig;
            float b0 = 0.f, b1 = 0.f;
            if (bias) { b0 = bias[col]; b1 = bias[col + 1]; }
            float2 xa = *reinterpret_cast<const float2*>(&resid[(size_t)r0 * 256 + col]);
            float2 xb = *reinterpret_cast<const float2*>(&resid[(size_t)r1 * 256 + col]);
            acc[mt][nt][0] += b0 + xa.x; acc[mt][nt][1] += b1 + xa.y;
            acc[mt][nt][2] += b0 + xb.x; acc[mt][nt][3] += b1 + xb.y;
        }
    }

    __syncthreads();
    float* sums  = sm;
    float* sumsq = sm + GBM_;
    if (tid < GBM_) { sums[tid] = 0.f; sumsq[tid] = 0.f; }
    __syncthreads();

#pragma unroll
    for (int mt = 0; mt < 2; mt++) {
        float sA = 0.f, qA = 0.f, sB = 0.f, qB = 0.f;
#pragma unroll
        for (int nt = 0; nt < 8; nt++) {
            sA += acc[mt][nt][0] + acc[mt][nt][1];
            qA += acc[mt][nt][0] * acc[mt][nt][0] + acc[mt][nt][1] * acc[mt][nt][1];
            sB += acc[mt][nt][2] + acc[mt][nt][3];
            qB += acc[mt][nt][2] * acc[mt][nt][2] + acc[mt][nt][3] * acc[mt][nt][3];
        }
        sA += __shfl_xor_sync(0xffffffffu, sA, 1); sA += __shfl_xor_sync(0xffffffffu, sA, 2);
        qA += __shfl_xor_sync(0xffffffffu, qA, 1); qA += __shfl_xor_sync(0xffffffffu, qA, 2);
        sB += __shfl_xor_sync(0xffffffffu, sB, 1); sB += __shfl_xor_sync(0xffffffffu, sB, 2);
        qB += __shfl_xor_sync(0xffffffffu, qB, 1); qB += __shfl_xor_sync(0xffffffffu, qB, 2);
        if (tig == 0) {
            const int lr = wm + mt * 16 + gid;
            atomicAdd(&sums[lr], sA);     atomicAdd(&sumsq[lr], qA);
            atomicAdd(&sums[lr + 8], sB); atomicAdd(&sumsq[lr + 8], qB);
        }
    }
    __syncthreads();

    const float inv = 1.f / 256.f;
#pragma unroll
    for (int mt = 0; mt < 2; mt++) {
        const int lr0 = wm + mt * 16 + gid;
        const int lr1 = lr0 + 8;
        const float mu0 = sums[lr0] * inv;
        const float mu1 = sums[lr1] * inv;
        const float rs0 = rsqrtf(sumsq[lr0] * inv - mu0 * mu0 + EPSv);
        const float rs1 = rsqrtf(sumsq[lr1] * inv - mu1 * mu1 + EPSv);
        const int r0 = bm + lr0, r1 = bm + lr1;
#pragma unroll
        for (int nt = 0; nt < 8; nt++) {
            const int col = wn + nt * 8 + 2 * tig;
            float2 gv = *reinterpret_cast<const float2*>(&lng[col]);
            float2 bv = *reinterpret_cast<const float2*>(&lnb[col]);
            float2 o0 = make_float2((acc[mt][nt][0] - mu0) * rs0 * gv.x + bv.x,
                                    (acc[mt][nt][1] - mu0) * rs0 * gv.y + bv.y);
            float2 o1 = make_float2((acc[mt][nt][2] - mu1) * rs1 * gv.x + bv.x,
                                    (acc[mt][nt][3] - mu1) * rs1 * gv.y + bv.y);
            *reinterpret_cast<float2*>(&C[(size_t)r0 * 256 + col]) = o0;
            *reinterpret_cast<float2*>(&C[(size_t)r1 * 256 + col]) = o1;
            if (C2) {
                float2 p0 = make_float2(tf32r(o0.x), tf32r(o0.y));
                float2 p1 = make_float2(tf32r(o1.x), tf32r(o1.y));
                *reinterpret_cast<float2*>(&C2[(size_t)r0 * 256 + col]) = p0;
                *reinterpret_cast<float2*>(&C2[(size_t)r1 * 256 + col]) = p1;
            }
        }
    }
}

#define SMEM_A (3 * (128 * 36 + 32 * 128) * 4)   // 104,448 B
#define SMEM_B (2 * (64 * 36 + 32 * 256) * 4)    // 83,968 B

__global__ __launch_bounds__(256, 2) void gemmA(
    const float* __restrict__ A, const float* __restrict__ B, float* __restrict__ C,
    int Kk, int Mm, const float* __restrict__ bias, int relu)
{
    gemm_core<128, 128, 3, false, true>(A, B, C, Kk, Mm, blockIdx.x * 128, bias, relu,
                                        nullptr, nullptr, nullptr, nullptr);
}

// QKV fused, with bn offset so the K/V column tiles can launch separately.
__global__ __launch_bounds__(256, 2) void gemm_qkv(
    const float* __restrict__ A0, const float* __restrict__ A1,
    const float* __restrict__ B, float* __restrict__ C, int bnoff)
{
    const int bn = (blockIdx.x + bnoff) * 128;
    const float* A = (bn < 256) ? A0 : A1;
    gemm_core<128, 128, 3, false, false>(A, B, C, DD, QKVS, bn, nullptr, 0,
                                         nullptr, nullptr, nullptr, nullptr);
}

__global__ __launch_bounds__(256, 2) void gemmB_ln(
    const float* __restrict__ A, const float* __restrict__ B, float* __restrict__ C,
    int Kk, const float* __restrict__ bias,
    const float* __restrict__ resid, const float* __restrict__ lng,
    const float* __restrict__ lnb, float* __restrict__ C2)
{
    gemm_core<64, 256, 2, true, false>(A, B, C, Kk, 256, 0, bias, 0, resid, lng, lnb, C2);
}

// ------------------------- CSR build ----------------------------------------------
__global__ void hist_kernel(const int* __restrict__ dst, int* __restrict__ cnt, int E)
{
    int e = blockIdx.x * blockDim.x + threadIdx.x;
    if (e < E) atomicAdd(&cnt[dst[e]], 1);
}

__global__ __launch_bounds__(1024) void scan64k(
    const int* __restrict__ cnt, int* __restrict__ rowptr, int* __restrict__ wr)
{
    __shared__ int ss[1024];
    const int tid = threadIdx.x;
    const int base = tid * 64;
    int s = 0;
#pragma unroll
    for (int i = 0; i < 64; i++) s += cnt[base + i];
    ss[tid] = s;
    __syncthreads();
#pragma unroll
    for (int off = 1; off < 1024; off <<= 1) {
        int t = (tid >= off) ? ss[tid - off] : 0;
        __syncthreads();
        ss[tid] += t;
        __syncthreads();
    }
    int run = ss[tid] - s;
    for (int i = 0; i < 64; i++) {
        rowptr[base + i] = run;
        wr[base + i] = run;
        run += cnt[base + i];
    }
    if (tid == 1023) rowptr[NN] = run;
}

__global__ void scatter_csr(const int* __restrict__ src, const int* __restrict__ dst,
                            const int* __restrict__ et, int* __restrict__ wr,
                            int* __restrict__ srcs, int* __restrict__ ets, int E)
{
    int e = blockIdx.x * blockDim.x + threadIdx.x;
    if (e >= E) return;
    int pos = atomicAdd(&wr[dst[e]], 1);
    srcs[pos] = src[e];
    if (et) ets[pos] = et[e];
}

// ------------------------- per-destination attention (no atomics) -----------------
template<bool HASAK>
__global__ void dst_attn(const float* __restrict__ qkv, const float* __restrict__ ak,
                         const int* __restrict__ srcs, const int* __restrict__ ets,
                         const int* __restrict__ rowptr, float* __restrict__ agg)
{
    const int node = (blockIdx.x * blockDim.x + threadIdx.x) >> 5;
    const int lane = threadIdx.x & 31;
    const float4* qr = reinterpret_cast<const float4*>(qkv + (size_t)node * QKVS);
    float4 q0 = qr[lane * 2], q1 = qr[lane * 2 + 1];
    const int beg = rowptr[node], end = rowptr[node + 1];

    float4 acc0 = make_float4(0.f, 0.f, 0.f, 0.f);
    float4 acc1 = make_float4(0.f, 0.f, 0.f, 0.f);
    float den = 0.f;

#pragma unroll 4
    for (int j = beg; j < end; j++) {
        const int s = srcs[j];
        const float4* kr = reinterpret_cast<const float4*>(qkv + (size_t)s * QKVS + 256);
        float4 k0 = kr[lane * 2], k1 = kr[lane * 2 + 1];
        if (HASAK) {
            const float4* ar = reinterpret_cast<const float4*>(ak + (size_t)ets[j] * DKK);
            float4 a0 = ar[(lane & 3) * 2], a1 = ar[(lane & 3) * 2 + 1];
            k0.x += a0.x; k0.y += a0.y; k0.z += a0.z; k0.w += a0.w;
            k1.x += a1.x; k1.y += a1.y; k1.z += a1.z; k1.w += a1.w;
        }
        float p = k0.x * q0.x + k0.y * q0.y + k0.z * q0.z + k0.w * q0.w
                + k1.x * q1.x + k1.y * q1.y + k1.z * q1.z + k1.w * q1.w;
        p += __shfl_xor_sync(0xffffffffu, p, 1);
        p += __shfl_xor_sync(0xffffffffu, p, 2);
        const float w = __expf(p * SCALEv);
        const float4* vr = reinterpret_cast<const float4*>(qkv + (size_t)s * QKVS + 512);
        float4 v0 = vr[lane * 2], v1 = vr[lane * 2 + 1];
        acc0.x += w * v0.x; acc0.y += w * v0.y; acc0.z += w * v0.z; acc0.w += w * v0.w;
        acc1.x += w * v1.x; acc1.y += w * v1.y; acc1.z += w * v1.z; acc1.w += w * v1.w;
        den += w;
    }
    const float r = den > 0.f ? __frcp_rn(den) : 0.f;
    float4* out = reinterpret_cast<float4*>(agg + (size_t)node * DD + lane * 8);
    out[0] = make_float4(tf32r(acc0.x * r), tf32r(acc0.y * r), tf32r(acc0.z * r), tf32r(acc0.w * r));
    out[1] = make_float4(tf32r(acc1.x * r), tf32r(acc1.y * r), tf32r(acc1.z * r), tf32r(acc1.w * r));
}

// ------------------------- host launch -------------------------
extern "C" void kernel_launch(void* const* d_in, const int* in_sizes, int n_in,
                              void* d_out, int out_size)
{
    const float *h = nullptr, *mem = nullptr, *ak = nullptr, *bf1 = nullptr;
    const float *W[8] = {nullptr};
    const float *Wf[2] = {nullptr};
    const float *v256[8] = {nullptr};
    const int *src_intra = nullptr, *dst_intra = nullptr, *etype = nullptr;
    const int *src_inter = nullptr, *dst_inter = nullptr;
    int c16 = 0, c1m = 0, c512k = 0, c64k = 0, c262k = 0, c256 = 0;

    for (int i = 0; i < n_in; i++) {
        int sz = in_sizes[i];
        void* p = d_in[i];
        if (sz == 16777216)      { if (c16 == 0) h = (const float*)p; else mem = (const float*)p; c16++; }
        else if (sz == 1048576)  { if (c1m == 0) src_intra = (const int*)p;
                                   else if (c1m == 1) dst_intra = (const int*)p;
                                   else etype = (const int*)p; c1m++; }
        else if (sz == 524288)   { if (c512k == 0) src_inter = (const int*)p; else dst_inter = (const int*)p; c512k++; }
        else if (sz == 65536)    { if (c64k < 8) W[c64k] = (const float*)p; c64k++; }
        else if (sz == 32000)    { ak = (const float*)p; }
        else if (sz == 262144)   { if (c262k < 2) Wf[c262k] = (const float*)p; c262k++; }
        else if (sz == 1024)     { bf1 = (const float*)p; }
        else if (sz == 256)      { if (c256 < 8) v256[c256] = (const float*)p; c256++; }
    }
    const float *ln0_g = v256[0], *ln0_b = v256[1];
    const float *ln1_g = v256[2], *ln1_b = v256[3];
    const float *ln2_g = v256[4], *ln2_b = v256[5];
    const float *bf2   = v256[6];

    float *qkv, *qkv2, *agg, *h1, *h1r, *hr, *memr, *ffn;
    float *wqkv0, *wqkv1, *wo0r, *wo1r, *wf1r, *wf2r;
    int *cnt, *wr, *rowptr, *srcs, *ets;
    int *cnt2, *wr2, *rowptr2, *srcs2;
    cudaGetSymbolAddress((void**)&qkv,    g_qkv);
    cudaGetSymbolAddress((void**)&qkv2,   g_qkv2);
    cudaGetSymbolAddress((void**)&agg,    g_agg);
    cudaGetSymbolAddress((void**)&h1,     g_h1);
    cudaGetSymbolAddress((void**)&h1r,    g_h1r);
    cudaGetSymbolAddress((void**)&hr,     g_hr);
    cudaGetSymbolAddress((void**)&memr,   g_memr);
    cudaGetSymbolAddress((void**)&ffn,    g_ffn);
    cudaGetSymbolAddress((void**)&wqkv0,  g_wqkv0);
    cudaGetSymbolAddress((void**)&wqkv1,  g_wqkv1);
    cudaGetSymbolAddress((void**)&wo0r,   g_wo0r);
    cudaGetSymbolAddress((void**)&wo1r,   g_wo1r);
    cudaGetSymbolAddress((void**)&wf1r,   g_wf1r);
    cudaGetSymbolAddress((void**)&wf2r,   g_wf2r);
    cudaGetSymbolAddress((void**)&cnt,    g_cnt);
    cudaGetSymbolAddress((void**)&wr,     g_wr);
    cudaGetSymbolAddress((void**)&rowptr, g_rowptr);
    cudaGetSymbolAddress((void**)&srcs,   g_srcs);
    cudaGetSymbolAddress((void**)&ets,    g_ets);
    cudaGetSymbolAddress((void**)&cnt2,   g_cnt2);
    cudaGetSymbolAddress((void**)&wr2,    g_wr2);
    cudaGetSymbolAddress((void**)&rowptr2,g_rowptr2);
    cudaGetSymbolAddress((void**)&srcs2,  g_srcs2);

    float* out = (float*)d_out;

    cudaFuncSetAttribute(gemmA,    cudaFuncAttributeMaxDynamicSharedMemorySize, SMEM_A);
    cudaFuncSetAttribute(gemm_qkv, cudaFuncAttributeMaxDynamicSharedMemorySize, SMEM_A);
    cudaFuncSetAttribute(gemmB_ln, cudaFuncAttributeMaxDynamicSharedMemorySize, SMEM_B);

    // ---------------- stream fork: side stream does CSR builds + stage-2 KV GEMM ----
    cudaStream_t s2;
    cudaStreamCreateWithFlags(&s2, cudaStreamNonBlocking);
    cudaEvent_t evRoot, evPrep, evCSR1, evS2;
    cudaEventCreateWithFlags(&evRoot, cudaEventDisableTiming);
    cudaEventCreateWithFlags(&evPrep, cudaEventDisableTiming);
    cudaEventCreateWithFlags(&evCSR1, cudaEventDisableTiming);
    cudaEventCreateWithFlags(&evS2,   cudaEventDisableTiming);

    cudaEventRecord(evRoot, 0);
    cudaStreamWaitEvent(s2, evRoot, 0);

    // side stream: both CSR builds (depend only on inputs)
    cudaMemsetAsync(cnt,  0, NN * sizeof(int), s2);
    cudaMemsetAsync(cnt2, 0, NN * sizeof(int), s2);
    hist_kernel<<<E1v / 256, 256, 0, s2>>>(dst_intra, cnt, E1v);
    scan64k<<<1, 1024, 0, s2>>>(cnt, rowptr, wr);
    scatter_csr<<<E1v / 256, 256, 0, s2>>>(src_intra, dst_intra, etype, wr, srcs, ets, E1v);
    cudaEventRecord(evCSR1, s2);
    hist_kernel<<<E2v / 256, 256, 0, s2>>>(dst_inter, cnt2, E2v);
    scan64k<<<1, 1024, 0, s2>>>(cnt2, rowptr2, wr2);
    scatter_csr<<<E2v / 256, 256, 0, s2>>>(src_inter, dst_inter, nullptr, wr2, srcs2, nullptr, E2v);

    // main stream: prep (weight packs + rounded activations)
    pack_qkv_b_frag<<<DD * QKVS / 256, 256>>>(W[0], W[1], W[2], wqkv0);
    pack_qkv_b_frag<<<DD * QKVS / 256, 256>>>(W[4], W[5], W[6], wqkv1);
    pack_b_frag<<<DD * DD / 256, 256>>>(W[3], wo0r, DD, DD);
    pack_b_frag<<<DD * DD / 256, 256>>>(W[7], wo1r, DD, DD);
    pack_b_frag<<<DD * DFFv / 256, 256>>>(Wf[0], wf1r, DD, DFFv);
    pack_b_frag<<<DFFv * DD / 256, 256>>>(Wf[1], wf2r, DFFv, DD);
    round_act<<<NN * DD / 4 / 256, 256>>>(h, hr);
    round_act<<<NN * DD / 4 / 256, 256>>>(mem, memr);
    cudaEventRecord(evPrep, 0);
    cudaStreamWaitEvent(s2, evPrep, 0);

    // side stream: stage-2 K/V projection (A = mem; independent of stage 1)
    gemm_qkv<<<dim3(4, NN / 128), 256, SMEM_A, s2>>>(memr, memr, wqkv1, qkv2, 2);
    cudaEventRecord(evS2, s2);

    dim3 gLN(1, NN / 64);              // (1, 1024)
    dim3 gF1(DFFv / 128, NN / 128);    // (8, 512)
    const int ATT_BLKS = NN / 8;

    // ---------------- stage 1: intra attention (main stream) ----------------
    gemm_qkv<<<dim3(6, NN / 128), 256, SMEM_A>>>(hr, hr, wqkv0, qkv, 0);
    cudaStreamWaitEvent(0, evCSR1, 0);
    dst_attn<true><<<ATT_BLKS, 256>>>(qkv, ak, srcs, ets, rowptr, agg);
    gemmB_ln<<<gLN, 256, SMEM_B>>>(agg, wo0r, h1, DD, nullptr, h, ln0_g, ln0_b, h1r);

    // ---------------- stage 2: inter attention ----------------
    // Q projection (needs h1r); K/V already computed on s2 into qkv2 cols [256,768)
    gemm_qkv<<<dim3(2, NN / 128), 256, SMEM_A>>>(h1r, h1r, wqkv1, qkv2, 0);
    cudaStreamWaitEvent(0, evS2, 0);
    dst_attn<false><<<ATT_BLKS, 256>>>(qkv2, nullptr, srcs2, nullptr, rowptr2, agg);
    gemmB_ln<<<gLN, 256, SMEM_B>>>(agg, wo1r, h1, DD, nullptr, h1, ln1_g, ln1_b, h1r);

    // ---------------- FFN + final norm ----------------
    gemmA<<<gF1, 256, SMEM_A>>>(h1r, wf1r, ffn, DD, DFFv, bf1, 1);
    gemmB_ln<<<gLN, 256, SMEM_B>>>(ffn, wf2r, out, DFFv, bf2, h1, ln2_g, ln2_b, nullptr);
}

// round 12
// speedup vs baseline: 3.3694x; 1.0042x over previous
#include <cuda_runtime.h>
#include <cuda_bf16.h>
#include <cstdint>
#include <math.h>

#define NN   65536
#define DD   256
#define HH   8
#define DKK  32
#define DFFv 1024
#define E1v  1048576
#define E2v  524288
#define EPSv 1e-5f
#define SCALEv 0.17677669529663687f  // 1/sqrt(32)
#define GBK 32
#define QKVS 768                     // packed qkv row stride

// ------------------------- scratch (static device globals) -------------------------
__device__ float g_qkv[(size_t)NN * QKVS];
__device__ float g_qkv2[(size_t)NN * QKVS];
__device__ float g_agg[NN * DD];
__device__ float g_h1[NN * DD];
__device__ float g_h1r[NN * DD];
__device__ float g_hr[NN * DD];
__device__ float g_memr[NN * DD];
__device__ float g_ffn[(size_t)NN * DFFv];
__device__ float g_wqkv0[DD * QKVS];
__device__ float g_wqkv1[DD * QKVS];
__device__ float g_wo0r[DD * DD];
__device__ float g_wo1r[DD * DD];
__device__ float g_wf1r[DD * DFFv];
__device__ float g_wf2r[DFFv * DD];
__device__ int   g_cnt[NN];
__device__ int   g_wr[NN];
__device__ int   g_rowptr[NN + 1];
__device__ int   g_srcs[E1v];
__device__ int   g_ets[E1v];
__device__ int   g_cnt2[NN];
__device__ int   g_wr2[NN];
__device__ int   g_rowptr2[NN + 1];
__device__ int   g_srcs2[E2v];

// ------------------------- helpers -------------------------
__device__ __forceinline__ unsigned f2tf32(float f) {
    unsigned r;
    asm("cvt.rna.tf32.f32 %0, %1;" : "=r"(r) : "f"(f));
    return r;
}
__device__ __forceinline__ float tf32r(float f) { return __uint_as_float(f2tf32(f)); }
__device__ __forceinline__ void cp16(void* smem, const void* g) {
    unsigned saddr = (unsigned)__cvta_generic_to_shared(smem);
    asm volatile("cp.async.cg.shared.global [%0], [%1], 16;" :: "r"(saddr), "l"(g));
}
#define CP_COMMIT() asm volatile("cp.async.commit_group;")
#define CP_WAIT1()  asm volatile("cp.async.wait_group 1;")
#define CP_WAIT0()  asm volatile("cp.async.wait_group 0;")

#define MMA_TF32(acc, a0, a1, a2, a3, b0, b1) \
    asm volatile( \
        "mma.sync.aligned.m16n8k8.row.col.f32.tf32.tf32.f32 " \
        "{%0,%1,%2,%3}, {%4,%5,%6,%7}, {%8,%9}, {%0,%1,%2,%3};" \
        : "+f"((acc)[0]), "+f"((acc)[1]), "+f"((acc)[2]), "+f"((acc)[3]) \
        : "r"(a0), "r"(a1), "r"(a2), "r"(a3), "r"(b0), "r"(b1))

// ------------------------- weight / activation prep ------------------------------
// fragment-major B pack: 8x8 blocks; within a block, thread pair (b0,b1) contiguous.
__global__ void pack_b_frag(const float* __restrict__ W, float* __restrict__ out,
                            int K, int Mm)
{
    int i = blockIdx.x * 256 + threadIdx.x;
    if (i >= K * Mm) return;
    int k = i / Mm, n = i % Mm;
    int blk = (k >> 3) * (Mm >> 3) + (n >> 3);
    int slot = blk * 64 + ((n & 7) * 4 + (k & 3)) * 2 + ((k & 7) >> 2);
    out[slot] = tf32r(W[i]);
}
__global__ void pack_qkv_b_frag(const float* __restrict__ Wq, const float* __restrict__ Wk,
                                const float* __restrict__ Wv, float* __restrict__ out)
{
    int i = blockIdx.x * 256 + threadIdx.x;          // DD*QKVS
    int k = i / QKVS, n = i % QKVS;
    const float* W = (n < 256) ? Wq : (n < 512 ? Wk : Wv);
    int blk = (k >> 3) * (QKVS >> 3) + (n >> 3);
    int slot = blk * 64 + ((n & 7) * 4 + (k & 3)) * 2 + ((k & 7) >> 2);
    out[slot] = tf32r(W[k * DD + (n & 255)]);
}
__global__ void round_act(const float* __restrict__ in, float* __restrict__ out)
{
    int i = blockIdx.x * 256 + threadIdx.x;
    float4 v = reinterpret_cast<const float4*>(in)[i];
    v.x = tf32r(v.x); v.y = tf32r(v.y); v.z = tf32r(v.z); v.w = tf32r(v.w);
    reinterpret_cast<float4*>(out)[i] = v;
}

// ------------------------- 4-warp TF32 GEMM core (64x64 warp tiles) ---------------
// block 128x128, 128 threads, 3-stage cp.async. Halved smem fragment traffic.
#define AST4 36
#define AW4  (128 * AST4)
#define BW4  (32 * 128)
#define SW4  (AW4 + BW4)
#define SMEM_A (3 * SW4 * 4)   // 104,448 B

template<bool ROUND>
__device__ __forceinline__ void gemm_core4(
    const float* __restrict__ A, const float* __restrict__ B, float* __restrict__ C,
    int Kk, int Mm, int bn, const float* __restrict__ bias, int relu)
{
    extern __shared__ float sm[];

    const int tid  = threadIdx.x;
    const int bm   = blockIdx.y * 128;
    const int wid  = tid >> 5;
    const int lane = tid & 31;
    const int wm   = (wid & 1) * 64;
    const int wn   = (wid >> 1) * 64;
    const int gid  = lane >> 2;
    const int tig  = lane & 3;

    float acc[4][8][4];
#pragma unroll
    for (int mt = 0; mt < 4; mt++)
#pragma unroll
        for (int nt = 0; nt < 8; nt++)
#pragma unroll
            for (int c = 0; c < 4; c++) acc[mt][nt][c] = 0.f;

    const int nIter = Kk / GBK;
    const int mm8 = Mm >> 3;

    auto issue = [&](int it) {
        float* As = sm + (it % 3) * SW4;
        float* Bs = As + AW4;
        const int k0 = it * GBK;
#pragma unroll
        for (int i = 0; i < 8; i++) {                // A: 1024 float4 chunks
            int c = tid + 128 * i;
            int r = c >> 3, cc = (c & 7) * 4;
            cp16(&As[r * AST4 + cc], &A[(size_t)(bm + r) * Kk + k0 + cc]);
        }
#pragma unroll
        for (int i = 0; i < 8; i++) {                // B: 1024 float4 chunks (frag-major)
            int c = tid + 128 * i;
            int ksb = c >> 8;                        // c / 256
            int rem = c & 255;
            const float4* gsrc = reinterpret_cast<const float4*>(B)
                + ((size_t)((k0 >> 3) + ksb) * mm8 + (bn >> 3)) * 16 + rem;
            cp16(&reinterpret_cast<float4*>(Bs)[ksb * 256 + rem], gsrc);
        }
        CP_COMMIT();
    };

    issue(0);
    if (nIter > 1) issue(1);

    for (int it = 0; it < nIter; it++) {
        if (it + 1 < nIter) { CP_WAIT1(); } else { CP_WAIT0(); }
        __syncthreads();
        if (it + 2 < nIter) issue(it + 2);

        const float* As = sm + (it % 3) * SW4;
        const float2* Bs2 = reinterpret_cast<const float2*>(As + AW4);

#pragma unroll
        for (int ks = 0; ks < 4; ks++) {
            const int kb = ks * 8;
            unsigned af[4][4];
#pragma unroll
            for (int mt = 0; mt < 4; mt++) {
                const int mr = wm + mt * 16 + gid;
                af[mt][0] = __float_as_uint(As[mr * AST4 + kb + tig]);
                af[mt][1] = __float_as_uint(As[(mr + 8) * AST4 + kb + tig]);
                af[mt][2] = __float_as_uint(As[mr * AST4 + kb + tig + 4]);
                af[mt][3] = __float_as_uint(As[(mr + 8) * AST4 + kb + tig + 4]);
            }
            unsigned bf[8][2];
#pragma unroll
            for (int nt = 0; nt < 8; nt++) {
                float2 pr = Bs2[ks * 512 + (wn / 8 + nt) * 32 + lane];
                bf[nt][0] = __float_as_uint(pr.x);
                bf[nt][1] = __float_as_uint(pr.y);
            }
#pragma unroll
            for (int mt = 0; mt < 4; mt++)
#pragma unroll
                for (int nt = 0; nt < 8; nt++)
                    MMA_TF32(acc[mt][nt], af[mt][0], af[mt][1], af[mt][2], af[mt][3],
                             bf[nt][0], bf[nt][1]);
        }
    }

#pragma unroll
    for (int mt = 0; mt < 4; mt++) {
        const int row0 = bm + wm + mt * 16 + gid;
#pragma unroll
        for (int nt = 0; nt < 8; nt++) {
            const int col = bn + wn + nt * 8 + 2 * tig;
            float b0 = 0.f, b1 = 0.f;
            if (bias) { b0 = bias[col]; b1 = bias[col + 1]; }
            float2 v0 = make_float2(acc[mt][nt][0] + b0, acc[mt][nt][1] + b1);
            float2 v1 = make_float2(acc[mt][nt][2] + b0, acc[mt][nt][3] + b1);
            if (relu) {
                v0.x = fmaxf(v0.x, 0.f); v0.y = fmaxf(v0.y, 0.f);
                v1.x = fmaxf(v1.x, 0.f); v1.y = fmaxf(v1.y, 0.f);
            }
            if (ROUND) {
                v0.x = tf32r(v0.x); v0.y = tf32r(v0.y);
                v1.x = tf32r(v1.x); v1.y = tf32r(v1.y);
            }
            *reinterpret_cast<float2*>(&C[(size_t)row0 * Mm + col]) = v0;
            *reinterpret_cast<float2*>(&C[(size_t)(row0 + 8) * Mm + col]) = v1;
        }
    }
}

__global__ __launch_bounds__(128, 2) void gemmA4(
    const float* __restrict__ A, const float* __restrict__ B, float* __restrict__ C,
    int Kk, int Mm, const float* __restrict__ bias, int relu)
{
    gemm_core4<true>(A, B, C, Kk, Mm, blockIdx.x * 128, bias, relu);
}

__global__ __launch_bounds__(128, 2) void gemm_qkv4(
    const float* __restrict__ A0, const float* __restrict__ A1,
    const float* __restrict__ B, float* __restrict__ C, int bnoff)
{
    const int bn = (blockIdx.x + bnoff) * 128;
    const float* A = (bn < 256) ? A0 : A1;
    gemm_core4<false>(A, B, C, DD, QKVS, bn, nullptr, 0);
}

// ------------------------- 8-warp LN-fused GEMM (64x256 block) --------------------
#define ASTB 36
#define AWB  (64 * ASTB)
#define BWB  (32 * 256)
#define SWB  (AWB + BWB)
#define SMEM_B (2 * SWB * 4)    // 83,968 B

__global__ __launch_bounds__(256, 2) void gemmB_ln(
    const float* __restrict__ A, const float* __restrict__ B, float* __restrict__ C,
    int Kk, const float* __restrict__ bias,
    const float* __restrict__ resid, const float* __restrict__ lng,
    const float* __restrict__ lnb, float* __restrict__ C2)
{
    extern __shared__ float sm[];

    const int tid  = threadIdx.x;
    const int bm   = blockIdx.y * 64;
    const int wid  = tid >> 5;
    const int lane = tid & 31;
    const int wm   = (wid & 1) * 32;
    const int wn   = (wid >> 1) * 64;
    const int gid  = lane >> 2;
    const int tig  = lane & 3;
    const int Mm   = 256;

    float acc[2][8][4];
#pragma unroll
    for (int mt = 0; mt < 2; mt++)
#pragma unroll
        for (int nt = 0; nt < 8; nt++)
#pragma unroll
            for (int c = 0; c < 4; c++) acc[mt][nt][c] = 0.f;

    const int nIter = Kk / GBK;
    const int mm8 = Mm >> 3;

    auto issue = [&](int it) {
        float* As = sm + (it & 1) * SWB;
        float* Bs = As + AWB;
        const int k0 = it * GBK;
#pragma unroll
        for (int i = 0; i < 2; i++) {
            int c = tid + 256 * i;
            int r = c >> 3, cc = (c & 7) * 4;
            cp16(&As[r * ASTB + cc], &A[(size_t)(bm + r) * Kk + k0 + cc]);
        }
#pragma unroll
        for (int i = 0; i < 8; i++) {
            int c = tid + 256 * i;
            int ksb = c >> 9;                        // c / 512
            int rem = c & 511;
            const float4* gsrc = reinterpret_cast<const float4*>(B)
                + ((size_t)((k0 >> 3) + ksb) * mm8) * 16 + rem;
            cp16(&reinterpret_cast<float4*>(Bs)[ksb * 512 + rem], gsrc);
        }
        CP_COMMIT();
    };

    issue(0);
    if (nIter > 1) issue(1);

    for (int it = 0; it < nIter; it++) {
        if (it + 1 < nIter) { CP_WAIT1(); } else { CP_WAIT0(); }
        __syncthreads();

        const float* As = sm + (it & 1) * SWB;
        const float2* Bs2 = reinterpret_cast<const float2*>(As + AWB);

#pragma unroll
        for (int ks = 0; ks < 4; ks++) {
            const int kb = ks * 8;
            unsigned af[2][4];
#pragma unroll
            for (int mt = 0; mt < 2; mt++) {
                const int mr = wm + mt * 16 + gid;
                af[mt][0] = __float_as_uint(As[mr * ASTB + kb + tig]);
                af[mt][1] = __float_as_uint(As[(mr + 8) * ASTB + kb + tig]);
                af[mt][2] = __float_as_uint(As[mr * ASTB + kb + tig + 4]);
                af[mt][3] = __float_as_uint(As[(mr + 8) * ASTB + kb + tig + 4]);
            }
            unsigned bf[8][2];
#pragma unroll
            for (int nt = 0; nt < 8; nt++) {
                float2 pr = Bs2[ks * 1024 + (wn / 8 + nt) * 32 + lane];
                bf[nt][0] = __float_as_uint(pr.x);
                bf[nt][1] = __float_as_uint(pr.y);
            }
#pragma unroll
            for (int mt = 0; mt < 2; mt++)
#pragma unroll
                for (int nt = 0; nt < 8; nt++)
                    MMA_TF32(acc[mt][nt], af[mt][0], af[mt][1], af[mt][2], af[mt][3],
                             bf[nt][0], bf[nt][1]);
        }

        if (it + 2 < nIter) {
            __syncthreads();
            issue(it + 2);
        }
    }

    // ---------- fused residual + LayerNorm epilogue ----------
#pragma unroll
    for (int mt = 0; mt < 2; mt++) {
        const int r0 = bm + wm + mt * 16 + gid;
        const int r1 = r0 + 8;
#pragma unroll
        for (int nt = 0; nt < 8; nt++) {
            const int col = wn + nt * 8 + 2 * tig;
            float b0 = 0.f, b1 = 0.f;
            if (bias) { b0 = bias[col]; b1 = bias[col + 1]; }
            float2 xa = *reinterpret_cast<const float2*>(&resid[(size_t)r0 * 256 + col]);
            float2 xb = *reinterpret_cast<const float2*>(&resid[(size_t)r1 * 256 + col]);
            acc[mt][nt][0] += b0 + xa.x; acc[mt][nt][1] += b1 + xa.y;
            acc[mt][nt][2] += b0 + xb.x; acc[mt][nt][3] += b1 + xb.y;
        }
    }

    __syncthreads();
    float* sums  = sm;
    float* sumsq = sm + 64;
    if (tid < 64) { sums[tid] = 0.f; sumsq[tid] = 0.f; }
    __syncthreads();

#pragma unroll
    for (int mt = 0; mt < 2; mt++) {
        float sA = 0.f, qA = 0.f, sB = 0.f, qB = 0.f;
#pragma unroll
        for (int nt = 0; nt < 8; nt++) {
            sA += acc[mt][nt][0] + acc[mt][nt][1];
            qA += acc[mt][nt][0] * acc[mt][nt][0] + acc[mt][nt][1] * acc[mt][nt][1];
            sB += acc[mt][nt][2] + acc[mt][nt][3];
            qB += acc[mt][nt][2] * acc[mt][nt][2] + acc[mt][nt][3] * acc[mt][nt][3];
        }
        sA += __shfl_xor_sync(0xffffffffu, sA, 1); sA += __shfl_xor_sync(0xffffffffu, sA, 2);
        qA += __shfl_xor_sync(0xffffffffu, qA, 1); qA += __shfl_xor_sync(0xffffffffu, qA, 2);
        sB += __shfl_xor_sync(0xffffffffu, sB, 1); sB += __shfl_xor_sync(0xffffffffu, sB, 2);
        qB += __shfl_xor_sync(0xffffffffu, qB, 1); qB += __shfl_xor_sync(0xffffffffu, qB, 2);
        if (tig == 0) {
            const int lr = wm + mt * 16 + gid;
            atomicAdd(&sums[lr], sA);     atomicAdd(&sumsq[lr], qA);
            atomicAdd(&sums[lr + 8], sB); atomicAdd(&sumsq[lr + 8], qB);
        }
    }
    __syncthreads();

    const float inv = 1.f / 256.f;
#pragma unroll
    for (int mt = 0; mt < 2; mt++) {
        const int lr0 = wm + mt * 16 + gid;
        const int lr1 = lr0 + 8;
        const float mu0 = sums[lr0] * inv;
        const float mu1 = sums[lr1] * inv;
        const float rs0 = rsqrtf(sumsq[lr0] * inv - mu0 * mu0 + EPSv);
        const float rs1 = rsqrtf(sumsq[lr1] * inv - mu1 * mu1 + EPSv);
        const int r0 = bm + lr0, r1 = bm + lr1;
#pragma unroll
        for (int nt = 0; nt < 8; nt++) {
            const int col = wn + nt * 8 + 2 * tig;
            float2 gv = *reinterpret_cast<const float2*>(&lng[col]);
            float2 bv = *reinterpret_cast<const float2*>(&lnb[col]);
            float2 o0 = make_float2((acc[mt][nt][0] - mu0) * rs0 * gv.x + bv.x,
                                    (acc[mt][nt][1] - mu0) * rs0 * gv.y + bv.y);
            float2 o1 = make_float2((acc[mt][nt][2] - mu1) * rs1 * gv.x + bv.x,
                                    (acc[mt][nt][3] - mu1) * rs1 * gv.y + bv.y);
            *reinterpret_cast<float2*>(&C[(size_t)r0 * 256 + col]) = o0;
            *reinterpret_cast<float2*>(&C[(size_t)r1 * 256 + col]) = o1;
            if (C2) {
                float2 p0 = make_float2(tf32r(o0.x), tf32r(o0.y));
                float2 p1 = make_float2(tf32r(o1.x), tf32r(o1.y));
                *reinterpret_cast<float2*>(&C2[(size_t)r0 * 256 + col]) = p0;
                *reinterpret_cast<float2*>(&C2[(size_t)r1 * 256 + col]) = p1;
            }
        }
    }
}

// ------------------------- CSR build ----------------------------------------------
__global__ void hist_kernel(const int* __restrict__ dst, int* __restrict__ cnt, int E)
{
    int e = blockIdx.x * blockDim.x + threadIdx.x;
    if (e < E) atomicAdd(&cnt[dst[e]], 1);
}

__global__ __launch_bounds__(1024) void scan64k(
    const int* __restrict__ cnt, int* __restrict__ rowptr, int* __restrict__ wr)
{
    __shared__ int ss[1024];
    const int tid = threadIdx.x;
    const int base = tid * 64;
    int s = 0;
#pragma unroll
    for (int i = 0; i < 64; i++) s += cnt[base + i];
    ss[tid] = s;
    __syncthreads();
#pragma unroll
    for (int off = 1; off < 1024; off <<= 1) {
        int t = (tid >= off) ? ss[tid - off] : 0;
        __syncthreads();
        ss[tid] += t;
        __syncthreads();
    }
    int run = ss[tid] - s;
    for (int i = 0; i < 64; i++) {
        rowptr[base + i] = run;
        wr[base + i] = run;
        run += cnt[base + i];
    }
    if (tid == 1023) rowptr[NN] = run;
}

__global__ void scatter_csr(const int* __restrict__ src, const int* __restrict__ dst,
                            const int* __restrict__ et, int* __restrict__ wr,
                            int* __restrict__ srcs, int* __restrict__ ets, int E)
{
    int e = blockIdx.x * blockDim.x + threadIdx.x;
    if (e >= E) return;
    int pos = atomicAdd(&wr[dst[e]], 1);
    srcs[pos] = src[e];
    if (et) ets[pos] = et[e];
}

// ------------------------- per-destination attention (no atomics) -----------------
template<bool HASAK>
__global__ void dst_attn(const float* __restrict__ qkv, const float* __restrict__ ak,
                         const int* __restrict__ srcs, const int* __restrict__ ets,
                         const int* __restrict__ rowptr, float* __restrict__ agg)
{
    const int node = (blockIdx.x * blockDim.x + threadIdx.x) >> 5;
    const int lane = threadIdx.x & 31;
    const float4* qr = reinterpret_cast<const float4*>(qkv + (size_t)node * QKVS);
    float4 q0 = qr[lane * 2], q1 = qr[lane * 2 + 1];
    const int beg = rowptr[node], end = rowptr[node + 1];

    float4 acc0 = make_float4(0.f, 0.f, 0.f, 0.f);
    float4 acc1 = make_float4(0.f, 0.f, 0.f, 0.f);
    float den = 0.f;

#pragma unroll 4
    for (int j = beg; j < end; j++) {
        const int s = srcs[j];
        const float4* kr = reinterpret_cast<const float4*>(qkv + (size_t)s * QKVS + 256);
        float4 k0 = kr[lane * 2], k1 = kr[lane * 2 + 1];
        if (HASAK) {
            const float4* ar = reinterpret_cast<const float4*>(ak + (size_t)ets[j] * DKK);
            float4 a0 = ar[(lane & 3) * 2], a1 = ar[(lane & 3) * 2 + 1];
            k0.x += a0.x; k0.y += a0.y; k0.z += a0.z; k0.w += a0.w;
            k1.x += a1.x; k1.y += a1.y; k1.z += a1.z; k1.w += a1.w;
        }
        float p = k0.x * q0.x + k0.y * q0.y + k0.z * q0.z + k0.w * q0.w
                + k1.x * q1.x + k1.y * q1.y + k1.z * q1.z + k1.w * q1.w;
        p += __shfl_xor_sync(0xffffffffu, p, 1);
        p += __shfl_xor_sync(0xffffffffu, p, 2);
        const float w = __expf(p * SCALEv);
        const float4* vr = reinterpret_cast<const float4*>(qkv + (size_t)s * QKVS + 512);
        float4 v0 = vr[lane * 2], v1 = vr[lane * 2 + 1];
        acc0.x += w * v0.x; acc0.y += w * v0.y; acc0.z += w * v0.z; acc0.w += w * v0.w;
        acc1.x += w * v1.x; acc1.y += w * v1.y; acc1.z += w * v1.z; acc1.w += w * v1.w;
        den += w;
    }
    const float r = den > 0.f ? __frcp_rn(den) : 0.f;
    float4* out = reinterpret_cast<float4*>(agg + (size_t)node * DD + lane * 8);
    out[0] = make_float4(tf32r(acc0.x * r), tf32r(acc0.y * r), tf32r(acc0.z * r), tf32r(acc0.w * r));
    out[1] = make_float4(tf32r(acc1.x * r), tf32r(acc1.y * r), tf32r(acc1.z * r), tf32r(acc1.w * r));
}

// ------------------------- host launch -------------------------
extern "C" void kernel_launch(void* const* d_in, const int* in_sizes, int n_in,
                              void* d_out, int out_size)
{
    const float *h = nullptr, *mem = nullptr, *ak = nullptr, *bf1 = nullptr;
    const float *W[8] = {nullptr};
    const float *Wf[2] = {nullptr};
    const float *v256[8] = {nullptr};
    const int *src_intra = nullptr, *dst_intra = nullptr, *etype = nullptr;
    const int *src_inter = nullptr, *dst_inter = nullptr;
    int c16 = 0, c1m = 0, c512k = 0, c64k = 0, c262k = 0, c256 = 0;

    for (int i = 0; i < n_in; i++) {
        int sz = in_sizes[i];
        void* p = d_in[i];
        if (sz == 16777216)      { if (c16 == 0) h = (const float*)p; else mem = (const float*)p; c16++; }
        else if (sz == 1048576)  { if (c1m == 0) src_intra = (const int*)p;
                                   else if (c1m == 1) dst_intra = (const int*)p;
                                   else etype = (const int*)p; c1m++; }
        else if (sz == 524288)   { if (c512k == 0) src_inter = (const int*)p; else dst_inter = (const int*)p; c512k++; }
        else if (sz == 65536)    { if (c64k < 8) W[c64k] = (const float*)p; c64k++; }
        else if (sz == 32000)    { ak = (const float*)p; }
        else if (sz == 262144)   { if (c262k < 2) Wf[c262k] = (const float*)p; c262k++; }
        else if (sz == 1024)     { bf1 = (const float*)p; }
        else if (sz == 256)      { if (c256 < 8) v256[c256] = (const float*)p; c256++; }
    }
    const float *ln0_g = v256[0], *ln0_b = v256[1];
    const float *ln1_g = v256[2], *ln1_b = v256[3];
    const float *ln2_g = v256[4], *ln2_b = v256[5];
    const float *bf2   = v256[6];

    float *qkv, *qkv2, *agg, *h1, *h1r, *hr, *memr, *ffn;
    float *wqkv0, *wqkv1, *wo0r, *wo1r, *wf1r, *wf2r;
    int *cnt, *wr, *rowptr, *srcs, *ets;
    int *cnt2, *wr2, *rowptr2, *srcs2;
    cudaGetSymbolAddress((void**)&qkv,    g_qkv);
    cudaGetSymbolAddress((void**)&qkv2,   g_qkv2);
    cudaGetSymbolAddress((void**)&agg,    g_agg);
    cudaGetSymbolAddress((void**)&h1,     g_h1);
    cudaGetSymbolAddress((void**)&h1r,    g_h1r);
    cudaGetSymbolAddress((void**)&hr,     g_hr);
    cudaGetSymbolAddress((void**)&memr,   g_memr);
    cudaGetSymbolAddress((void**)&ffn,    g_ffn);
    cudaGetSymbolAddress((void**)&wqkv0,  g_wqkv0);
    cudaGetSymbolAddress((void**)&wqkv1,  g_wqkv1);
    cudaGetSymbolAddress((void**)&wo0r,   g_wo0r);
    cudaGetSymbolAddress((void**)&wo1r,   g_wo1r);
    cudaGetSymbolAddress((void**)&wf1r,   g_wf1r);
    cudaGetSymbolAddress((void**)&wf2r,   g_wf2r);
    cudaGetSymbolAddress((void**)&cnt,    g_cnt);
    cudaGetSymbolAddress((void**)&wr,     g_wr);
    cudaGetSymbolAddress((void**)&rowptr, g_rowptr);
    cudaGetSymbolAddress((void**)&srcs,   g_srcs);
    cudaGetSymbolAddress((void**)&ets,    g_ets);
    cudaGetSymbolAddress((void**)&cnt2,   g_cnt2);
    cudaGetSymbolAddress((void**)&wr2,    g_wr2);
    cudaGetSymbolAddress((void**)&rowptr2,g_rowptr2);
    cudaGetSymbolAddress((void**)&srcs2,  g_srcs2);

    float* out = (float*)d_out;

    cudaFuncSetAttribute(gemmA4,    cudaFuncAttributeMaxDynamicSharedMemorySize, SMEM_A);
    cudaFuncSetAttribute(gemm_qkv4, cudaFuncAttributeMaxDynamicSharedMemorySize, SMEM_A);
    cudaFuncSetAttribute(gemmB_ln,  cudaFuncAttributeMaxDynamicSharedMemorySize, SMEM_B);

    // ---------------- stream fork: side stream does CSR builds + stage-2 KV GEMM ----
    cudaStream_t s2;
    cudaStreamCreateWithFlags(&s2, cudaStreamNonBlocking);
    cudaEvent_t evRoot, evPrep, evCSR1, evS2;
    cudaEventCreateWithFlags(&evRoot, cudaEventDisableTiming);
    cudaEventCreateWithFlags(&evPrep, cudaEventDisableTiming);
    cudaEventCreateWithFlags(&evCSR1, cudaEventDisableTiming);
    cudaEventCreateWithFlags(&evS2,   cudaEventDisableTiming);

    cudaEventRecord(evRoot, 0);
    cudaStreamWaitEvent(s2, evRoot, 0);

    // side stream: both CSR builds (depend only on inputs)
    cudaMemsetAsync(cnt,  0, NN * sizeof(int), s2);
    cudaMemsetAsync(cnt2, 0, NN * sizeof(int), s2);
    hist_kernel<<<E1v / 256, 256, 0, s2>>>(dst_intra, cnt, E1v);
    scan64k<<<1, 1024, 0, s2>>>(cnt, rowptr, wr);
    scatter_csr<<<E1v / 256, 256, 0, s2>>>(src_intra, dst_intra, etype, wr, srcs, ets, E1v);
    cudaEventRecord(evCSR1, s2);
    hist_kernel<<<E2v / 256, 256, 0, s2>>>(dst_inter, cnt2, E2v);
    scan64k<<<1, 1024, 0, s2>>>(cnt2, rowptr2, wr2);
    scatter_csr<<<E2v / 256, 256, 0, s2>>>(src_inter, dst_inter, nullptr, wr2, srcs2, nullptr, E2v);

    // main stream: prep (weight packs + rounded activations)
    pack_qkv_b_frag<<<DD * QKVS / 256, 256>>>(W[0], W[1], W[2], wqkv0);
    pack_qkv_b_frag<<<DD * QKVS / 256, 256>>>(W[4], W[5], W[6], wqkv1);
    pack_b_frag<<<DD * DD / 256, 256>>>(W[3], wo0r, DD, DD);
    pack_b_frag<<<DD * DD / 256, 256>>>(W[7], wo1r, DD, DD);
    pack_b_frag<<<DD * DFFv / 256, 256>>>(Wf[0], wf1r, DD, DFFv);
    pack_b_frag<<<DFFv * DD / 256, 256>>>(Wf[1], wf2r, DFFv, DD);
    round_act<<<NN * DD / 4 / 256, 256>>>(h, hr);
    round_act<<<NN * DD / 4 / 256, 256>>>(mem, memr);
    cudaEventRecord(evPrep, 0);
    cudaStreamWaitEvent(s2, evPrep, 0);

    // side stream: stage-2 K/V projection (A = mem; independent of stage 1)
    gemm_qkv4<<<dim3(4, NN / 128), 128, SMEM_A, s2>>>(memr, memr, wqkv1, qkv2, 2);
    cudaEventRecord(evS2, s2);

    dim3 gLN(1, NN / 64);              // (1, 1024)
    dim3 gF1(DFFv / 128, NN / 128);    // (8, 512)
    const int ATT_BLKS = NN / 8;

    // ---------------- stage 1: intra attention (main stream) ----------------
    gemm_qkv4<<<dim3(6, NN / 128), 128, SMEM_A>>>(hr, hr, wqkv0, qkv, 0);
    cudaStreamWaitEvent(0, evCSR1, 0);
    dst_attn<true><<<ATT_BLKS, 256>>>(qkv, ak, srcs, ets, rowptr, agg);
    gemmB_ln<<<gLN, 256, SMEM_B>>>(agg, wo0r, h1, DD, nullptr, h, ln0_g, ln0_b, h1r);

    // ---------------- stage 2: inter attention ----------------
    gemm_qkv4<<<dim3(2, NN / 128), 128, SMEM_A>>>(h1r, h1r, wqkv1, qkv2, 0);
    cudaStreamWaitEvent(0, evS2, 0);
    dst_attn<false><<<ATT_BLKS, 256>>>(qkv2, nullptr, srcs2, nullptr, rowptr2, agg);
    gemmB_ln<<<gLN, 256, SMEM_B>>>(agg, wo1r, h1, DD, nullptr, h1, ln1_g, ln1_b, h1r);

    // ---------------- FFN + final norm ----------------
    gemmA4<<<gF1, 128, SMEM_A>>>(h1r, wf1r, ffn, DD, DFFv, bf1, 1);
    gemmB_ln<<<gLN, 256, SMEM_B>>>(ffn, wf2r, out, DFFv, bf2, h1, ln2_g, ln2_b, nullptr);
}